// round 1
// baseline (speedup 1.0000x reference)
#include <cuda_runtime.h>
#include <cuda_bf16.h>
#include <math.h>

// Problem constants
#define Bsz 8192
#define Dm  1024
#define Ff  4096
#define Ssup 4
#define Rr  16
#define Hh  4
#define HD  256   // Dm / Hh

// ---------------- scratch (device globals; allocation-free) ----------------
__device__ float g_w1[(size_t)Ssup * Dm * Ff];   // [S, D, F]   64 MB
__device__ float g_w2[(size_t)Ssup * Ff * Dm];   // [S, F, D]   64 MB
__device__ float g_h [(size_t)Ssup * Bsz * Ff];  // [S, B, F]  512 MB
__device__ float g_y [(size_t)Ssup * Bsz * Dm];  // [S, B, D]  128 MB
__device__ float g_q [(size_t)Bsz * Dm];         // [B, D]      32 MB
__device__ float g_k [(size_t)Ssup * Bsz * Dm];  // [S, B, D]  128 MB
__device__ float g_v [(size_t)Ssup * Bsz * Dm];  // [S, B, D]  128 MB
__device__ float g_o [(size_t)Bsz * Dm];         // [B, D]      32 MB

// ---------------- helpers ----------------
__device__ __forceinline__ float gelu_exact(float x) {
    return 0.5f * x * (1.0f + erff(x * 0.70710678118654752440f));
}

// ---------------- TT-core contraction kernels ----------------
// w1[s, i1*32+i2, o1*64+o2] = sum_r g1a[s,i1,o1,r] * g1b[s,r,i2,o2]
__global__ void build_w1(const float* __restrict__ g1a,
                         const float* __restrict__ g1b,
                         float* __restrict__ w1)
{
    size_t e = (size_t)blockIdx.x * blockDim.x + threadIdx.x;
    int s = (int)(e >> 22);              // D*F = 2^22 per s
    int d = (int)((e >> 12) & 1023);
    int f = (int)(e & 4095);
    int i1 = d >> 5, i2 = d & 31, o1 = f >> 6, o2 = f & 63;
    const float* a = g1a + (((size_t)s * 32 + i1) * 64 + o1) * 16;       // [S,I1,O1,R]
    const float* b = g1b + (size_t)s * 16 * 32 * 64 + (size_t)i2 * 64 + o2; // [S,R,I2,O2]
    float sum = 0.f;
#pragma unroll
    for (int r = 0; r < 16; r++) sum += a[r] * b[(size_t)r * 2048];
    w1[e] = sum;
}

// w2[s, o1*64+o2, i1*32+i2] = sum_r g2a[s,o1,i1,r] * g2b[s,r,o2,i2]
__global__ void build_w2(const float* __restrict__ g2a,
                         const float* __restrict__ g2b,
                         float* __restrict__ w2)
{
    size_t e = (size_t)blockIdx.x * blockDim.x + threadIdx.x;
    int s = (int)(e >> 22);              // F*D = 2^22 per s
    int f = (int)((e >> 10) & 4095);
    int d = (int)(e & 1023);
    int o1 = f >> 6, o2 = f & 63, i1 = d >> 5, i2 = d & 31;
    const float* a = g2a + (((size_t)s * 64 + o1) * 32 + i1) * 16;       // [S,O1,I1,R]
    const float* b = g2b + (size_t)s * 16 * 64 * 32 + (size_t)o2 * 32 + i2; // [S,R,O2,I2]
    float sum = 0.f;
#pragma unroll
    for (int r = 0; r < 16; r++) sum += a[r] * b[(size_t)r * 2048];
    w2[e] = sum;
}

// ---------------- tiled SGEMM: C = A(row) * B(row) [+bias / gelu] ----------------
// BM=128, BN=128, BK=16, 256 threads, 8x8 per thread. All dims multiples of 128.
// EPI: 0 none, 1 exact gelu, 2 bias add
#define BM 128
#define BN 128
#define BK 16

template <int EPI>
__global__ __launch_bounds__(256)
void sgemm(const float* __restrict__ Ag, const float* __restrict__ Bg,
           float* __restrict__ Cg, const float* __restrict__ bias,
           int M, int N, int K, size_t sA, size_t sB, size_t sC)
{
    const float* A = Ag + (size_t)blockIdx.z * sA;
    const float* B = Bg + (size_t)blockIdx.z * sB;
    float*       C = Cg + (size_t)blockIdx.z * sC;

    __shared__ float As[BK][BM];
    __shared__ float Bs[BK][BN];

    const int tid  = threadIdx.x;
    const int row0 = blockIdx.y * BM;
    const int col0 = blockIdx.x * BN;
    const int tx   = tid & 15;   // 16 cols of threads
    const int ty   = tid >> 4;   // 16 rows of threads

    float acc[8][8];
#pragma unroll
    for (int i = 0; i < 8; i++)
#pragma unroll
        for (int j = 0; j < 8; j++) acc[i][j] = 0.f;

    for (int k0 = 0; k0 < K; k0 += BK) {
        // load A tile (128x16) transposed into As[k][m]
#pragma unroll
        for (int l = 0; l < 2; l++) {
            int id = tid + 256 * l;          // 0..511 float4 slots
            int m  = id >> 2;                // BK/4 = 4 float4 per row
            int kq = id & 3;
            float4 va = *reinterpret_cast<const float4*>(
                &A[(size_t)(row0 + m) * K + k0 + kq * 4]);
            As[kq * 4 + 0][m] = va.x;
            As[kq * 4 + 1][m] = va.y;
            As[kq * 4 + 2][m] = va.z;
            As[kq * 4 + 3][m] = va.w;
        }
        // load B tile (16x128) directly
#pragma unroll
        for (int l = 0; l < 2; l++) {
            int id = tid + 256 * l;
            int kk = id >> 5;                // 32 float4 per row
            int nq = id & 31;
            float4 vb = *reinterpret_cast<const float4*>(
                &B[(size_t)(k0 + kk) * N + col0 + nq * 4]);
            *reinterpret_cast<float4*>(&Bs[kk][nq * 4]) = vb;
        }
        __syncthreads();

#pragma unroll
        for (int k = 0; k < BK; k++) {
            float a[8], b[8];
            float4 a0 = *reinterpret_cast<float4*>(&As[k][ty * 8]);
            float4 a1 = *reinterpret_cast<float4*>(&As[k][ty * 8 + 4]);
            a[0]=a0.x; a[1]=a0.y; a[2]=a0.z; a[3]=a0.w;
            a[4]=a1.x; a[5]=a1.y; a[6]=a1.z; a[7]=a1.w;
            float4 b0 = *reinterpret_cast<float4*>(&Bs[k][tx * 8]);
            float4 b1 = *reinterpret_cast<float4*>(&Bs[k][tx * 8 + 4]);
            b[0]=b0.x; b[1]=b0.y; b[2]=b0.z; b[3]=b0.w;
            b[4]=b1.x; b[5]=b1.y; b[6]=b1.z; b[7]=b1.w;
#pragma unroll
            for (int i = 0; i < 8; i++)
#pragma unroll
                for (int j = 0; j < 8; j++) acc[i][j] = fmaf(a[i], b[j], acc[i][j]);
        }
        __syncthreads();
    }

    // epilogue
    const int c0 = col0 + tx * 8;
#pragma unroll
    for (int i = 0; i < 8; i++) {
        int r = row0 + ty * 8 + i;
        float out[8];
#pragma unroll
        for (int j = 0; j < 8; j++) {
            float v = acc[i][j];
            if (EPI == 1) v = gelu_exact(v);
            if (EPI == 2) v += bias[c0 + j];
            out[j] = v;
        }
        *reinterpret_cast<float4*>(&C[(size_t)r * N + c0])     = make_float4(out[0], out[1], out[2], out[3]);
        *reinterpret_cast<float4*>(&C[(size_t)r * N + c0 + 4]) = make_float4(out[4], out[5], out[6], out[7]);
    }
}

// ---------------- softmax-over-S attention collapse ----------------
// q:[B,D], k,v:[S,B,D] -> o:[B,D]
__global__ __launch_bounds__(256)
void attn_kernel(const float* __restrict__ q, const float* __restrict__ k,
                 const float* __restrict__ v, float* __restrict__ o)
{
    const int b   = blockIdx.x;
    const int tid = threadIdx.x;
    __shared__ float sc[Hh * Ssup];

    const int warp = tid >> 5, lane = tid & 31;
    // 16 (h,s) dot products of length 256; 8 warps -> 2 each
#pragma unroll
    for (int p = warp * 2; p < warp * 2 + 2; p++) {
        const int h = p >> 2, s = p & 3;
        const float* qp = q + (size_t)b * Dm + h * HD;
        const float* kp = k + ((size_t)s * Bsz + b) * Dm + h * HD;
        float sum = 0.f;
#pragma unroll
        for (int j = lane; j < HD; j += 32) sum = fmaf(qp[j], kp[j], sum);
#pragma unroll
        for (int off = 16; off; off >>= 1) sum += __shfl_xor_sync(0xffffffffu, sum, off);
        if (lane == 0) sc[p] = sum * 0.0625f;   // 1/sqrt(256)
    }
    __syncthreads();

#pragma unroll
    for (int it = 0; it < 4; it++) {
        const int d = tid + it * 256;
        const int h = d >> 8;
        float s0 = sc[h * 4 + 0], s1 = sc[h * 4 + 1], s2 = sc[h * 4 + 2], s3 = sc[h * 4 + 3];
        float m  = fmaxf(fmaxf(s0, s1), fmaxf(s2, s3));
        float e0 = expf(s0 - m), e1 = expf(s1 - m), e2 = expf(s2 - m), e3 = expf(s3 - m);
        float inv = 1.f / (e0 + e1 + e2 + e3);
        const size_t base = (size_t)b * Dm + d;
        float acc = e0 * v[base]
                  + e1 * v[(size_t)Bsz * Dm + base]
                  + e2 * v[(size_t)2 * Bsz * Dm + base]
                  + e3 * v[(size_t)3 * Bsz * Dm + base];
        o[base] = acc * inv;
    }
}

// ---------------- launch ----------------
extern "C" void kernel_launch(void* const* d_in, const int* in_sizes, int n_in,
                              void* d_out, int out_size)
{
    const float* x   = (const float*)d_in[0];
    const float* g1a = (const float*)d_in[1];
    const float* g1b = (const float*)d_in[2];
    const float* g2a = (const float*)d_in[3];
    const float* g2b = (const float*)d_in[4];
    const float* wq  = (const float*)d_in[5];
    const float* bq  = (const float*)d_in[6];
    const float* wk  = (const float*)d_in[7];
    const float* bk  = (const float*)d_in[8];
    const float* wv  = (const float*)d_in[9];
    const float* bv  = (const float*)d_in[10];
    const float* wo  = (const float*)d_in[11];
    const float* bo  = (const float*)d_in[12];
    float* out = (float*)d_out;

    float *w1, *w2, *h, *y, *q, *k, *v, *o;
    cudaGetSymbolAddress((void**)&w1, g_w1);
    cudaGetSymbolAddress((void**)&w2, g_w2);
    cudaGetSymbolAddress((void**)&h,  g_h);
    cudaGetSymbolAddress((void**)&y,  g_y);
    cudaGetSymbolAddress((void**)&q,  g_q);
    cudaGetSymbolAddress((void**)&k,  g_k);
    cudaGetSymbolAddress((void**)&v,  g_v);
    cudaGetSymbolAddress((void**)&o,  g_o);

    // 1) materialize TT weights
    build_w1<<<(Ssup * Dm * Ff) / 256, 256>>>(g1a, g1b, w1);
    build_w2<<<(Ssup * Ff * Dm) / 256, 256>>>(g2a, g2b, w2);

    // 2) FFN1 + exact gelu: h[s] = gelu(x @ w1[s])   [8192x1024]x[1024x4096]
    {
        dim3 grid(Ff / BN, Bsz / BM, Ssup);
        sgemm<1><<<grid, 256>>>(x, w1, h, nullptr, Bsz, Ff, Dm,
                                0, (size_t)Dm * Ff, (size_t)Bsz * Ff);
    }
    // 3) FFN2: y[s] = h[s] @ w2[s]   [8192x4096]x[4096x1024]
    {
        dim3 grid(Dm / BN, Bsz / BM, Ssup);
        sgemm<0><<<grid, 256>>>(h, w2, y, nullptr, Bsz, Dm, Ff,
                                (size_t)Bsz * Ff, (size_t)Ff * Dm, (size_t)Bsz * Dm);
    }
    // 4) q = x @ wq + bq
    {
        dim3 grid(Dm / BN, Bsz / BM, 1);
        sgemm<2><<<grid, 256>>>(x, wq, q, bq, Bsz, Dm, Dm, 0, 0, 0);
    }
    // 5) k[s] = y[s] @ wk + bk ; v[s] = y[s] @ wv + bv
    {
        dim3 grid(Dm / BN, Bsz / BM, Ssup);
        sgemm<2><<<grid, 256>>>(y, wk, k, bk, Bsz, Dm, Dm,
                                (size_t)Bsz * Dm, 0, (size_t)Bsz * Dm);
        sgemm<2><<<grid, 256>>>(y, wv, v, bv, Bsz, Dm, Dm,
                                (size_t)Bsz * Dm, 0, (size_t)Bsz * Dm);
    }
    // 6) softmax-over-S collapse
    attn_kernel<<<Bsz, 256>>>(q, k, v, o);

    // 7) out = o @ wo + bo
    {
        dim3 grid(Dm / BN, Bsz / BM, 1);
        sgemm<2><<<grid, 256>>>(o, wo, out, bo, Bsz, Dm, Dm, 0, 0, 0);
    }
}

// round 3
// speedup vs baseline: 2.0128x; 2.0128x over previous
#include <cuda_runtime.h>
#include <cuda_bf16.h>
#include <math.h>
#include <stdint.h>

// ---------------- problem constants ----------------
#define Bsz 8192
#define Dm  1024
#define Ff  4096
#define Ssup 4
#define Hh  4
#define HD  256

// ---------------- GEMM tiling ----------------
#define BM 128
#define BN 128
#define BK 32                  // bf16 elems per k-tile (64 B rows)
#define NST 3                  // cp.async pipeline stages
#define MAT_B   (BM * BK * 2)  // 8192 bytes per matrix tile
#define STAGE_B (4 * MAT_B)    // Ah, Al, Bh, Bl = 32768
#define SMEM_T  (NST * STAGE_B)

// ---------------- scratch (device globals) ----------------
__device__ __nv_bfloat16 g_xh [(size_t)Bsz*Dm],     g_xl [(size_t)Bsz*Dm];
__device__ __nv_bfloat16 g_w1h[(size_t)Ssup*Ff*Dm], g_w1l[(size_t)Ssup*Ff*Dm];  // [s][f][d]
__device__ __nv_bfloat16 g_w2h[(size_t)Ssup*Dm*Ff], g_w2l[(size_t)Ssup*Dm*Ff];  // [s][d][f]
__device__ __nv_bfloat16 g_wqh[(size_t)Dm*Dm], g_wql[(size_t)Dm*Dm];
__device__ __nv_bfloat16 g_wkh[(size_t)Dm*Dm], g_wkl[(size_t)Dm*Dm];
__device__ __nv_bfloat16 g_wvh[(size_t)Dm*Dm], g_wvl[(size_t)Dm*Dm];
__device__ __nv_bfloat16 g_woh[(size_t)Dm*Dm], g_wol[(size_t)Dm*Dm];
__device__ __nv_bfloat16 g_hh [(size_t)Ssup*Bsz*Ff], g_hl [(size_t)Ssup*Bsz*Ff];
__device__ __nv_bfloat16 g_yh [(size_t)Ssup*Bsz*Dm], g_yl [(size_t)Ssup*Bsz*Dm];
__device__ __nv_bfloat16 g_oh [(size_t)Bsz*Dm],      g_ol [(size_t)Bsz*Dm];
__device__ float g_q [(size_t)Bsz*Dm];
__device__ float g_k [(size_t)Ssup*Bsz*Dm];
__device__ float g_v [(size_t)Ssup*Bsz*Dm];

// ---------------- asm helpers (all generic-target PTX, sm_80+) ----------------
__device__ __forceinline__ uint32_t smem_u32(const void* p) {
    uint32_t a;
    asm("{ .reg .u64 t; cvta.to.shared.u64 t, %1; cvt.u32.u64 %0, t; }" : "=r"(a) : "l"(p));
    return a;
}
__device__ __forceinline__ void cp16(uint32_t dst, const void* src) {
    asm volatile("cp.async.cg.shared.global [%0], [%1], 16;" :: "r"(dst), "l"(src));
}
#define CP_COMMIT() asm volatile("cp.async.commit_group;" ::: "memory")
#define CP_WAIT(n)  asm volatile("cp.async.wait_group %0;" :: "n"(n) : "memory")
#define LDSM4(r, a) asm volatile("ldmatrix.sync.aligned.m8n8.x4.shared.b16 {%0,%1,%2,%3}, [%4];" \
    : "=r"((r)[0]), "=r"((r)[1]), "=r"((r)[2]), "=r"((r)[3]) : "r"(a))
#define LDSM2(r, a) asm volatile("ldmatrix.sync.aligned.m8n8.x2.shared.b16 {%0,%1}, [%2];" \
    : "=r"((r)[0]), "=r"((r)[1]) : "r"(a))
#define MMA16816(ac, a, b) \
    asm volatile("mma.sync.aligned.m16n8k16.row.col.f32.bf16.bf16.f32 " \
        "{%0,%1,%2,%3}, {%4,%5,%6,%7}, {%8,%9}, {%0,%1,%2,%3};" \
        : "+f"((ac)[0]), "+f"((ac)[1]), "+f"((ac)[2]), "+f"((ac)[3]) \
        : "r"((a)[0]), "r"((a)[1]), "r"((a)[2]), "r"((a)[3]), "r"((b)[0]), "r"((b)[1]))

__device__ __forceinline__ float gelu_exact(float x) {
    return 0.5f * x * (1.0f + erff(x * 0.70710678118654752440f));
}
__device__ __forceinline__ void split2(float v, __nv_bfloat16* h, __nv_bfloat16* l) {
    __nv_bfloat16 hb = __float2bfloat16(v);
    *h = hb;
    *l = __float2bfloat16(v - __bfloat162float(hb));
}
// 16B-chunk swizzle for 64B rows: phys chunk = row*4 + (c16 ^ ((row>>1)&3))
__device__ __forceinline__ uint32_t swz(int row, int c16) {
    return (uint32_t)(row * 4 + (c16 ^ ((row >> 1) & 3))) * 16u;
}

// ---------------- conversion / build kernels ----------------
__global__ void split_x(const float* __restrict__ in, __nv_bfloat16* __restrict__ hi,
                        __nv_bfloat16* __restrict__ lo, size_t n) {
    size_t i = (size_t)blockIdx.x * blockDim.x + threadIdx.x;
    if (i < n) split2(in[i], &hi[i], &lo[i]);
}
__global__ void tsplit_w(const float* __restrict__ w, __nv_bfloat16* __restrict__ hi,
                         __nv_bfloat16* __restrict__ lo) {
    size_t e = (size_t)blockIdx.x * blockDim.x + threadIdx.x;
    int n = (int)(e >> 10), k = (int)(e & 1023);
    split2(w[(size_t)k * Dm + n], &hi[e], &lo[e]);
}
__global__ void build_w1t(const float* __restrict__ g1a, const float* __restrict__ g1b,
                          __nv_bfloat16* __restrict__ hi, __nv_bfloat16* __restrict__ lo) {
    size_t e = (size_t)blockIdx.x * blockDim.x + threadIdx.x;
    int s = (int)(e >> 22), f = (int)((e >> 10) & 4095), d = (int)(e & 1023);
    int i1 = d >> 5, i2 = d & 31, o1 = f >> 6, o2 = f & 63;
    const float* a = g1a + (((size_t)s * 32 + i1) * 64 + o1) * 16;
    const float* b = g1b + (size_t)s * 32768 + (size_t)i2 * 64 + o2;
    float sum = 0.f;
#pragma unroll
    for (int r = 0; r < 16; r++) sum += a[r] * b[(size_t)r * 2048];
    split2(sum, &hi[e], &lo[e]);
}
__global__ void build_w2t(const float* __restrict__ g2a, const float* __restrict__ g2b,
                          __nv_bfloat16* __restrict__ hi, __nv_bfloat16* __restrict__ lo) {
    size_t e = (size_t)blockIdx.x * blockDim.x + threadIdx.x;
    int s = (int)(e >> 22), d = (int)((e >> 12) & 1023), f = (int)(e & 4095);
    int o1 = f >> 6, o2 = f & 63, i1 = d >> 5, i2 = d & 31;
    const float* a = g2a + (((size_t)s * 64 + o1) * 32 + i1) * 16;
    const float* b = g2b + (size_t)s * 32768 + (size_t)o2 * 32 + i2;
    float sum = 0.f;
#pragma unroll
    for (int r = 0; r < 16; r++) sum += a[r] * b[(size_t)r * 2048];
    split2(sum, &hi[e], &lo[e]);
}

// ---------------- bf16x3 HMMA GEMM ----------------
// C[M, N] = A[M, K] * B[N, K]^T, bf16x3 compensated. Batched over blockIdx.z
// via strides (0 = shared operand). EPI: 0 split bf16 write, 1 gelu+split, 2 bias+fp32.
template <int EPI>
__global__ __launch_bounds__(256)
void mma_gemm(const __nv_bfloat16* __restrict__ Ah, const __nv_bfloat16* __restrict__ Al, size_t sA,
              const __nv_bfloat16* __restrict__ Bh, const __nv_bfloat16* __restrict__ Bl, size_t sB,
              int K, float* __restrict__ Cf,
              __nv_bfloat16* __restrict__ Chi, __nv_bfloat16* __restrict__ Clo,
              const float* __restrict__ bias, size_t sC)
{
    extern __shared__ char smem[];
    const uint32_t sb = smem_u32(smem);
    const int tid = threadIdx.x, wid = tid >> 5, lane = tid & 31;
    const int zz = blockIdx.z;
    const int m0 = blockIdx.y * BM, n0 = blockIdx.x * BN;
    const int N = gridDim.x * BN;

    const __nv_bfloat16* pAh = Ah + (size_t)zz * sA;
    const __nv_bfloat16* pAl = Al + (size_t)zz * sA;
    const __nv_bfloat16* pBh = Bh + (size_t)zz * sB;
    const __nv_bfloat16* pBl = Bl + (size_t)zz * sB;

    const int mwarp = (wid & 3) * 32;   // 4 warps over M
    const int nwarp = (wid >> 2) * 64;  // 2 warps over N

    float acc[2][8][4];
#pragma unroll
    for (int i = 0; i < 2; i++)
#pragma unroll
        for (int j = 0; j < 8; j++)
#pragma unroll
            for (int c = 0; c < 4; c++) acc[i][j][c] = 0.f;

    const int nk = K / BK;

    // per-thread fill coordinates (each thread: 2 chunks per matrix tile)
    const int fr0 = tid >> 2, fc0 = tid & 3;        // chunk tid
    const int fr1 = (tid + 256) >> 2, fc1 = (tid + 256) & 3;

    auto fill = [&](int kt, int st) {
        const int k0 = kt * BK;
        const uint32_t base = sb + st * STAGE_B;
        // A hi / A lo (rows m0+row)
        cp16(base + swz(fr0, fc0),             pAh + (size_t)(m0 + fr0) * K + k0 + fc0 * 8);
        cp16(base + swz(fr1, fc1),             pAh + (size_t)(m0 + fr1) * K + k0 + fc1 * 8);
        cp16(base + MAT_B + swz(fr0, fc0),     pAl + (size_t)(m0 + fr0) * K + k0 + fc0 * 8);
        cp16(base + MAT_B + swz(fr1, fc1),     pAl + (size_t)(m0 + fr1) * K + k0 + fc1 * 8);
        // B hi / B lo (rows n0+row)
        cp16(base + 2*MAT_B + swz(fr0, fc0),   pBh + (size_t)(n0 + fr0) * K + k0 + fc0 * 8);
        cp16(base + 2*MAT_B + swz(fr1, fc1),   pBh + (size_t)(n0 + fr1) * K + k0 + fc1 * 8);
        cp16(base + 3*MAT_B + swz(fr0, fc0),   pBl + (size_t)(n0 + fr0) * K + k0 + fc0 * 8);
        cp16(base + 3*MAT_B + swz(fr1, fc1),   pBl + (size_t)(n0 + fr1) * K + k0 + fc1 * 8);
        CP_COMMIT();
    };

    fill(0, 0);
    fill(1, 1);

    // per-lane ldmatrix coordinates
    const int ra  = lane & 15;           // A row within 16
    const int ca8 = lane >> 4;           // A k-half (0/1)
    const int rb  = lane & 7;            // B row within 8
    const int cb8 = (lane >> 3) & 1;     // B k-half

    for (int kt = 0; kt < nk; kt++) {
        if (kt + 1 == nk) { CP_WAIT(0); } else { CP_WAIT(1); }
        __syncthreads();
        if (kt + 2 < nk) fill(kt + 2, (kt + 2) % NST);

        const uint32_t base = sb + (kt % NST) * STAGE_B;
        const uint32_t sAh = base, sAl = base + MAT_B;
        const uint32_t sBh = base + 2 * MAT_B, sBl = base + 3 * MAT_B;

#pragma unroll
        for (int kk = 0; kk < 2; kk++) {
            uint32_t ah[2][4], al[2][4];
#pragma unroll
            for (int mt = 0; mt < 2; mt++) {
                int row = mwarp + mt * 16 + ra;
                uint32_t off = swz(row, kk * 2 + ca8);
                LDSM4(ah[mt], sAh + off);
                LDSM4(al[mt], sAl + off);
            }
#pragma unroll
            for (int nt = 0; nt < 8; nt++) {
                uint32_t bh[2], bl[2];
                int row = nwarp + nt * 8 + rb;
                uint32_t off = swz(row, kk * 2 + cb8);
                LDSM2(bh, sBh + off);
                LDSM2(bl, sBl + off);
#pragma unroll
                for (int mt = 0; mt < 2; mt++) {
                    MMA16816(acc[mt][nt], ah[mt], bh);
                    MMA16816(acc[mt][nt], al[mt], bh);
                    MMA16816(acc[mt][nt], ah[mt], bl);
                }
            }
        }
        __syncthreads();
    }

    // ---------------- epilogue ----------------
    float* Cfp = Cf ? Cf + (size_t)zz * sC : nullptr;
    __nv_bfloat16* Chp = Chi ? Chi + (size_t)zz * sC : nullptr;
    __nv_bfloat16* Clp = Clo ? Clo + (size_t)zz * sC : nullptr;
    const int g4 = lane >> 2, q2 = (lane & 3) * 2;

#pragma unroll
    for (int mt = 0; mt < 2; mt++) {
#pragma unroll
        for (int nt = 0; nt < 8; nt++) {
            int r = m0 + mwarp + mt * 16 + g4;
            int c = n0 + nwarp + nt * 8 + q2;
#pragma unroll
            for (int half = 0; half < 2; half++) {
                int rr = r + half * 8;
                float v0 = acc[mt][nt][half * 2 + 0];
                float v1 = acc[mt][nt][half * 2 + 1];
                size_t off = (size_t)rr * N + c;
                if (EPI == 2) {
                    float2 o = make_float2(v0 + bias[c], v1 + bias[c + 1]);
                    *reinterpret_cast<float2*>(&Cfp[off]) = o;
                } else {
                    if (EPI == 1) { v0 = gelu_exact(v0); v1 = gelu_exact(v1); }
                    __nv_bfloat162 h2, l2;
                    split2(v0, &h2.x, &l2.x);
                    split2(v1, &h2.y, &l2.y);
                    *reinterpret_cast<__nv_bfloat162*>(&Chp[off]) = h2;
                    *reinterpret_cast<__nv_bfloat162*>(&Clp[off]) = l2;
                }
            }
        }
    }
}

// ---------------- attention collapse ----------------
__global__ __launch_bounds__(256)
void attn_kernel(const float* __restrict__ q, const float* __restrict__ k,
                 const float* __restrict__ v,
                 __nv_bfloat16* __restrict__ ohi, __nv_bfloat16* __restrict__ olo)
{
    const int b = blockIdx.x;
    const int tid = threadIdx.x;
    __shared__ float sc[Hh * Ssup];
    const int warp = tid >> 5, lane = tid & 31;
#pragma unroll
    for (int p = warp * 2; p < warp * 2 + 2; p++) {
        const int h = p >> 2, s = p & 3;
        const float* qp = q + (size_t)b * Dm + h * HD;
        const float* kp = k + ((size_t)s * Bsz + b) * Dm + h * HD;
        float sum = 0.f;
#pragma unroll
        for (int j = lane; j < HD; j += 32) sum = fmaf(qp[j], kp[j], sum);
#pragma unroll
        for (int off = 16; off; off >>= 1) sum += __shfl_xor_sync(0xffffffffu, sum, off);
        if (lane == 0) sc[p] = sum * 0.0625f;
    }
    __syncthreads();
#pragma unroll
    for (int it = 0; it < 4; it++) {
        const int d = tid + it * 256;
        const int h = d >> 8;
        float s0 = sc[h*4+0], s1 = sc[h*4+1], s2 = sc[h*4+2], s3 = sc[h*4+3];
        float m = fmaxf(fmaxf(s0, s1), fmaxf(s2, s3));
        float e0 = expf(s0-m), e1 = expf(s1-m), e2 = expf(s2-m), e3 = expf(s3-m);
        float inv = 1.f / (e0 + e1 + e2 + e3);
        const size_t base = (size_t)b * Dm + d;
        float a = e0 * v[base]
                + e1 * v[(size_t)Bsz*Dm + base]
                + e2 * v[(size_t)2*Bsz*Dm + base]
                + e3 * v[(size_t)3*Bsz*Dm + base];
        split2(a * inv, &ohi[base], &olo[base]);
    }
}

// ---------------- launch ----------------
extern "C" void kernel_launch(void* const* d_in, const int* in_sizes, int n_in,
                              void* d_out, int out_size)
{
    const float* x   = (const float*)d_in[0];
    const float* g1a = (const float*)d_in[1];
    const float* g1b = (const float*)d_in[2];
    const float* g2a = (const float*)d_in[3];
    const float* g2b = (const float*)d_in[4];
    const float* wq  = (const float*)d_in[5];
    const float* bq  = (const float*)d_in[6];
    const float* wk  = (const float*)d_in[7];
    const float* bk  = (const float*)d_in[8];
    const float* wv  = (const float*)d_in[9];
    const float* bv  = (const float*)d_in[10];
    const float* wo  = (const float*)d_in[11];
    const float* bo  = (const float*)d_in[12];
    float* out = (float*)d_out;

    __nv_bfloat16 *xh,*xl,*w1h,*w1l,*w2h,*w2l,*wqh,*wql,*wkh,*wkl,*wvh,*wvl,*woh,*wol,*hh,*hl,*yh,*yl,*oh,*ol;
    float *q,*k,*v;
    cudaGetSymbolAddress((void**)&xh, g_xh);   cudaGetSymbolAddress((void**)&xl, g_xl);
    cudaGetSymbolAddress((void**)&w1h, g_w1h); cudaGetSymbolAddress((void**)&w1l, g_w1l);
    cudaGetSymbolAddress((void**)&w2h, g_w2h); cudaGetSymbolAddress((void**)&w2l, g_w2l);
    cudaGetSymbolAddress((void**)&wqh, g_wqh); cudaGetSymbolAddress((void**)&wql, g_wql);
    cudaGetSymbolAddress((void**)&wkh, g_wkh); cudaGetSymbolAddress((void**)&wkl, g_wkl);
    cudaGetSymbolAddress((void**)&wvh, g_wvh); cudaGetSymbolAddress((void**)&wvl, g_wvl);
    cudaGetSymbolAddress((void**)&woh, g_woh); cudaGetSymbolAddress((void**)&wol, g_wol);
    cudaGetSymbolAddress((void**)&hh, g_hh);   cudaGetSymbolAddress((void**)&hl, g_hl);
    cudaGetSymbolAddress((void**)&yh, g_yh);   cudaGetSymbolAddress((void**)&yl, g_yl);
    cudaGetSymbolAddress((void**)&oh, g_oh);   cudaGetSymbolAddress((void**)&ol, g_ol);
    cudaGetSymbolAddress((void**)&q, g_q);
    cudaGetSymbolAddress((void**)&k, g_k);
    cudaGetSymbolAddress((void**)&v, g_v);

    cudaFuncSetAttribute(mma_gemm<0>, cudaFuncAttributeMaxDynamicSharedMemorySize, SMEM_T);
    cudaFuncSetAttribute(mma_gemm<1>, cudaFuncAttributeMaxDynamicSharedMemorySize, SMEM_T);
    cudaFuncSetAttribute(mma_gemm<2>, cudaFuncAttributeMaxDynamicSharedMemorySize, SMEM_T);

    // 1) conversions / TT materialization
    split_x<<<(Bsz * Dm) / 256, 256>>>(x, xh, xl, (size_t)Bsz * Dm);
    tsplit_w<<<(Dm * Dm) / 256, 256>>>(wq, wqh, wql);
    tsplit_w<<<(Dm * Dm) / 256, 256>>>(wk, wkh, wkl);
    tsplit_w<<<(Dm * Dm) / 256, 256>>>(wv, wvh, wvl);
    tsplit_w<<<(Dm * Dm) / 256, 256>>>(wo, woh, wol);
    build_w1t<<<(Ssup * Ff * Dm) / 256, 256>>>(g1a, g1b, w1h, w1l);
    build_w2t<<<(Ssup * Dm * Ff) / 256, 256>>>(g2a, g2b, w2h, w2l);

    const size_t sBD = (size_t)Bsz * Dm, sBF = (size_t)Bsz * Ff;

    // 2) FFN1: h[s] = gelu(x @ w1t[s]^T)  [M=B, N=F, K=D]
    {
        dim3 grid(Ff / BN, Bsz / BM, Ssup);
        mma_gemm<1><<<grid, 256, SMEM_T>>>(xh, xl, 0, w1h, w1l, (size_t)Ff * Dm,
                                           Dm, nullptr, hh, hl, nullptr, sBF);
    }
    // 3) FFN2: y[s] = h[s] @ w2t[s]^T     [M=B, N=D, K=F]
    {
        dim3 grid(Dm / BN, Bsz / BM, Ssup);
        mma_gemm<0><<<grid, 256, SMEM_T>>>(hh, hl, sBF, w2h, w2l, (size_t)Dm * Ff,
                                           Ff, nullptr, yh, yl, nullptr, sBD);
    }
    // 4) q = x @ wq + bq (fp32)
    {
        dim3 grid(Dm / BN, Bsz / BM, 1);
        mma_gemm<2><<<grid, 256, SMEM_T>>>(xh, xl, 0, wqh, wql, 0,
                                           Dm, q, nullptr, nullptr, bq, 0);
    }
    // 5) k[s] = y[s] @ wk + bk ; v[s] = y[s] @ wv + bv (fp32)
    {
        dim3 grid(Dm / BN, Bsz / BM, Ssup);
        mma_gemm<2><<<grid, 256, SMEM_T>>>(yh, yl, sBD, wkh, wkl, 0,
                                           Dm, k, nullptr, nullptr, bk, sBD);
        mma_gemm<2><<<grid, 256, SMEM_T>>>(yh, yl, sBD, wvh, wvl, 0,
                                           Dm, v, nullptr, nullptr, bv, sBD);
    }
    // 6) softmax-over-S collapse -> o (split bf16)
    attn_kernel<<<Bsz, 256>>>(q, k, v, oh, ol);
    // 7) out = o @ wo + bo (fp32)
    {
        dim3 grid(Dm / BN, Bsz / BM, 1);
        mma_gemm<2><<<grid, 256, SMEM_T>>>(oh, ol, 0, woh, wol, 0,
                                           Dm, out, nullptr, nullptr, bo, 0);
    }
}

// round 5
// speedup vs baseline: 2.1417x; 1.0641x over previous
#include <cuda_runtime.h>
#include <cuda_bf16.h>
#include <math.h>
#include <stdint.h>

// ---------------- problem constants ----------------
#define Bsz 8192
#define Dm  1024
#define Ff  4096
#define Ssup 4
#define Hh  4
#define HD  256

// ---------------- GEMM tiling ----------------
#define BM 128
#define BN 256
#define BK 32                    // bf16 elems per k-tile (64B rows)
#define NST 3
#define A_B   (BM * BK * 2)      // 8192  bytes (one matrix, hi or lo)
#define B_B   (BN * BK * 2)      // 16384 bytes
#define STAGE_B (2 * A_B + 2 * B_B)  // 49152
#define SMEM_T  (NST * STAGE_B)      // 147456

// ---------------- scratch (device globals) ----------------
__device__ __nv_bfloat16 g_xh [(size_t)Bsz*Dm],     g_xl [(size_t)Bsz*Dm];
__device__ __nv_bfloat16 g_w1h[(size_t)Ssup*Ff*Dm], g_w1l[(size_t)Ssup*Ff*Dm];  // [s][f][d]
__device__ __nv_bfloat16 g_w2h[(size_t)Ssup*Dm*Ff], g_w2l[(size_t)Ssup*Dm*Ff];  // [s][d][f]
__device__ __nv_bfloat16 g_wqh[(size_t)Dm*Dm], g_wql[(size_t)Dm*Dm];   // transposed [n][k]
__device__ __nv_bfloat16 g_wk2h[(size_t)Dm*Dm], g_wk2l[(size_t)Dm*Dm]; // straight [m][d]
__device__ __nv_bfloat16 g_wvh[(size_t)Dm*Dm], g_wvl[(size_t)Dm*Dm];   // transposed
__device__ __nv_bfloat16 g_woh[(size_t)Dm*Dm], g_wol[(size_t)Dm*Dm];   // transposed
__device__ __nv_bfloat16 g_hh [(size_t)Ssup*Bsz*Ff], g_hl [(size_t)Ssup*Bsz*Ff];
__device__ __nv_bfloat16 g_yh [(size_t)Ssup*Bsz*Dm], g_yl [(size_t)Ssup*Bsz*Dm];
__device__ __nv_bfloat16 g_qh [(size_t)Bsz*Dm],      g_ql [(size_t)Bsz*Dm];
__device__ __nv_bfloat16 g_zh [(size_t)Hh*Bsz*Dm],   g_zl [(size_t)Hh*Bsz*Dm];  // [h][b][m]
__device__ __nv_bfloat16 g_oh [(size_t)Bsz*Dm],      g_ol [(size_t)Bsz*Dm];
__device__ float g_t [(size_t)Hh*Bsz*Dm];   // [h][b][m]

// ---------------- asm helpers (generic-target PTX, sm_80+) ----------------
__device__ __forceinline__ uint32_t smem_u32(const void* p) {
    uint32_t a;
    asm("{ .reg .u64 t; cvta.to.shared.u64 t, %1; cvt.u32.u64 %0, t; }" : "=r"(a) : "l"(p));
    return a;
}
__device__ __forceinline__ void cp16(uint32_t dst, const void* src) {
    asm volatile("cp.async.cg.shared.global [%0], [%1], 16;" :: "r"(dst), "l"(src));
}
#define CP_COMMIT() asm volatile("cp.async.commit_group;" ::: "memory")
#define CP_WAIT(n)  asm volatile("cp.async.wait_group %0;" :: "n"(n) : "memory")
#define LDSM4(r, a) asm volatile("ldmatrix.sync.aligned.m8n8.x4.shared.b16 {%0,%1,%2,%3}, [%4];" \
    : "=r"((r)[0]), "=r"((r)[1]), "=r"((r)[2]), "=r"((r)[3]) : "r"(a))
#define MMA16816(ac, a, b0, b1) \
    asm volatile("mma.sync.aligned.m16n8k16.row.col.f32.bf16.bf16.f32 " \
        "{%0,%1,%2,%3}, {%4,%5,%6,%7}, {%8,%9}, {%0,%1,%2,%3};" \
        : "+f"((ac)[0]), "+f"((ac)[1]), "+f"((ac)[2]), "+f"((ac)[3]) \
        : "r"((a)[0]), "r"((a)[1]), "r"((a)[2]), "r"((a)[3]), "r"(b0), "r"(b1))

__device__ __forceinline__ float gelu_exact(float x) {
    return 0.5f * x * (1.0f + erff(x * 0.70710678118654752440f));
}
__device__ __forceinline__ void split2(float v, __nv_bfloat16* h, __nv_bfloat16* l) {
    __nv_bfloat16 hb = __float2bfloat16(v);
    *h = hb;
    *l = __float2bfloat16(v - __bfloat162float(hb));
}
// 16B-chunk swizzle for 64B rows
__device__ __forceinline__ uint32_t swz(int row, int c16) {
    return (uint32_t)(row * 4 + (c16 ^ ((row >> 1) & 3))) * 16u;
}

// ---------------- conversion / build kernels ----------------
__global__ void split_arr(const float* __restrict__ in, __nv_bfloat16* __restrict__ hi,
                          __nv_bfloat16* __restrict__ lo, size_t n) {
    size_t i = (size_t)blockIdx.x * blockDim.x + threadIdx.x;
    if (i < n) split2(in[i], &hi[i], &lo[i]);
}
__global__ void tsplit_w(const float* __restrict__ w, __nv_bfloat16* __restrict__ hi,
                         __nv_bfloat16* __restrict__ lo) {
    size_t e = (size_t)blockIdx.x * blockDim.x + threadIdx.x;
    int n = (int)(e >> 10), k = (int)(e & 1023);
    split2(w[(size_t)k * Dm + n], &hi[e], &lo[e]);
}
__global__ void build_w1t(const float* __restrict__ g1a, const float* __restrict__ g1b,
                          __nv_bfloat16* __restrict__ hi, __nv_bfloat16* __restrict__ lo) {
    size_t e = (size_t)blockIdx.x * blockDim.x + threadIdx.x;
    int s = (int)(e >> 22), f = (int)((e >> 10) & 4095), d = (int)(e & 1023);
    int i1 = d >> 5, i2 = d & 31, o1 = f >> 6, o2 = f & 63;
    const float* a = g1a + (((size_t)s * 32 + i1) * 64 + o1) * 16;
    const float* b = g1b + (size_t)s * 32768 + (size_t)i2 * 64 + o2;
    float sum = 0.f;
#pragma unroll
    for (int r = 0; r < 16; r++) sum += a[r] * b[(size_t)r * 2048];
    split2(sum, &hi[e], &lo[e]);
}
__global__ void build_w2t(const float* __restrict__ g2a, const float* __restrict__ g2b,
                          __nv_bfloat16* __restrict__ hi, __nv_bfloat16* __restrict__ lo) {
    size_t e = (size_t)blockIdx.x * blockDim.x + threadIdx.x;
    int s = (int)(e >> 22), d = (int)((e >> 12) & 1023), f = (int)(e & 4095);
    int o1 = f >> 6, o2 = f & 63, i1 = d >> 5, i2 = d & 31;
    const float* a = g2a + (((size_t)s * 64 + o1) * 32 + i1) * 16;
    const float* b = g2b + (size_t)s * 32768 + (size_t)o2 * 32 + i2;
    float sum = 0.f;
#pragma unroll
    for (int r = 0; r < 16; r++) sum += a[r] * b[(size_t)r * 2048];
    split2(sum, &hi[e], &lo[e]);
}

// ---------------- bf16x3 HMMA GEMM ----------------
// C = A * B^T. A: [BM rows, K] lda; B: [N rows, K] ldb. Batched over blockIdx.z
// by pointer offsets (aBS/bBS/cBS/biasBS in elements).
// EPI: 0 split, 1 gelu+split, 2 bias+fp32, 3 bias+split, 4 fp32
template <int EPI>
__global__ __launch_bounds__(256, 1)
void mma_gemm(const __nv_bfloat16* __restrict__ Ah, const __nv_bfloat16* __restrict__ Al,
              int lda, size_t aBS,
              const __nv_bfloat16* __restrict__ Bh, const __nv_bfloat16* __restrict__ Bl,
              int ldb, size_t bBS,
              int K, int ldc, size_t cBS,
              float* __restrict__ Cf,
              __nv_bfloat16* __restrict__ Chi, __nv_bfloat16* __restrict__ Clo,
              const float* __restrict__ bias, size_t biasBS)
{
    extern __shared__ char smem[];
    const uint32_t sb = smem_u32(smem);
    const int tid = threadIdx.x, wid = tid >> 5, lane = tid & 31;
    const int zz = blockIdx.z;
    const int m0 = blockIdx.y * BM, n0 = blockIdx.x * BN;

    const __nv_bfloat16* pAh = Ah + (size_t)zz * aBS;
    const __nv_bfloat16* pAl = Al + (size_t)zz * aBS;
    const __nv_bfloat16* pBh = Bh + (size_t)zz * bBS;
    const __nv_bfloat16* pBl = Bl + (size_t)zz * bBS;

    const int mwarp = (wid & 1) * 64;    // 2 warps over M
    const int nwarp = (wid >> 1) * 64;   // 4 warps over N

    float acc[4][8][4];
#pragma unroll
    for (int i = 0; i < 4; i++)
#pragma unroll
        for (int j = 0; j < 8; j++)
#pragma unroll
            for (int c = 0; c < 4; c++) acc[i][j][c] = 0.f;

    const int nk = K / BK;

    const int fr = tid >> 2, fc = tid & 3;   // chunk coords (row block of 64, col 0..3)

    auto fill = [&](int kt, int st) {
        const int k0 = kt * BK;
        const uint32_t base = sb + st * STAGE_B;
        // A: 512 chunks per matrix (128 rows x 4)
#pragma unroll
        for (int i = 0; i < 2; i++) {
            int r = fr + i * 64;
            cp16(base + swz(r, fc),       pAh + (size_t)(m0 + r) * lda + k0 + fc * 8);
            cp16(base + A_B + swz(r, fc), pAl + (size_t)(m0 + r) * lda + k0 + fc * 8);
        }
        // B: 1024 chunks per matrix (256 rows x 4)
#pragma unroll
        for (int i = 0; i < 4; i++) {
            int r = fr + i * 64;
            cp16(base + 2*A_B + swz(r, fc),       pBh + (size_t)(n0 + r) * ldb + k0 + fc * 8);
            cp16(base + 2*A_B + B_B + swz(r, fc), pBl + (size_t)(n0 + r) * ldb + k0 + fc * 8);
        }
        CP_COMMIT();
    };

    fill(0, 0);
    if (nk > 1) fill(1, 1);

    const int ra = lane & 15, ca = lane >> 4;           // A ldmatrix coords
    const int gb = lane >> 3, rb = lane & 7;            // B ldmatrix coords

    for (int kt = 0; kt < nk; kt++) {
        if (kt + 1 >= nk) { CP_WAIT(0); } else { CP_WAIT(1); }
        __syncthreads();
        if (kt + 2 < nk) fill(kt + 2, (kt + 2) % NST);

        const uint32_t base = sb + (kt % NST) * STAGE_B;
        const uint32_t sAh = base, sAl = base + A_B;
        const uint32_t sBh = base + 2 * A_B, sBl = base + 2 * A_B + B_B;

#pragma unroll
        for (int kk = 0; kk < 2; kk++) {
            uint32_t ah[4][4], al[4][4];
#pragma unroll
            for (int mt = 0; mt < 4; mt++) {
                uint32_t off = swz(mwarp + mt * 16 + ra, kk * 2 + ca);
                LDSM4(ah[mt], sAh + off);
                LDSM4(al[mt], sAl + off);
            }
#pragma unroll
            for (int p = 0; p < 4; p++) {
                // paired B load: 16 n-rows, both k-halves -> frags for nt=2p, 2p+1
                uint32_t bh[4], bl[4];
                uint32_t off = swz(nwarp + p * 16 + (gb & 1) * 8 + rb, kk * 2 + (gb >> 1));
                LDSM4(bh, sBh + off);
                LDSM4(bl, sBl + off);
#pragma unroll
                for (int mt = 0; mt < 4; mt++) {
                    MMA16816(acc[mt][2*p],   ah[mt], bh[0], bh[2]);
                    MMA16816(acc[mt][2*p],   al[mt], bh[0], bh[2]);
                    MMA16816(acc[mt][2*p],   ah[mt], bl[0], bl[2]);
                    MMA16816(acc[mt][2*p+1], ah[mt], bh[1], bh[3]);
                    MMA16816(acc[mt][2*p+1], al[mt], bh[1], bh[3]);
                    MMA16816(acc[mt][2*p+1], ah[mt], bl[1], bl[3]);
                }
            }
        }
    }

    // ---------------- epilogue ----------------
    float* Cfp = Cf ? Cf + (size_t)zz * cBS : nullptr;
    __nv_bfloat16* Chp = Chi ? Chi + (size_t)zz * cBS : nullptr;
    __nv_bfloat16* Clp = Clo ? Clo + (size_t)zz * cBS : nullptr;
    const float* bp = bias ? bias + (size_t)zz * biasBS : nullptr;
    const int g4 = lane >> 2, q2 = (lane & 3) * 2;

#pragma unroll
    for (int mt = 0; mt < 4; mt++) {
#pragma unroll
        for (int nt = 0; nt < 8; nt++) {
            int r0 = m0 + mwarp + mt * 16 + g4;
            int c  = n0 + nwarp + nt * 8 + q2;
#pragma unroll
            for (int half = 0; half < 2; half++) {
                int rr = r0 + half * 8;
                float v0 = acc[mt][nt][half * 2 + 0];
                float v1 = acc[mt][nt][half * 2 + 1];
                size_t off = (size_t)rr * ldc + c;
                if (EPI == 2) {
                    *reinterpret_cast<float2*>(&Cfp[off]) =
                        make_float2(v0 + bp[c], v1 + bp[c + 1]);
                } else if (EPI == 4) {
                    *reinterpret_cast<float2*>(&Cfp[off]) = make_float2(v0, v1);
                } else {
                    if (EPI == 1) { v0 = gelu_exact(v0); v1 = gelu_exact(v1); }
                    if (EPI == 3) { v0 += bp[c]; v1 += bp[c + 1]; }
                    __nv_bfloat162 h2, l2;
                    split2(v0, &h2.x, &l2.x);
                    split2(v1, &h2.y, &l2.y);
                    *reinterpret_cast<__nv_bfloat162*>(&Chp[off]) = h2;
                    *reinterpret_cast<__nv_bfloat162*>(&Clp[off]) = l2;
                }
            }
        }
    }
}

// ---------------- attention collapse: scores, softmax, z ----------------
// scores[b,h,s] = (y_s[b,:]·t[h,b,:] + q[b,h,:]·bk[h,:]) / 16
// z[h,b,m] = sum_s attn[b,h,s] * y_s[b,m]    (split bf16 out)
__global__ __launch_bounds__(256)
void attn_collapse(const __nv_bfloat16* __restrict__ qh, const __nv_bfloat16* __restrict__ ql,
                   const float* __restrict__ t,
                   const __nv_bfloat16* __restrict__ yh, const __nv_bfloat16* __restrict__ yl,
                   const float* __restrict__ bk,
                   __nv_bfloat16* __restrict__ zh, __nv_bfloat16* __restrict__ zl)
{
    const int b = blockIdx.x, tid = threadIdx.x;
    const int wid = tid >> 5, lane = tid & 31;
    __shared__ float ys[Ssup][Dm];
    __shared__ float sc[16], qb[Hh], attn[16];

    // stage y (reconstructed fp32)
#pragma unroll
    for (int it = 0; it < 16; it++) {
        int idx = tid + it * 256;
        int s = idx >> 10, m = idx & 1023;
        size_t g = ((size_t)s * Bsz + b) * Dm + m;
        ys[s][m] = __bfloat162float(yh[g]) + __bfloat162float(yl[g]);
    }
    // q·bk per head (bk is typically zero; kept for exactness)
    if (wid < Hh) {
        float sum = 0.f;
        for (int j = lane; j < HD; j += 32) {
            size_t g = (size_t)b * Dm + wid * HD + j;
            float qv = __bfloat162float(qh[g]) + __bfloat162float(ql[g]);
            sum = fmaf(qv, bk[wid * HD + j], sum);
        }
#pragma unroll
        for (int o = 16; o; o >>= 1) sum += __shfl_xor_sync(0xffffffffu, sum, o);
        if (lane == 0) qb[wid] = sum;
    }
    __syncthreads();

    // 16 (h,s) dots of length 1024
#pragma unroll
    for (int i = 0; i < 2; i++) {
        int p = wid * 2 + i;
        int h = p >> 2, s = p & 3;
        const float* tp = t + ((size_t)h * Bsz + b) * Dm;
        float sum = 0.f;
        for (int m = lane; m < Dm; m += 32) sum = fmaf(ys[s][m], tp[m], sum);
#pragma unroll
        for (int o = 16; o; o >>= 1) sum += __shfl_xor_sync(0xffffffffu, sum, o);
        if (lane == 0) sc[p] = sum;
    }
    __syncthreads();

    if (tid < Hh) {
        int h = tid;
        float s0 = (sc[h*4+0] + qb[h]) * 0.0625f;
        float s1 = (sc[h*4+1] + qb[h]) * 0.0625f;
        float s2 = (sc[h*4+2] + qb[h]) * 0.0625f;
        float s3 = (sc[h*4+3] + qb[h]) * 0.0625f;
        float m = fmaxf(fmaxf(s0, s1), fmaxf(s2, s3));
        float e0 = expf(s0-m), e1 = expf(s1-m), e2 = expf(s2-m), e3 = expf(s3-m);
        float inv = 1.f / (e0 + e1 + e2 + e3);
        attn[h*4+0] = e0*inv; attn[h*4+1] = e1*inv;
        attn[h*4+2] = e2*inv; attn[h*4+3] = e3*inv;
    }
    __syncthreads();

    // z[h,b,m]
#pragma unroll
    for (int it = 0; it < 16; it++) {
        int idx = tid + it * 256;
        int h = idx >> 10, m = idx & 1023;
        float a0 = attn[h*4+0], a1 = attn[h*4+1], a2 = attn[h*4+2], a3 = attn[h*4+3];
        float zv = a0*ys[0][m] + a1*ys[1][m] + a2*ys[2][m] + a3*ys[3][m];
        size_t g = ((size_t)h * Bsz + b) * Dm + m;
        split2(zv, &zh[g], &zl[g]);
    }
}

// ---------------- launch ----------------
extern "C" void kernel_launch(void* const* d_in, const int* in_sizes, int n_in,
                              void* d_out, int out_size)
{
    const float* x   = (const float*)d_in[0];
    const float* g1a = (const float*)d_in[1];
    const float* g1b = (const float*)d_in[2];
    const float* g2a = (const float*)d_in[3];
    const float* g2b = (const float*)d_in[4];
    const float* wq  = (const float*)d_in[5];
    const float* bq  = (const float*)d_in[6];
    const float* wk  = (const float*)d_in[7];
    const float* bk  = (const float*)d_in[8];
    const float* wv  = (const float*)d_in[9];
    const float* bv  = (const float*)d_in[10];
    const float* wo  = (const float*)d_in[11];
    const float* bo  = (const float*)d_in[12];
    float* out = (float*)d_out;

    __nv_bfloat16 *xh,*xl,*w1h,*w1l,*w2h,*w2l,*wqh,*wql,*wk2h,*wk2l,*wvh,*wvl,*woh,*wol;
    __nv_bfloat16 *hh,*hl,*yh,*yl,*qh,*ql,*zh,*zl,*oh,*ol;
    float *t;
    cudaGetSymbolAddress((void**)&xh, g_xh);     cudaGetSymbolAddress((void**)&xl, g_xl);
    cudaGetSymbolAddress((void**)&w1h, g_w1h);   cudaGetSymbolAddress((void**)&w1l, g_w1l);
    cudaGetSymbolAddress((void**)&w2h, g_w2h);   cudaGetSymbolAddress((void**)&w2l, g_w2l);
    cudaGetSymbolAddress((void**)&wqh, g_wqh);   cudaGetSymbolAddress((void**)&wql, g_wql);
    cudaGetSymbolAddress((void**)&wk2h, g_wk2h); cudaGetSymbolAddress((void**)&wk2l, g_wk2l);
    cudaGetSymbolAddress((void**)&wvh, g_wvh);   cudaGetSymbolAddress((void**)&wvl, g_wvl);
    cudaGetSymbolAddress((void**)&woh, g_woh);   cudaGetSymbolAddress((void**)&wol, g_wol);
    cudaGetSymbolAddress((void**)&hh, g_hh);     cudaGetSymbolAddress((void**)&hl, g_hl);
    cudaGetSymbolAddress((void**)&yh, g_yh);     cudaGetSymbolAddress((void**)&yl, g_yl);
    cudaGetSymbolAddress((void**)&qh, g_qh);     cudaGetSymbolAddress((void**)&ql, g_ql);
    cudaGetSymbolAddress((void**)&zh, g_zh);     cudaGetSymbolAddress((void**)&zl, g_zl);
    cudaGetSymbolAddress((void**)&oh, g_oh);     cudaGetSymbolAddress((void**)&ol, g_ol);
    cudaGetSymbolAddress((void**)&t, g_t);

    cudaFuncSetAttribute(mma_gemm<0>, cudaFuncAttributeMaxDynamicSharedMemorySize, SMEM_T);
    cudaFuncSetAttribute(mma_gemm<1>, cudaFuncAttributeMaxDynamicSharedMemorySize, SMEM_T);
    cudaFuncSetAttribute(mma_gemm<2>, cudaFuncAttributeMaxDynamicSharedMemorySize, SMEM_T);
    cudaFuncSetAttribute(mma_gemm<3>, cudaFuncAttributeMaxDynamicSharedMemorySize, SMEM_T);
    cudaFuncSetAttribute(mma_gemm<4>, cudaFuncAttributeMaxDynamicSharedMemorySize, SMEM_T);

    const size_t sBD = (size_t)Bsz * Dm, sBF = (size_t)Bsz * Ff;
    const size_t sDD = (size_t)Dm * Dm, sFD = (size_t)Ff * Dm;

    // 1) conversions / TT materialization
    split_arr<<<(Bsz * Dm) / 256, 256>>>(x, xh, xl, sBD);
    split_arr<<<(Dm * Dm) / 256, 256>>>(wk, wk2h, wk2l, sDD);   // straight layout
    tsplit_w<<<(Dm * Dm) / 256, 256>>>(wq, wqh, wql);
    tsplit_w<<<(Dm * Dm) / 256, 256>>>(wv, wvh, wvl);
    tsplit_w<<<(Dm * Dm) / 256, 256>>>(wo, woh, wol);
    build_w1t<<<(Ssup * Ff * Dm) / 256, 256>>>(g1a, g1b, w1h, w1l);
    build_w2t<<<(Ssup * Dm * Ff) / 256, 256>>>(g2a, g2b, w2h, w2l);

    // 2) FFN1: h[s] = gelu(x @ w1t[s]^T)   [M=B, N=F, K=D]
    mma_gemm<1><<<dim3(Ff/BN, Bsz/BM, Ssup), 256, SMEM_T>>>(
        xh, xl, Dm, 0, w1h, w1l, Dm, sFD, Dm, Ff, sBF,
        nullptr, hh, hl, nullptr, 0);

    // 3) FFN2: y[s] = h[s] @ w2t[s]^T      [M=B, N=D, K=F]   (K=Ff — fixed)
    mma_gemm<0><<<dim3(Dm/BN, Bsz/BM, Ssup), 256, SMEM_T>>>(
        hh, hl, Ff, sBF, w2h, w2l, Ff, (size_t)Dm*Ff, Ff, Dm, sBD,
        nullptr, yh, yl, nullptr, 0);

    // 4) q = x @ wq + bq -> split bf16
    mma_gemm<3><<<dim3(Dm/BN, Bsz/BM, 1), 256, SMEM_T>>>(
        xh, xl, Dm, 0, wqh, wql, Dm, 0, Dm, Dm, 0,
        nullptr, qh, ql, bq, 0);

    // 5) t[h] = q[:,h-block] @ wk[:,h-block]^T   [M=B, N=D, K=256] batched over h
    mma_gemm<4><<<dim3(Dm/BN, Bsz/BM, Hh), 256, SMEM_T>>>(
        qh, ql, Dm, HD, wk2h, wk2l, Dm, HD, HD, Dm, sBD,
        t, nullptr, nullptr, nullptr, 0);

    // 6) scores + softmax + z
    attn_collapse<<<Bsz, 256>>>(qh, ql, t, yh, yl, bk, zh, zl);

    // 7) o[:,h-block] = z[h] @ wv[:,h-block]^T + bv[h-block]   [M=B, N=256, K=D]
    mma_gemm<3><<<dim3(1, Bsz/BM, Hh), 256, SMEM_T>>>(
        zh, zl, Dm, sBD, wvh, wvl, Dm, (size_t)HD*Dm, Dm, Dm, (size_t)HD,
        nullptr, oh, ol, bv, HD);

    // 8) out = o @ wo + bo (fp32)
    mma_gemm<2><<<dim3(Dm/BN, Bsz/BM, 1), 256, SMEM_T>>>(
        oh, ol, Dm, 0, woh, wol, Dm, 0, Dm, Dm, 0,
        out, nullptr, nullptr, bo, 0);
}

// round 6
// speedup vs baseline: 2.7569x; 1.2872x over previous
#include <cuda_runtime.h>
#include <cuda_fp16.h>
#include <math.h>
#include <stdint.h>

// ---------------- problem constants ----------------
#define Bsz 8192
#define Dm  1024
#define Ff  4096
#define Ssup 4
#define Hh  4
#define HD  256

// ---------------- GEMM tiling ----------------
#define BM 128
#define BN 256
#define BK 32                    // fp16 elems per k-tile (64B rows)
#define NST 4
#define A_B   (BM * BK * 2)      // 8192 bytes (one matrix, hi or lo)
#define B_B   (BN * BK * 2)      // 16384 bytes
#define STAGE_B (2 * A_B + B_B)  // 32768
#define SMEM_T  (NST * STAGE_B)  // 131072

// ---------------- scratch (device globals) ----------------
__device__ __half g_xh [(size_t)Bsz*Dm],     g_xl [(size_t)Bsz*Dm];
__device__ __half g_w1 [(size_t)Ssup*Ff*Dm];   // [s][f][d] (transposed)
__device__ __half g_w2 [(size_t)Ssup*Dm*Ff];   // [s][d][f]
__device__ __half g_wq [(size_t)Dm*Dm];        // transposed [n][k]
__device__ __half g_wk2[(size_t)Dm*Dm];        // straight [m][d]
__device__ __half g_wv [(size_t)Dm*Dm];        // transposed
__device__ __half g_wo [(size_t)Dm*Dm];        // transposed
__device__ __half g_hh [(size_t)Ssup*Bsz*Ff],  g_hl [(size_t)Ssup*Bsz*Ff];
__device__ __half g_yh [(size_t)Ssup*Bsz*Dm],  g_yl [(size_t)Ssup*Bsz*Dm];
__device__ __half g_qh [(size_t)Bsz*Dm],       g_ql [(size_t)Bsz*Dm];
__device__ __half g_zh [(size_t)Hh*Bsz*Dm],    g_zl [(size_t)Hh*Bsz*Dm];  // [h][b][m]
__device__ __half g_oh [(size_t)Bsz*Dm],       g_ol [(size_t)Bsz*Dm];
__device__ float g_t [(size_t)Hh*Bsz*Dm];      // [h][b][m]

// ---------------- asm helpers (generic-target PTX, sm_80+) ----------------
__device__ __forceinline__ uint32_t smem_u32(const void* p) {
    uint32_t a;
    asm("{ .reg .u64 t; cvta.to.shared.u64 t, %1; cvt.u32.u64 %0, t; }" : "=r"(a) : "l"(p));
    return a;
}
__device__ __forceinline__ void cp16(uint32_t dst, const void* src) {
    asm volatile("cp.async.cg.shared.global [%0], [%1], 16;" :: "r"(dst), "l"(src));
}
#define CP_COMMIT() asm volatile("cp.async.commit_group;" ::: "memory")
#define CP_WAIT(n)  asm volatile("cp.async.wait_group %0;" :: "n"(n) : "memory")
#define LDSM4(r, a) asm volatile("ldmatrix.sync.aligned.m8n8.x4.shared.b16 {%0,%1,%2,%3}, [%4];" \
    : "=r"((r)[0]), "=r"((r)[1]), "=r"((r)[2]), "=r"((r)[3]) : "r"(a))
#define MMA16816(ac, a, b0, b1) \
    asm volatile("mma.sync.aligned.m16n8k16.row.col.f32.f16.f16.f32 " \
        "{%0,%1,%2,%3}, {%4,%5,%6,%7}, {%8,%9}, {%0,%1,%2,%3};" \
        : "+f"((ac)[0]), "+f"((ac)[1]), "+f"((ac)[2]), "+f"((ac)[3]) \
        : "r"((a)[0]), "r"((a)[1]), "r"((a)[2]), "r"((a)[3]), "r"(b0), "r"(b1))

__device__ __forceinline__ float gelu_exact(float x) {
    return 0.5f * x * (1.0f + erff(x * 0.70710678118654752440f));
}
__device__ __forceinline__ void split2(float v, __half* h, __half* l) {
    __half hb = __float2half(v);
    *h = hb;
    *l = __float2half(v - __half2float(hb));
}
// 16B-chunk swizzle for 64B rows
__device__ __forceinline__ uint32_t swz(int row, int c16) {
    return (uint32_t)(row * 4 + (c16 ^ ((row >> 1) & 3))) * 16u;
}

// ---------------- conversion / build kernels ----------------
__global__ void split_arr(const float* __restrict__ in, __half* __restrict__ hi,
                          __half* __restrict__ lo, size_t n) {
    size_t i = (size_t)blockIdx.x * blockDim.x + threadIdx.x;
    if (i < n) split2(in[i], &hi[i], &lo[i]);
}
// straight fp16 round
__global__ void half_arr(const float* __restrict__ in, __half* __restrict__ o, size_t n) {
    size_t i = (size_t)blockIdx.x * blockDim.x + threadIdx.x;
    if (i < n) o[i] = __float2half(in[i]);
}
// w [K=D, N=D] -> wt[n][k] fp16
__global__ void thalf_w(const float* __restrict__ w, __half* __restrict__ o) {
    size_t e = (size_t)blockIdx.x * blockDim.x + threadIdx.x;
    int n = (int)(e >> 10), k = (int)(e & 1023);
    o[e] = __float2half(w[(size_t)k * Dm + n]);
}
__global__ void build_w1t(const float* __restrict__ g1a, const float* __restrict__ g1b,
                          __half* __restrict__ o) {
    size_t e = (size_t)blockIdx.x * blockDim.x + threadIdx.x;
    int s = (int)(e >> 22), f = (int)((e >> 10) & 4095), d = (int)(e & 1023);
    int i1 = d >> 5, i2 = d & 31, o1 = f >> 6, o2 = f & 63;
    const float* a = g1a + (((size_t)s * 32 + i1) * 64 + o1) * 16;
    const float* b = g1b + (size_t)s * 32768 + (size_t)i2 * 64 + o2;
    float sum = 0.f;
#pragma unroll
    for (int r = 0; r < 16; r++) sum += a[r] * b[(size_t)r * 2048];
    o[e] = __float2half(sum);
}
__global__ void build_w2t(const float* __restrict__ g2a, const float* __restrict__ g2b,
                          __half* __restrict__ o) {
    size_t e = (size_t)blockIdx.x * blockDim.x + threadIdx.x;
    int s = (int)(e >> 22), d = (int)((e >> 12) & 1023), f = (int)(e & 4095);
    int o1 = f >> 6, o2 = f & 63, i1 = d >> 5, i2 = d & 31;
    const float* a = g2a + (((size_t)s * 64 + o1) * 32 + i1) * 16;
    const float* b = g2b + (size_t)s * 32768 + (size_t)o2 * 32 + i2;
    float sum = 0.f;
#pragma unroll
    for (int r = 0; r < 16; r++) sum += a[r] * b[(size_t)r * 2048];
    o[e] = __float2half(sum);
}

// ---------------- fp16x2 HMMA GEMM ----------------
// C = A * B^T. A split (Ah+Al) fp16x2, B single fp16. A: [BM rows, K] lda;
// B: [N rows, K] ldb. Batched over blockIdx.z via element offsets.
// EPI: 0 split, 1 gelu+split, 2 bias+fp32, 3 bias+split, 4 fp32
template <int EPI>
__global__ __launch_bounds__(256, 1)
void mma_gemm(const __half* __restrict__ Ah, const __half* __restrict__ Al,
              int lda, size_t aBS,
              const __half* __restrict__ Bh, int ldb, size_t bBS,
              int K, int ldc, size_t cBS,
              float* __restrict__ Cf,
              __half* __restrict__ Chi, __half* __restrict__ Clo,
              const float* __restrict__ bias, size_t biasBS)
{
    extern __shared__ char smem[];
    const uint32_t sb = smem_u32(smem);
    const int tid = threadIdx.x, wid = tid >> 5, lane = tid & 31;
    const int zz = blockIdx.z;
    const int m0 = blockIdx.y * BM, n0 = blockIdx.x * BN;

    const __half* pAh = Ah + (size_t)zz * aBS;
    const __half* pAl = Al + (size_t)zz * aBS;
    const __half* pBh = Bh + (size_t)zz * bBS;

    const int mwarp = (wid & 1) * 64;    // 2 warps over M
    const int nwarp = (wid >> 1) * 64;   // 4 warps over N

    float acc[4][8][4];
#pragma unroll
    for (int i = 0; i < 4; i++)
#pragma unroll
        for (int j = 0; j < 8; j++)
#pragma unroll
            for (int c = 0; c < 4; c++) acc[i][j][c] = 0.f;

    const int nk = K / BK;
    const int fr = tid >> 2, fc = tid & 3;

    auto fill = [&](int kt, int st) {
        const int k0 = kt * BK;
        const uint32_t base = sb + st * STAGE_B;
#pragma unroll
        for (int i = 0; i < 2; i++) {
            int r = fr + i * 64;
            cp16(base + swz(r, fc),       pAh + (size_t)(m0 + r) * lda + k0 + fc * 8);
            cp16(base + A_B + swz(r, fc), pAl + (size_t)(m0 + r) * lda + k0 + fc * 8);
        }
#pragma unroll
        for (int i = 0; i < 4; i++) {
            int r = fr + i * 64;
            cp16(base + 2*A_B + swz(r, fc), pBh + (size_t)(n0 + r) * ldb + k0 + fc * 8);
        }
        CP_COMMIT();
    };

    fill(0, 0);
    if (nk > 1) fill(1, 1);
    if (nk > 2) fill(2, 2);

    const int ra = lane & 15, ca = lane >> 4;
    const int gb = lane >> 3, rb = lane & 7;

    for (int kt = 0; kt < nk; kt++) {
        if (kt + 1 >= nk)      { CP_WAIT(0); }
        else if (kt + 2 >= nk) { CP_WAIT(1); }
        else                   { CP_WAIT(2); }
        __syncthreads();
        if (kt + 3 < nk) fill(kt + 3, (kt + 3) % NST);

        const uint32_t base = sb + (kt % NST) * STAGE_B;
        const uint32_t sAh = base, sAl = base + A_B;
        const uint32_t sBh = base + 2 * A_B;

#pragma unroll
        for (int kk = 0; kk < 2; kk++) {
            uint32_t ah[4][4], al[4][4];
#pragma unroll
            for (int mt = 0; mt < 4; mt++) {
                uint32_t off = swz(mwarp + mt * 16 + ra, kk * 2 + ca);
                LDSM4(ah[mt], sAh + off);
                LDSM4(al[mt], sAl + off);
            }
#pragma unroll
            for (int p = 0; p < 4; p++) {
                uint32_t bh[4];
                uint32_t off = swz(nwarp + p * 16 + (gb & 1) * 8 + rb, kk * 2 + (gb >> 1));
                LDSM4(bh, sBh + off);
#pragma unroll
                for (int mt = 0; mt < 4; mt++) {
                    MMA16816(acc[mt][2*p],   ah[mt], bh[0], bh[2]);
                    MMA16816(acc[mt][2*p],   al[mt], bh[0], bh[2]);
                    MMA16816(acc[mt][2*p+1], ah[mt], bh[1], bh[3]);
                    MMA16816(acc[mt][2*p+1], al[mt], bh[1], bh[3]);
                }
            }
        }
    }

    // ---------------- epilogue ----------------
    float* Cfp = Cf ? Cf + (size_t)zz * cBS : nullptr;
    __half* Chp = Chi ? Chi + (size_t)zz * cBS : nullptr;
    __half* Clp = Clo ? Clo + (size_t)zz * cBS : nullptr;
    const float* bp = bias ? bias + (size_t)zz * biasBS : nullptr;
    const int g4 = lane >> 2, q2 = (lane & 3) * 2;

#pragma unroll
    for (int mt = 0; mt < 4; mt++) {
#pragma unroll
        for (int nt = 0; nt < 8; nt++) {
            int r0 = m0 + mwarp + mt * 16 + g4;
            int c  = n0 + nwarp + nt * 8 + q2;
#pragma unroll
            for (int half = 0; half < 2; half++) {
                int rr = r0 + half * 8;
                float v0 = acc[mt][nt][half * 2 + 0];
                float v1 = acc[mt][nt][half * 2 + 1];
                size_t off = (size_t)rr * ldc + c;
                if (EPI == 2) {
                    *reinterpret_cast<float2*>(&Cfp[off]) =
                        make_float2(v0 + bp[c], v1 + bp[c + 1]);
                } else if (EPI == 4) {
                    *reinterpret_cast<float2*>(&Cfp[off]) = make_float2(v0, v1);
                } else {
                    if (EPI == 1) { v0 = gelu_exact(v0); v1 = gelu_exact(v1); }
                    if (EPI == 3) { v0 += bp[c]; v1 += bp[c + 1]; }
                    __half2 h2, l2;
                    split2(v0, &h2.x, &l2.x);
                    split2(v1, &h2.y, &l2.y);
                    *reinterpret_cast<__half2*>(&Chp[off]) = h2;
                    *reinterpret_cast<__half2*>(&Clp[off]) = l2;
                }
            }
        }
    }
}

// ---------------- attention collapse: scores, softmax, z ----------------
// scores[b,h,s] = (y_s[b,:]·t[h,b,:] + q[b,h,:]·bk[h,:]) / 16
// z[h,b,m] = sum_s attn[b,h,s] * y_s[b,m]    (split fp16 out)
__global__ __launch_bounds__(256)
void attn_collapse(const __half* __restrict__ qh, const __half* __restrict__ ql,
                   const float* __restrict__ t,
                   const __half* __restrict__ yh, const __half* __restrict__ yl,
                   const float* __restrict__ bk,
                   __half* __restrict__ zh, __half* __restrict__ zl)
{
    const int b = blockIdx.x, tid = threadIdx.x;
    const int wid = tid >> 5, lane = tid & 31;
    __shared__ float ys[Ssup][Dm];
    __shared__ float sc[16], qb[Hh], attn[16];

#pragma unroll
    for (int it = 0; it < 16; it++) {
        int idx = tid + it * 256;
        int s = idx >> 10, m = idx & 1023;
        size_t g = ((size_t)s * Bsz + b) * Dm + m;
        ys[s][m] = __half2float(yh[g]) + __half2float(yl[g]);
    }
    if (wid < Hh) {
        float sum = 0.f;
        for (int j = lane; j < HD; j += 32) {
            size_t g = (size_t)b * Dm + wid * HD + j;
            float qv = __half2float(qh[g]) + __half2float(ql[g]);
            sum = fmaf(qv, bk[wid * HD + j], sum);
        }
#pragma unroll
        for (int o = 16; o; o >>= 1) sum += __shfl_xor_sync(0xffffffffu, sum, o);
        if (lane == 0) qb[wid] = sum;
    }
    __syncthreads();

#pragma unroll
    for (int i = 0; i < 2; i++) {
        int p = wid * 2 + i;
        int h = p >> 2, s = p & 3;
        const float* tp = t + ((size_t)h * Bsz + b) * Dm;
        float sum = 0.f;
        for (int m = lane; m < Dm; m += 32) sum = fmaf(ys[s][m], tp[m], sum);
#pragma unroll
        for (int o = 16; o; o >>= 1) sum += __shfl_xor_sync(0xffffffffu, sum, o);
        if (lane == 0) sc[p] = sum;
    }
    __syncthreads();

    if (tid < Hh) {
        int h = tid;
        float s0 = (sc[h*4+0] + qb[h]) * 0.0625f;
        float s1 = (sc[h*4+1] + qb[h]) * 0.0625f;
        float s2 = (sc[h*4+2] + qb[h]) * 0.0625f;
        float s3 = (sc[h*4+3] + qb[h]) * 0.0625f;
        float m = fmaxf(fmaxf(s0, s1), fmaxf(s2, s3));
        float e0 = expf(s0-m), e1 = expf(s1-m), e2 = expf(s2-m), e3 = expf(s3-m);
        float inv = 1.f / (e0 + e1 + e2 + e3);
        attn[h*4+0] = e0*inv; attn[h*4+1] = e1*inv;
        attn[h*4+2] = e2*inv; attn[h*4+3] = e3*inv;
    }
    __syncthreads();

#pragma unroll
    for (int it = 0; it < 16; it++) {
        int idx = tid + it * 256;
        int h = idx >> 10, m = idx & 1023;
        float a0 = attn[h*4+0], a1 = attn[h*4+1], a2 = attn[h*4+2], a3 = attn[h*4+3];
        float zv = a0*ys[0][m] + a1*ys[1][m] + a2*ys[2][m] + a3*ys[3][m];
        size_t g = ((size_t)h * Bsz + b) * Dm + m;
        split2(zv, &zh[g], &zl[g]);
    }
}

// ---------------- launch ----------------
extern "C" void kernel_launch(void* const* d_in, const int* in_sizes, int n_in,
                              void* d_out, int out_size)
{
    const float* x   = (const float*)d_in[0];
    const float* g1a = (const float*)d_in[1];
    const float* g1b = (const float*)d_in[2];
    const float* g2a = (const float*)d_in[3];
    const float* g2b = (const float*)d_in[4];
    const float* wq  = (const float*)d_in[5];
    const float* bq  = (const float*)d_in[6];
    const float* wk  = (const float*)d_in[7];
    const float* bk  = (const float*)d_in[8];
    const float* wv  = (const float*)d_in[9];
    const float* bv  = (const float*)d_in[10];
    const float* wo  = (const float*)d_in[11];
    const float* bo  = (const float*)d_in[12];
    float* out = (float*)d_out;

    __half *xh,*xl,*w1,*w2,*wqp,*wk2,*wvp,*wop,*hh,*hl,*yh,*yl,*qh,*ql,*zh,*zl,*oh,*ol;
    float *t;
    cudaGetSymbolAddress((void**)&xh, g_xh);   cudaGetSymbolAddress((void**)&xl, g_xl);
    cudaGetSymbolAddress((void**)&w1, g_w1);   cudaGetSymbolAddress((void**)&w2, g_w2);
    cudaGetSymbolAddress((void**)&wqp, g_wq);  cudaGetSymbolAddress((void**)&wk2, g_wk2);
    cudaGetSymbolAddress((void**)&wvp, g_wv);  cudaGetSymbolAddress((void**)&wop, g_wo);
    cudaGetSymbolAddress((void**)&hh, g_hh);   cudaGetSymbolAddress((void**)&hl, g_hl);
    cudaGetSymbolAddress((void**)&yh, g_yh);   cudaGetSymbolAddress((void**)&yl, g_yl);
    cudaGetSymbolAddress((void**)&qh, g_qh);   cudaGetSymbolAddress((void**)&ql, g_ql);
    cudaGetSymbolAddress((void**)&zh, g_zh);   cudaGetSymbolAddress((void**)&zl, g_zl);
    cudaGetSymbolAddress((void**)&oh, g_oh);   cudaGetSymbolAddress((void**)&ol, g_ol);
    cudaGetSymbolAddress((void**)&t, g_t);

    cudaFuncSetAttribute(mma_gemm<0>, cudaFuncAttributeMaxDynamicSharedMemorySize, SMEM_T);
    cudaFuncSetAttribute(mma_gemm<1>, cudaFuncAttributeMaxDynamicSharedMemorySize, SMEM_T);
    cudaFuncSetAttribute(mma_gemm<2>, cudaFuncAttributeMaxDynamicSharedMemorySize, SMEM_T);
    cudaFuncSetAttribute(mma_gemm<3>, cudaFuncAttributeMaxDynamicSharedMemorySize, SMEM_T);
    cudaFuncSetAttribute(mma_gemm<4>, cudaFuncAttributeMaxDynamicSharedMemorySize, SMEM_T);

    const size_t sBD = (size_t)Bsz * Dm, sBF = (size_t)Bsz * Ff;
    const size_t sDD = (size_t)Dm * Dm, sFD = (size_t)Ff * Dm;

    // 1) conversions / TT materialization
    split_arr<<<(Bsz * Dm) / 256, 256>>>(x, xh, xl, sBD);
    half_arr<<<(Dm * Dm) / 256, 256>>>(wk, wk2, sDD);     // straight layout
    thalf_w<<<(Dm * Dm) / 256, 256>>>(wq, wqp);
    thalf_w<<<(Dm * Dm) / 256, 256>>>(wv, wvp);
    thalf_w<<<(Dm * Dm) / 256, 256>>>(wo, wop);
    build_w1t<<<(Ssup * Ff * Dm) / 256, 256>>>(g1a, g1b, w1);
    build_w2t<<<(Ssup * Dm * Ff) / 256, 256>>>(g2a, g2b, w2);

    // 2) FFN1: h[s] = gelu(x @ w1t[s]^T)   [M=B, N=F, K=D]
    mma_gemm<1><<<dim3(Ff/BN, Bsz/BM, Ssup), 256, SMEM_T>>>(
        xh, xl, Dm, 0, w1, Dm, sFD, Dm, Ff, sBF,
        nullptr, hh, hl, nullptr, 0);

    // 3) FFN2: y[s] = h[s] @ w2t[s]^T      [M=B, N=D, K=F]
    mma_gemm<0><<<dim3(Dm/BN, Bsz/BM, Ssup), 256, SMEM_T>>>(
        hh, hl, Ff, sBF, w2, Ff, (size_t)Dm*Ff, Ff, Dm, sBD,
        nullptr, yh, yl, nullptr, 0);

    // 4) q = x @ wq + bq -> split fp16
    mma_gemm<3><<<dim3(Dm/BN, Bsz/BM, 1), 256, SMEM_T>>>(
        xh, xl, Dm, 0, wqp, Dm, 0, Dm, Dm, 0,
        nullptr, qh, ql, bq, 0);

    // 5) t[h] = q[:,h-block] @ wk[:,h-block]^T   [M=B, N=D, K=256] batched over h
    mma_gemm<4><<<dim3(Dm/BN, Bsz/BM, Hh), 256, SMEM_T>>>(
        qh, ql, Dm, HD, wk2, Dm, HD, HD, Dm, sBD,
        t, nullptr, nullptr, nullptr, 0);

    // 6) scores + softmax + z
    attn_collapse<<<Bsz, 256>>>(qh, ql, t, yh, yl, bk, zh, zl);

    // 7) o[:,h-block] = z[h] @ wv[:,h-block]^T + bv[h-block]   [M=B, N=256, K=D]
    mma_gemm<3><<<dim3(1, Bsz/BM, Hh), 256, SMEM_T>>>(
        zh, zl, Dm, sBD, wvp, Dm, (size_t)HD*Dm, Dm, Dm, (size_t)HD,
        nullptr, oh, ol, bv, HD);

    // 8) out = o @ wo + bo (fp32)
    mma_gemm<2><<<dim3(Dm/BN, Bsz/BM, 1), 256, SMEM_T>>>(
        oh, ol, Dm, 0, wop, Dm, 0, Dm, Dm, 0,
        out, nullptr, nullptr, bo, 0);
}

// round 7
// speedup vs baseline: 3.6437x; 1.3217x over previous
#include <cuda_runtime.h>
#include <cuda_fp16.h>
#include <math.h>
#include <stdint.h>

// ---------------- problem constants ----------------
#define Bsz 8192
#define Dm  1024
#define Ff  4096
#define Ssup 4
#define Hh  4
#define HD  256

// ---------------- GEMM tiling ----------------
#define BM 128
#define BN 256
#define BK 32                    // fp16 elems per k-tile (64B rows)
#define NST 4
#define A_B   (BM * BK * 2)      // 8192 bytes per A matrix (hi or lo)
#define B_B   (BN * BK * 2)      // 16384 bytes

// ---------------- scratch (device globals) ----------------
__device__ __half g_xh [(size_t)Bsz*Dm],     g_xl [(size_t)Bsz*Dm];
__device__ __half g_w1 [(size_t)Ssup*Ff*Dm];   // [s][f][d] (transposed)
__device__ __half g_w2 [(size_t)Ssup*Dm*Ff];   // [s][d][f]
__device__ __half g_wq [(size_t)Dm*Dm];        // transposed [n][k]
__device__ __half g_wk2[(size_t)Dm*Dm];        // straight [m][d]
__device__ __half g_wv [(size_t)Dm*Dm];        // transposed
__device__ __half g_wo [(size_t)Dm*Dm];        // transposed
__device__ __half g_hh [(size_t)Ssup*Bsz*Ff];                             // h single fp16
__device__ __half g_yh [(size_t)Ssup*Bsz*Dm],  g_yl [(size_t)Ssup*Bsz*Dm];
__device__ __half g_qh [(size_t)Bsz*Dm],       g_ql [(size_t)Bsz*Dm];
__device__ __half g_zh [(size_t)Hh*Bsz*Dm],    g_zl [(size_t)Hh*Bsz*Dm];  // [h][b][m]
__device__ __half g_oh [(size_t)Bsz*Dm],       g_ol [(size_t)Bsz*Dm];
__device__ float g_t [(size_t)Hh*Bsz*Dm];      // [h][b][m]

// ---------------- asm helpers (generic-target PTX, sm_80+) ----------------
__device__ __forceinline__ uint32_t smem_u32(const void* p) {
    uint32_t a;
    asm("{ .reg .u64 t; cvta.to.shared.u64 t, %1; cvt.u32.u64 %0, t; }" : "=r"(a) : "l"(p));
    return a;
}
__device__ __forceinline__ void cp16(uint32_t dst, const void* src) {
    asm volatile("cp.async.cg.shared.global [%0], [%1], 16;" :: "r"(dst), "l"(src));
}
#define CP_COMMIT() asm volatile("cp.async.commit_group;" ::: "memory")
#define CP_WAIT(n)  asm volatile("cp.async.wait_group %0;" :: "n"(n) : "memory")
#define LDSM4(r, a) asm volatile("ldmatrix.sync.aligned.m8n8.x4.shared.b16 {%0,%1,%2,%3}, [%4];" \
    : "=r"((r)[0]), "=r"((r)[1]), "=r"((r)[2]), "=r"((r)[3]) : "r"(a))
#define MMA16816(ac, a, b0, b1) \
    asm volatile("mma.sync.aligned.m16n8k16.row.col.f32.f16.f16.f32 " \
        "{%0,%1,%2,%3}, {%4,%5,%6,%7}, {%8,%9}, {%0,%1,%2,%3};" \
        : "+f"((ac)[0]), "+f"((ac)[1]), "+f"((ac)[2]), "+f"((ac)[3]) \
        : "r"((a)[0]), "r"((a)[1]), "r"((a)[2]), "r"((a)[3]), "r"(b0), "r"(b1))

__device__ __forceinline__ float gelu_exact(float x) {
    return 0.5f * x * (1.0f + erff(x * 0.70710678118654752440f));
}
__device__ __forceinline__ void split2(float v, __half* h, __half* l) {
    __half hb = __float2half(v);
    *h = hb;
    *l = __float2half(v - __half2float(hb));
}
// 16B-chunk swizzle for 64B rows
__device__ __forceinline__ uint32_t swz(int row, int c16) {
    return (uint32_t)(row * 4 + (c16 ^ ((row >> 1) & 3))) * 16u;
}

// ---------------- conversion / build kernels ----------------
__global__ void split_arr(const float* __restrict__ in, __half* __restrict__ hi,
                          __half* __restrict__ lo, size_t n) {
    size_t i = (size_t)blockIdx.x * blockDim.x + threadIdx.x;
    if (i < n) split2(in[i], &hi[i], &lo[i]);
}
__global__ void half_arr(const float* __restrict__ in, __half* __restrict__ o, size_t n) {
    size_t i = (size_t)blockIdx.x * blockDim.x + threadIdx.x;
    if (i < n) o[i] = __float2half(in[i]);
}
__global__ void thalf_w(const float* __restrict__ w, __half* __restrict__ o) {
    size_t e = (size_t)blockIdx.x * blockDim.x + threadIdx.x;
    int n = (int)(e >> 10), k = (int)(e & 1023);
    o[e] = __float2half(w[(size_t)k * Dm + n]);
}
__global__ void build_w1t(const float* __restrict__ g1a, const float* __restrict__ g1b,
                          __half* __restrict__ o) {
    size_t e = (size_t)blockIdx.x * blockDim.x + threadIdx.x;
    int s = (int)(e >> 22), f = (int)((e >> 10) & 4095), d = (int)(e & 1023);
    int i1 = d >> 5, i2 = d & 31, o1 = f >> 6, o2 = f & 63;
    const float* a = g1a + (((size_t)s * 32 + i1) * 64 + o1) * 16;
    const float* b = g1b + (size_t)s * 32768 + (size_t)i2 * 64 + o2;
    float sum = 0.f;
#pragma unroll
    for (int r = 0; r < 16; r++) sum += a[r] * b[(size_t)r * 2048];
    o[e] = __float2half(sum);
}
__global__ void build_w2t(const float* __restrict__ g2a, const float* __restrict__ g2b,
                          __half* __restrict__ o) {
    size_t e = (size_t)blockIdx.x * blockDim.x + threadIdx.x;
    int s = (int)(e >> 22), d = (int)((e >> 12) & 1023), f = (int)(e & 4095);
    int o1 = f >> 6, o2 = f & 63, i1 = d >> 5, i2 = d & 31;
    const float* a = g2a + (((size_t)s * 64 + o1) * 32 + i1) * 16;
    const float* b = g2b + (size_t)s * 32768 + (size_t)o2 * 32 + i2;
    float sum = 0.f;
#pragma unroll
    for (int r = 0; r < 16; r++) sum += a[r] * b[(size_t)r * 2048];
    o[e] = __float2half(sum);
}

// ---------------- fp16 HMMA GEMM (XA = 1 plain, 2 compensated A) ----------------
// C = A * B^T. A: [BM rows, K] lda (+ optional Al); B: [N rows, K] ldb.
// Batched over blockIdx.z via element offsets.
// EPI: 0 split, 1 gelu+single, 2 bias+fp32, 3 bias+split, 4 fp32
template <int EPI, int XA>
__global__ __launch_bounds__(256, 1)
void mma_gemm(const __half* __restrict__ Ah, const __half* __restrict__ Al,
              int lda, size_t aBS,
              const __half* __restrict__ Bh, int ldb, size_t bBS,
              int K, int ldc, size_t cBS,
              float* __restrict__ Cf,
              __half* __restrict__ Chi, __half* __restrict__ Clo,
              const float* __restrict__ bias, size_t biasBS)
{
    constexpr uint32_t STG = XA * A_B + B_B;
    extern __shared__ char smem[];
    const uint32_t sb = smem_u32(smem);
    const int tid = threadIdx.x, wid = tid >> 5, lane = tid & 31;
    const int zz = blockIdx.z;
    const int m0 = blockIdx.y * BM, n0 = blockIdx.x * BN;

    const __half* pAh = Ah + (size_t)zz * aBS;
    const __half* pAl = (XA == 2) ? Al + (size_t)zz * aBS : nullptr;
    const __half* pBh = Bh + (size_t)zz * bBS;

    const int mwarp = (wid & 1) * 64;    // 2 warps over M
    const int nwarp = (wid >> 1) * 64;   // 4 warps over N

    float acc[4][8][4];
#pragma unroll
    for (int i = 0; i < 4; i++)
#pragma unroll
        for (int j = 0; j < 8; j++)
#pragma unroll
            for (int c = 0; c < 4; c++) acc[i][j][c] = 0.f;

    const int nk = K / BK;
    const int fr = tid >> 2, fc = tid & 3;

    auto fill = [&](int kt, int st) {
        const int k0 = kt * BK;
        const uint32_t base = sb + st * STG;
#pragma unroll
        for (int i = 0; i < 2; i++) {
            int r = fr + i * 64;
            cp16(base + swz(r, fc), pAh + (size_t)(m0 + r) * lda + k0 + fc * 8);
            if (XA == 2)
                cp16(base + A_B + swz(r, fc), pAl + (size_t)(m0 + r) * lda + k0 + fc * 8);
        }
#pragma unroll
        for (int i = 0; i < 4; i++) {
            int r = fr + i * 64;
            cp16(base + XA*A_B + swz(r, fc), pBh + (size_t)(n0 + r) * ldb + k0 + fc * 8);
        }
        CP_COMMIT();
    };

    fill(0, 0);
    if (nk > 1) fill(1, 1);
    if (nk > 2) fill(2, 2);

    const int ra = lane & 15, ca = lane >> 4;
    const int gb = lane >> 3, rb = lane & 7;

    for (int kt = 0; kt < nk; kt++) {
        if (kt + 1 >= nk)      { CP_WAIT(0); }
        else if (kt + 2 >= nk) { CP_WAIT(1); }
        else                   { CP_WAIT(2); }
        __syncthreads();
        if (kt + 3 < nk) fill(kt + 3, (kt + 3) % NST);

        const uint32_t base = sb + (kt % NST) * STG;
        const uint32_t sAh = base, sAl = base + A_B;
        const uint32_t sBh = base + XA * A_B;

#pragma unroll
        for (int kk = 0; kk < 2; kk++) {
            uint32_t ah[4][4], al[4][4];
#pragma unroll
            for (int mt = 0; mt < 4; mt++) {
                uint32_t off = swz(mwarp + mt * 16 + ra, kk * 2 + ca);
                LDSM4(ah[mt], sAh + off);
                if (XA == 2) LDSM4(al[mt], sAl + off);
            }
#pragma unroll
            for (int p = 0; p < 4; p++) {
                uint32_t bh[4];
                uint32_t off = swz(nwarp + p * 16 + (gb & 1) * 8 + rb, kk * 2 + (gb >> 1));
                LDSM4(bh, sBh + off);
#pragma unroll
                for (int mt = 0; mt < 4; mt++) {
                    MMA16816(acc[mt][2*p],   ah[mt], bh[0], bh[2]);
                    MMA16816(acc[mt][2*p+1], ah[mt], bh[1], bh[3]);
                    if (XA == 2) {
                        MMA16816(acc[mt][2*p],   al[mt], bh[0], bh[2]);
                        MMA16816(acc[mt][2*p+1], al[mt], bh[1], bh[3]);
                    }
                }
            }
        }
    }

    // ---------------- epilogue ----------------
    float* Cfp = Cf ? Cf + (size_t)zz * cBS : nullptr;
    __half* Chp = Chi ? Chi + (size_t)zz * cBS : nullptr;
    __half* Clp = Clo ? Clo + (size_t)zz * cBS : nullptr;
    const float* bp = bias ? bias + (size_t)zz * biasBS : nullptr;
    const int g4 = lane >> 2, q2 = (lane & 3) * 2;

#pragma unroll
    for (int mt = 0; mt < 4; mt++) {
#pragma unroll
        for (int nt = 0; nt < 8; nt++) {
            int r0 = m0 + mwarp + mt * 16 + g4;
            int c  = n0 + nwarp + nt * 8 + q2;
#pragma unroll
            for (int half = 0; half < 2; half++) {
                int rr = r0 + half * 8;
                float v0 = acc[mt][nt][half * 2 + 0];
                float v1 = acc[mt][nt][half * 2 + 1];
                size_t off = (size_t)rr * ldc + c;
                if (EPI == 2) {
                    *reinterpret_cast<float2*>(&Cfp[off]) =
                        make_float2(v0 + bp[c], v1 + bp[c + 1]);
                } else if (EPI == 4) {
                    *reinterpret_cast<float2*>(&Cfp[off]) = make_float2(v0, v1);
                } else if (EPI == 1) {
                    __half2 h2;
                    h2.x = __float2half(gelu_exact(v0));
                    h2.y = __float2half(gelu_exact(v1));
                    *reinterpret_cast<__half2*>(&Chp[off]) = h2;
                } else {
                    if (EPI == 3) { v0 += bp[c]; v1 += bp[c + 1]; }
                    __half2 h2, l2;
                    split2(v0, &h2.x, &l2.x);
                    split2(v1, &h2.y, &l2.y);
                    *reinterpret_cast<__half2*>(&Chp[off]) = h2;
                    *reinterpret_cast<__half2*>(&Clp[off]) = l2;
                }
            }
        }
    }
}

// ---------------- attention collapse: scores, softmax, z ----------------
__global__ __launch_bounds__(256)
void attn_collapse(const __half* __restrict__ qh, const __half* __restrict__ ql,
                   const float* __restrict__ t,
                   const __half* __restrict__ yh, const __half* __restrict__ yl,
                   const float* __restrict__ bk,
                   __half* __restrict__ zh, __half* __restrict__ zl)
{
    const int b = blockIdx.x, tid = threadIdx.x;
    const int wid = tid >> 5, lane = tid & 31;
    __shared__ float ys[Ssup][Dm];
    __shared__ float sc[16], qb[Hh], attn[16];

#pragma unroll
    for (int it = 0; it < 16; it++) {
        int idx = tid + it * 256;
        int s = idx >> 10, m = idx & 1023;
        size_t g = ((size_t)s * Bsz + b) * Dm + m;
        ys[s][m] = __half2float(yh[g]) + __half2float(yl[g]);
    }
    if (wid < Hh) {
        float sum = 0.f;
        for (int j = lane; j < HD; j += 32) {
            size_t g = (size_t)b * Dm + wid * HD + j;
            float qv = __half2float(qh[g]) + __half2float(ql[g]);
            sum = fmaf(qv, bk[wid * HD + j], sum);
        }
#pragma unroll
        for (int o = 16; o; o >>= 1) sum += __shfl_xor_sync(0xffffffffu, sum, o);
        if (lane == 0) qb[wid] = sum;
    }
    __syncthreads();

#pragma unroll
    for (int i = 0; i < 2; i++) {
        int p = wid * 2 + i;
        int h = p >> 2, s = p & 3;
        const float* tp = t + ((size_t)h * Bsz + b) * Dm;
        float sum = 0.f;
        for (int m = lane; m < Dm; m += 32) sum = fmaf(ys[s][m], tp[m], sum);
#pragma unroll
        for (int o = 16; o; o >>= 1) sum += __shfl_xor_sync(0xffffffffu, sum, o);
        if (lane == 0) sc[p] = sum;
    }
    __syncthreads();

    if (tid < Hh) {
        int h = tid;
        float s0 = (sc[h*4+0] + qb[h]) * 0.0625f;
        float s1 = (sc[h*4+1] + qb[h]) * 0.0625f;
        float s2 = (sc[h*4+2] + qb[h]) * 0.0625f;
        float s3 = (sc[h*4+3] + qb[h]) * 0.0625f;
        float m = fmaxf(fmaxf(s0, s1), fmaxf(s2, s3));
        float e0 = expf(s0-m), e1 = expf(s1-m), e2 = expf(s2-m), e3 = expf(s3-m);
        float inv = 1.f / (e0 + e1 + e2 + e3);
        attn[h*4+0] = e0*inv; attn[h*4+1] = e1*inv;
        attn[h*4+2] = e2*inv; attn[h*4+3] = e3*inv;
    }
    __syncthreads();

#pragma unroll
    for (int it = 0; it < 16; it++) {
        int idx = tid + it * 256;
        int h = idx >> 10, m = idx & 1023;
        float a0 = attn[h*4+0], a1 = attn[h*4+1], a2 = attn[h*4+2], a3 = attn[h*4+3];
        float zv = a0*ys[0][m] + a1*ys[1][m] + a2*ys[2][m] + a3*ys[3][m];
        size_t g = ((size_t)h * Bsz + b) * Dm + m;
        split2(zv, &zh[g], &zl[g]);
    }
}

// ---------------- launch ----------------
extern "C" void kernel_launch(void* const* d_in, const int* in_sizes, int n_in,
                              void* d_out, int out_size)
{
    const float* x   = (const float*)d_in[0];
    const float* g1a = (const float*)d_in[1];
    const float* g1b = (const float*)d_in[2];
    const float* g2a = (const float*)d_in[3];
    const float* g2b = (const float*)d_in[4];
    const float* wq  = (const float*)d_in[5];
    const float* bq  = (const float*)d_in[6];
    const float* wk  = (const float*)d_in[7];
    const float* bk  = (const float*)d_in[8];
    const float* wv  = (const float*)d_in[9];
    const float* bv  = (const float*)d_in[10];
    const float* wo  = (const float*)d_in[11];
    const float* bo  = (const float*)d_in[12];
    float* out = (float*)d_out;

    __half *xh,*xl,*w1,*w2,*wqp,*wk2,*wvp,*wop,*hh,*yh,*yl,*qh,*ql,*zh,*zl,*oh,*ol;
    float *t;
    cudaGetSymbolAddress((void**)&xh, g_xh);   cudaGetSymbolAddress((void**)&xl, g_xl);
    cudaGetSymbolAddress((void**)&w1, g_w1);   cudaGetSymbolAddress((void**)&w2, g_w2);
    cudaGetSymbolAddress((void**)&wqp, g_wq);  cudaGetSymbolAddress((void**)&wk2, g_wk2);
    cudaGetSymbolAddress((void**)&wvp, g_wv);  cudaGetSymbolAddress((void**)&wop, g_wo);
    cudaGetSymbolAddress((void**)&hh, g_hh);
    cudaGetSymbolAddress((void**)&yh, g_yh);   cudaGetSymbolAddress((void**)&yl, g_yl);
    cudaGetSymbolAddress((void**)&qh, g_qh);   cudaGetSymbolAddress((void**)&ql, g_ql);
    cudaGetSymbolAddress((void**)&zh, g_zh);   cudaGetSymbolAddress((void**)&zl, g_zl);
    cudaGetSymbolAddress((void**)&oh, g_oh);   cudaGetSymbolAddress((void**)&ol, g_ol);
    cudaGetSymbolAddress((void**)&t, g_t);

    const int SM1 = NST * (A_B + B_B);       // 98304  (XA=1)
    const int SM2 = NST * (2 * A_B + B_B);   // 131072 (XA=2)
    cudaFuncSetAttribute((const void*)mma_gemm<1,1>, cudaFuncAttributeMaxDynamicSharedMemorySize, SM1);
    cudaFuncSetAttribute((const void*)mma_gemm<0,1>, cudaFuncAttributeMaxDynamicSharedMemorySize, SM1);
    cudaFuncSetAttribute((const void*)mma_gemm<3,2>, cudaFuncAttributeMaxDynamicSharedMemorySize, SM2);
    cudaFuncSetAttribute((const void*)mma_gemm<4,2>, cudaFuncAttributeMaxDynamicSharedMemorySize, SM2);
    cudaFuncSetAttribute((const void*)mma_gemm<2,2>, cudaFuncAttributeMaxDynamicSharedMemorySize, SM2);

    const size_t sBD = (size_t)Bsz * Dm, sBF = (size_t)Bsz * Ff;
    const size_t sDD = (size_t)Dm * Dm, sFD = (size_t)Ff * Dm;

    // 1) conversions / TT materialization
    split_arr<<<(Bsz * Dm) / 256, 256>>>(x, xh, xl, sBD);
    half_arr<<<(Dm * Dm) / 256, 256>>>(wk, wk2, sDD);
    thalf_w<<<(Dm * Dm) / 256, 256>>>(wq, wqp);
    thalf_w<<<(Dm * Dm) / 256, 256>>>(wv, wvp);
    thalf_w<<<(Dm * Dm) / 256, 256>>>(wo, wop);
    build_w1t<<<(Ssup * Ff * Dm) / 256, 256>>>(g1a, g1b, w1);
    build_w2t<<<(Ssup * Dm * Ff) / 256, 256>>>(g2a, g2b, w2);

    // 2) FFN1 (plain fp16): h[s] = gelu(x @ w1t[s]^T)  -> single fp16
    mma_gemm<1,1><<<dim3(Ff/BN, Bsz/BM, Ssup), 256, SM1>>>(
        xh, nullptr, Dm, 0, w1, Dm, sFD, Dm, Ff, sBF,
        nullptr, hh, nullptr, nullptr, 0);

    // 3) FFN2 (plain fp16): y[s] = h[s] @ w2t[s]^T -> split fp16
    mma_gemm<0,1><<<dim3(Dm/BN, Bsz/BM, Ssup), 256, SM1>>>(
        hh, nullptr, Ff, sBF, w2, Ff, (size_t)Dm*Ff, Ff, Dm, sBD,
        nullptr, yh, yl, nullptr, 0);

    // 4) q = x @ wq + bq -> split fp16  (x2)
    mma_gemm<3,2><<<dim3(Dm/BN, Bsz/BM, 1), 256, SM2>>>(
        xh, xl, Dm, 0, wqp, Dm, 0, Dm, Dm, 0,
        nullptr, qh, ql, bq, 0);

    // 5) t[h] = q[:,h-block] @ wk[:,h-block]^T  (x2), batched over h
    mma_gemm<4,2><<<dim3(Dm/BN, Bsz/BM, Hh), 256, SM2>>>(
        qh, ql, Dm, HD, wk2, Dm, HD, HD, Dm, sBD,
        t, nullptr, nullptr, nullptr, 0);

    // 6) scores + softmax + z
    attn_collapse<<<Bsz, 256>>>(qh, ql, t, yh, yl, bk, zh, zl);

    // 7) o[:,h-block] = z[h] @ wv[:,h-block]^T + bv  (x2)
    mma_gemm<3,2><<<dim3(1, Bsz/BM, Hh), 256, SM2>>>(
        zh, zl, Dm, sBD, wvp, Dm, (size_t)HD*Dm, Dm, Dm, (size_t)HD,
        nullptr, oh, ol, bv, HD);

    // 8) out = o @ wo + bo (fp32)  (x2)
    mma_gemm<2,2><<<dim3(Dm/BN, Bsz/BM, 1), 256, SM2>>>(
        oh, ol, Dm, 0, wop, Dm, 0, Dm, Dm, 0,
        out, nullptr, nullptr, bo, 0);
}

// round 8
// speedup vs baseline: 4.8776x; 1.3386x over previous
#include <cuda_runtime.h>
#include <cuda_fp16.h>
#include <math.h>
#include <stdint.h>

// ---------------- problem constants ----------------
#define Bsz 8192
#define Dm  1024
#define Ff  4096
#define Ssup 4
#define Hh  4
#define HD  256

// ---------------- GEMM tiling ----------------
#define BM 128
#define BN 256
#define BK 64                    // fp16 elems per k-tile (128B rows)
#define NST 3
#define A_B   (BM * BK * 2)      // 16384 bytes per A matrix (hi or lo)
#define B_B   (BN * BK * 2)      // 32768 bytes

// ---------------- scratch (device globals) ----------------
__device__ __half g_xh [(size_t)Bsz*Dm],     g_xl [(size_t)Bsz*Dm];
__device__ __half g_w1 [(size_t)Ssup*Ff*Dm];   // [s][f][d] (transposed)
__device__ __half g_w2 [(size_t)Ssup*Dm*Ff];   // [s][d][f]
__device__ __half g_wq [(size_t)Dm*Dm];        // transposed [n][k]
__device__ __half g_wk2[(size_t)Dm*Dm];        // straight [m][d]
__device__ __half g_wv [(size_t)Dm*Dm];        // transposed
__device__ __half g_wo [(size_t)Dm*Dm];        // transposed
__device__ __half g_hh [(size_t)Ssup*Bsz*Ff];                             // h single fp16
__device__ __half g_yh [(size_t)Ssup*Bsz*Dm],  g_yl [(size_t)Ssup*Bsz*Dm];
__device__ __half g_qh [(size_t)Bsz*Dm],       g_ql [(size_t)Bsz*Dm];
__device__ __half g_zh [(size_t)Hh*Bsz*Dm],    g_zl [(size_t)Hh*Bsz*Dm];  // [h][b][m]
__device__ __half g_oh [(size_t)Bsz*Dm],       g_ol [(size_t)Bsz*Dm];
__device__ float g_t [(size_t)Hh*Bsz*Dm];      // [h][b][m]

// ---------------- asm helpers (generic-target PTX, sm_80+) ----------------
__device__ __forceinline__ uint32_t smem_u32(const void* p) {
    uint32_t a;
    asm("{ .reg .u64 t; cvta.to.shared.u64 t, %1; cvt.u32.u64 %0, t; }" : "=r"(a) : "l"(p));
    return a;
}
__device__ __forceinline__ void cp16(uint32_t dst, const void* src) {
    asm volatile("cp.async.cg.shared.global [%0], [%1], 16;" :: "r"(dst), "l"(src));
}
#define CP_COMMIT() asm volatile("cp.async.commit_group;" ::: "memory")
#define CP_WAIT(n)  asm volatile("cp.async.wait_group %0;" :: "n"(n) : "memory")
#define LDSM4(r, a) asm volatile("ldmatrix.sync.aligned.m8n8.x4.shared.b16 {%0,%1,%2,%3}, [%4];" \
    : "=r"((r)[0]), "=r"((r)[1]), "=r"((r)[2]), "=r"((r)[3]) : "r"(a))
#define MMA16816(ac, a, b0, b1) \
    asm volatile("mma.sync.aligned.m16n8k16.row.col.f32.f16.f16.f32 " \
        "{%0,%1,%2,%3}, {%4,%5,%6,%7}, {%8,%9}, {%0,%1,%2,%3};" \
        : "+f"((ac)[0]), "+f"((ac)[1]), "+f"((ac)[2]), "+f"((ac)[3]) \
        : "r"((a)[0]), "r"((a)[1]), "r"((a)[2]), "r"((a)[3]), "r"(b0), "r"(b1))

__device__ __forceinline__ float gelu_exact(float x) {
    return 0.5f * x * (1.0f + erff(x * 0.70710678118654752440f));
}
__device__ __forceinline__ void split2(float v, __half* h, __half* l) {
    __half hb = __float2half(v);
    *h = hb;
    *l = __float2half(v - __half2float(hb));
}
// 16B-chunk swizzle for 128B rows (8 chunks per row): chunk' = chunk ^ (row & 7)
__device__ __forceinline__ uint32_t swz(int row, int c16) {
    return (uint32_t)(row * 8 + (c16 ^ (row & 7))) * 16u;
}

// ---------------- conversion / build kernels ----------------
__global__ void split_arr(const float* __restrict__ in, __half* __restrict__ hi,
                          __half* __restrict__ lo, size_t n) {
    size_t i = (size_t)blockIdx.x * blockDim.x + threadIdx.x;
    if (i < n) split2(in[i], &hi[i], &lo[i]);
}
__global__ void half_arr(const float* __restrict__ in, __half* __restrict__ o, size_t n) {
    size_t i = (size_t)blockIdx.x * blockDim.x + threadIdx.x;
    if (i < n) o[i] = __float2half(in[i]);
}
__global__ void thalf_w(const float* __restrict__ w, __half* __restrict__ o) {
    size_t e = (size_t)blockIdx.x * blockDim.x + threadIdx.x;
    int n = (int)(e >> 10), k = (int)(e & 1023);
    o[e] = __float2half(w[(size_t)k * Dm + n]);
}

// smem-tiled w1 build: block (o1, s). Stages full g1b[s] (128KB, padded) + A row slab.
// w1t[s][o1*64+o2][i1*32+i2] = sum_r g1a[s,i1,o1,r] * g1b[s,r,i2,o2]
#define W1_SMEM ((16*32*65 + 512) * 4)
__global__ __launch_bounds__(256)
void build_w1_tiled(const float* __restrict__ g1a, const float* __restrict__ g1b,
                    __half* __restrict__ o)
{
    extern __shared__ float dsm[];
    float* Bs = dsm;                 // [r][i2][o2] stride 65
    float* As = dsm + 16 * 32 * 65;  // [i1][r]
    const int tid = threadIdx.x;
    const int o1 = blockIdx.x, s = blockIdx.y;

    for (int idx = tid; idx < 32768; idx += 256) {
        int r = idx >> 11, i2 = (idx >> 6) & 31, o2 = idx & 63;
        Bs[(r * 32 + i2) * 65 + o2] = g1b[(size_t)s * 32768 + idx];
    }
    for (int idx = tid; idx < 512; idx += 256) {
        int i1 = idx >> 4, r = idx & 15;
        As[idx] = g1a[(((size_t)s * 32 + i1) * 64 + o1) * 16 + r];
    }
    __syncthreads();

    const size_t ob = ((size_t)s * Ff + (size_t)o1 * 64) * Dm;
#pragma unroll 4
    for (int it = 0; it < 256; it++) {
        int idx = tid + (it << 8);
        int o2 = idx >> 10, d = idx & 1023;
        int i1 = d >> 5, i2 = d & 31;
        const float* ap = As + i1 * 16;
        const float* bp = Bs + i2 * 65 + o2;
        float sum = 0.f;
#pragma unroll
        for (int r = 0; r < 16; r++) sum += ap[r] * bp[r * 2080];
        o[ob + (size_t)o2 * Dm + d] = __float2half(sum);
    }
}

// w2t build: broadcast-friendly access pattern (kept simple)
__global__ void build_w2t(const float* __restrict__ g2a, const float* __restrict__ g2b,
                          __half* __restrict__ o) {
    size_t e = (size_t)blockIdx.x * blockDim.x + threadIdx.x;
    int s = (int)(e >> 22), d = (int)((e >> 12) & 1023), f = (int)(e & 4095);
    int o1 = f >> 6, o2 = f & 63, i1 = d >> 5, i2 = d & 31;
    const float* a = g2a + (((size_t)s * 64 + o1) * 32 + i1) * 16;
    const float* b = g2b + (size_t)s * 32768 + (size_t)o2 * 32 + i2;
    float sum = 0.f;
#pragma unroll
    for (int r = 0; r < 16; r++) sum += a[r] * b[(size_t)r * 2048];
    o[e] = __float2half(sum);
}

// ---------------- fp16 HMMA GEMM (XA = 1 plain, 2 compensated A) ----------------
// C = A * B^T. A: [BM rows, K] lda (+ optional Al); B: [N rows, K] ldb.
// Batched over blockIdx.z via element offsets.
// EPI: 0 split, 1 gelu+single, 2 bias+fp32, 3 bias+split, 4 fp32
template <int EPI, int XA>
__global__ __launch_bounds__(256, 1)
void mma_gemm(const __half* __restrict__ Ah, const __half* __restrict__ Al,
              int lda, size_t aBS,
              const __half* __restrict__ Bh, int ldb, size_t bBS,
              int K, int ldc, size_t cBS,
              float* __restrict__ Cf,
              __half* __restrict__ Chi, __half* __restrict__ Clo,
              const float* __restrict__ bias, size_t biasBS)
{
    constexpr uint32_t STG = XA * A_B + B_B;
    extern __shared__ char smem[];
    const uint32_t sb = smem_u32(smem);
    const int tid = threadIdx.x, wid = tid >> 5, lane = tid & 31;
    const int zz = blockIdx.z;
    const int m0 = blockIdx.y * BM, n0 = blockIdx.x * BN;

    const __half* pAh = Ah + (size_t)zz * aBS;
    const __half* pAl = (XA == 2) ? Al + (size_t)zz * aBS : nullptr;
    const __half* pBh = Bh + (size_t)zz * bBS;

    const int mwarp = (wid & 1) * 64;    // 2 warps over M
    const int nwarp = (wid >> 1) * 64;   // 4 warps over N

    float acc[4][8][4];
#pragma unroll
    for (int i = 0; i < 4; i++)
#pragma unroll
        for (int j = 0; j < 8; j++)
#pragma unroll
            for (int c = 0; c < 4; c++) acc[i][j][c] = 0.f;

    const int nk = K / BK;
    const int fr = tid >> 3, fc = tid & 7;   // 32 rows per pass, 8 chunk-cols

    auto fill = [&](int kt, int st) {
        const int k0 = kt * BK;
        const uint32_t base = sb + st * STG;
#pragma unroll
        for (int i = 0; i < 4; i++) {
            int r = fr + i * 32;
            cp16(base + swz(r, fc), pAh + (size_t)(m0 + r) * lda + k0 + fc * 8);
            if (XA == 2)
                cp16(base + A_B + swz(r, fc), pAl + (size_t)(m0 + r) * lda + k0 + fc * 8);
        }
#pragma unroll
        for (int i = 0; i < 8; i++) {
            int r = fr + i * 32;
            cp16(base + XA*A_B + swz(r, fc), pBh + (size_t)(n0 + r) * ldb + k0 + fc * 8);
        }
        CP_COMMIT();
    };

    fill(0, 0);
    if (nk > 1) fill(1, 1);

    const int ra = lane & 15, ca = lane >> 4;
    const int gb = lane >> 3, rb = lane & 7;

    for (int kt = 0; kt < nk; kt++) {
        if (kt + 1 >= nk) { CP_WAIT(0); } else { CP_WAIT(1); }
        __syncthreads();
        if (kt + 2 < nk) fill(kt + 2, (kt + 2) % NST);

        const uint32_t base = sb + (kt % NST) * STG;
        const uint32_t sAh = base, sAl = base + A_B;
        const uint32_t sBh = base + XA * A_B;

#pragma unroll
        for (int kk = 0; kk < 4; kk++) {
            uint32_t ah[4][4], al[4][4];
#pragma unroll
            for (int mt = 0; mt < 4; mt++) {
                uint32_t off = swz(mwarp + mt * 16 + ra, kk * 2 + ca);
                LDSM4(ah[mt], sAh + off);
                if (XA == 2) LDSM4(al[mt], sAl + off);
            }
#pragma unroll
            for (int p = 0; p < 4; p++) {
                uint32_t bh[4];
                uint32_t off = swz(nwarp + p * 16 + (gb & 1) * 8 + rb, kk * 2 + (gb >> 1));
                LDSM4(bh, sBh + off);
#pragma unroll
                for (int mt = 0; mt < 4; mt++) {
                    MMA16816(acc[mt][2*p],   ah[mt], bh[0], bh[2]);
                    MMA16816(acc[mt][2*p+1], ah[mt], bh[1], bh[3]);
                    if (XA == 2) {
                        MMA16816(acc[mt][2*p],   al[mt], bh[0], bh[2]);
                        MMA16816(acc[mt][2*p+1], al[mt], bh[1], bh[3]);
                    }
                }
            }
        }
    }

    // ---------------- epilogue ----------------
    float* Cfp = Cf ? Cf + (size_t)zz * cBS : nullptr;
    __half* Chp = Chi ? Chi + (size_t)zz * cBS : nullptr;
    __half* Clp = Clo ? Clo + (size_t)zz * cBS : nullptr;
    const float* bp = bias ? bias + (size_t)zz * biasBS : nullptr;
    const int g4 = lane >> 2, q2 = (lane & 3) * 2;

#pragma unroll
    for (int mt = 0; mt < 4; mt++) {
#pragma unroll
        for (int nt = 0; nt < 8; nt++) {
            int r0 = m0 + mwarp + mt * 16 + g4;
            int c  = n0 + nwarp + nt * 8 + q2;
#pragma unroll
            for (int half = 0; half < 2; half++) {
                int rr = r0 + half * 8;
                float v0 = acc[mt][nt][half * 2 + 0];
                float v1 = acc[mt][nt][half * 2 + 1];
                size_t off = (size_t)rr * ldc + c;
                if (EPI == 2) {
                    *reinterpret_cast<float2*>(&Cfp[off]) =
                        make_float2(v0 + bp[c], v1 + bp[c + 1]);
                } else if (EPI == 4) {
                    *reinterpret_cast<float2*>(&Cfp[off]) = make_float2(v0, v1);
                } else if (EPI == 1) {
                    __half2 h2;
                    h2.x = __float2half(gelu_exact(v0));
                    h2.y = __float2half(gelu_exact(v1));
                    *reinterpret_cast<__half2*>(&Chp[off]) = h2;
                } else {
                    if (EPI == 3) { v0 += bp[c]; v1 += bp[c + 1]; }
                    __half2 h2, l2;
                    split2(v0, &h2.x, &l2.x);
                    split2(v1, &h2.y, &l2.y);
                    *reinterpret_cast<__half2*>(&Chp[off]) = h2;
                    *reinterpret_cast<__half2*>(&Clp[off]) = l2;
                }
            }
        }
    }
}

// ---------------- attention collapse: scores, softmax, z ----------------
__global__ __launch_bounds__(256)
void attn_collapse(const __half* __restrict__ qh, const __half* __restrict__ ql,
                   const float* __restrict__ t,
                   const __half* __restrict__ yh, const __half* __restrict__ yl,
                   const float* __restrict__ bk,
                   __half* __restrict__ zh, __half* __restrict__ zl)
{
    const int b = blockIdx.x, tid = threadIdx.x;
    const int wid = tid >> 5, lane = tid & 31;
    __shared__ float ys[Ssup][Dm];
    __shared__ float sc[16], qb[Hh], attn[16];

    // stage y (reconstructed fp32), half2-vectorized
#pragma unroll
    for (int it = 0; it < 8; it++) {
        int idx = tid + it * 256;          // 2048 half2 slots
        int s = idx >> 9, mm = idx & 511;
        size_t g = ((size_t)s * Bsz + b) * Dm + mm * 2;
        __half2 h2 = *reinterpret_cast<const __half2*>(&yh[g]);
        __half2 l2 = *reinterpret_cast<const __half2*>(&yl[g]);
        ys[s][mm * 2]     = __half2float(h2.x) + __half2float(l2.x);
        ys[s][mm * 2 + 1] = __half2float(h2.y) + __half2float(l2.y);
    }
    if (wid < Hh) {
        float sum = 0.f;
        for (int j = lane; j < HD; j += 32) {
            size_t g = (size_t)b * Dm + wid * HD + j;
            float qv = __half2float(qh[g]) + __half2float(ql[g]);
            sum = fmaf(qv, bk[wid * HD + j], sum);
        }
#pragma unroll
        for (int o = 16; o; o >>= 1) sum += __shfl_xor_sync(0xffffffffu, sum, o);
        if (lane == 0) qb[wid] = sum;
    }
    __syncthreads();

#pragma unroll
    for (int i = 0; i < 2; i++) {
        int p = wid * 2 + i;
        int h = p >> 2, s = p & 3;
        const float* tp = t + ((size_t)h * Bsz + b) * Dm;
        float sum = 0.f;
        for (int m = lane; m < Dm; m += 32) sum = fmaf(ys[s][m], tp[m], sum);
#pragma unroll
        for (int o = 16; o; o >>= 1) sum += __shfl_xor_sync(0xffffffffu, sum, o);
        if (lane == 0) sc[p] = sum;
    }
    __syncthreads();

    if (tid < Hh) {
        int h = tid;
        float s0 = (sc[h*4+0] + qb[h]) * 0.0625f;
        float s1 = (sc[h*4+1] + qb[h]) * 0.0625f;
        float s2 = (sc[h*4+2] + qb[h]) * 0.0625f;
        float s3 = (sc[h*4+3] + qb[h]) * 0.0625f;
        float m = fmaxf(fmaxf(s0, s1), fmaxf(s2, s3));
        float e0 = expf(s0-m), e1 = expf(s1-m), e2 = expf(s2-m), e3 = expf(s3-m);
        float inv = 1.f / (e0 + e1 + e2 + e3);
        attn[h*4+0] = e0*inv; attn[h*4+1] = e1*inv;
        attn[h*4+2] = e2*inv; attn[h*4+3] = e3*inv;
    }
    __syncthreads();

    // z[h,b,m], half2-vectorized
#pragma unroll
    for (int it = 0; it < 8; it++) {
        int idx = tid + it * 256;
        int h = idx >> 9, mm = idx & 511;
        int m = mm * 2;
        float a0 = attn[h*4+0], a1 = attn[h*4+1], a2 = attn[h*4+2], a3 = attn[h*4+3];
        float z0 = a0*ys[0][m]   + a1*ys[1][m]   + a2*ys[2][m]   + a3*ys[3][m];
        float z1 = a0*ys[0][m+1] + a1*ys[1][m+1] + a2*ys[2][m+1] + a3*ys[3][m+1];
        size_t g = ((size_t)h * Bsz + b) * Dm + m;
        __half2 zh2, zl2;
        split2(z0, &zh2.x, &zl2.x);
        split2(z1, &zh2.y, &zl2.y);
        *reinterpret_cast<__half2*>(&zh[g]) = zh2;
        *reinterpret_cast<__half2*>(&zl[g]) = zl2;
    }
}

// ---------------- launch ----------------
extern "C" void kernel_launch(void* const* d_in, const int* in_sizes, int n_in,
                              void* d_out, int out_size)
{
    const float* x   = (const float*)d_in[0];
    const float* g1a = (const float*)d_in[1];
    const float* g1b = (const float*)d_in[2];
    const float* g2a = (const float*)d_in[3];
    const float* g2b = (const float*)d_in[4];
    const float* wq  = (const float*)d_in[5];
    const float* bq  = (const float*)d_in[6];
    const float* wk  = (const float*)d_in[7];
    const float* bk  = (const float*)d_in[8];
    const float* wv  = (const float*)d_in[9];
    const float* bv  = (const float*)d_in[10];
    const float* wo  = (const float*)d_in[11];
    const float* bo  = (const float*)d_in[12];
    float* out = (float*)d_out;

    __half *xh,*xl,*w1,*w2,*wqp,*wk2,*wvp,*wop,*hh,*yh,*yl,*qh,*ql,*zh,*zl,*oh,*ol;
    float *t;
    cudaGetSymbolAddress((void**)&xh, g_xh);   cudaGetSymbolAddress((void**)&xl, g_xl);
    cudaGetSymbolAddress((void**)&w1, g_w1);   cudaGetSymbolAddress((void**)&w2, g_w2);
    cudaGetSymbolAddress((void**)&wqp, g_wq);  cudaGetSymbolAddress((void**)&wk2, g_wk2);
    cudaGetSymbolAddress((void**)&wvp, g_wv);  cudaGetSymbolAddress((void**)&wop, g_wo);
    cudaGetSymbolAddress((void**)&hh, g_hh);
    cudaGetSymbolAddress((void**)&yh, g_yh);   cudaGetSymbolAddress((void**)&yl, g_yl);
    cudaGetSymbolAddress((void**)&qh, g_qh);   cudaGetSymbolAddress((void**)&ql, g_ql);
    cudaGetSymbolAddress((void**)&zh, g_zh);   cudaGetSymbolAddress((void**)&zl, g_zl);
    cudaGetSymbolAddress((void**)&oh, g_oh);   cudaGetSymbolAddress((void**)&ol, g_ol);
    cudaGetSymbolAddress((void**)&t, g_t);

    const int SM1 = NST * (A_B + B_B);       // 147456 (XA=1)
    const int SM2 = NST * (2 * A_B + B_B);   // 196608 (XA=2)
    cudaFuncSetAttribute((const void*)mma_gemm<1,1>, cudaFuncAttributeMaxDynamicSharedMemorySize, SM1);
    cudaFuncSetAttribute((const void*)mma_gemm<0,1>, cudaFuncAttributeMaxDynamicSharedMemorySize, SM1);
    cudaFuncSetAttribute((const void*)mma_gemm<3,2>, cudaFuncAttributeMaxDynamicSharedMemorySize, SM2);
    cudaFuncSetAttribute((const void*)mma_gemm<4,2>, cudaFuncAttributeMaxDynamicSharedMemorySize, SM2);
    cudaFuncSetAttribute((const void*)mma_gemm<2,2>, cudaFuncAttributeMaxDynamicSharedMemorySize, SM2);
    cudaFuncSetAttribute((const void*)build_w1_tiled, cudaFuncAttributeMaxDynamicSharedMemorySize, W1_SMEM);

    const size_t sBD = (size_t)Bsz * Dm, sBF = (size_t)Bsz * Ff;
    const size_t sDD = (size_t)Dm * Dm, sFD = (size_t)Ff * Dm;

    // 1) conversions / TT materialization
    split_arr<<<(Bsz * Dm) / 256, 256>>>(x, xh, xl, sBD);
    half_arr<<<(Dm * Dm) / 256, 256>>>(wk, wk2, sDD);
    thalf_w<<<(Dm * Dm) / 256, 256>>>(wq, wqp);
    thalf_w<<<(Dm * Dm) / 256, 256>>>(wv, wvp);
    thalf_w<<<(Dm * Dm) / 256, 256>>>(wo, wop);
    build_w1_tiled<<<dim3(64, Ssup), 256, W1_SMEM>>>(g1a, g1b, w1);
    build_w2t<<<(Ssup * Dm * Ff) / 256, 256>>>(g2a, g2b, w2);

    // 2) FFN1 (plain fp16): h[s] = gelu(x @ w1t[s]^T)  -> single fp16
    mma_gemm<1,1><<<dim3(Ff/BN, Bsz/BM, Ssup), 256, SM1>>>(
        xh, nullptr, Dm, 0, w1, Dm, sFD, Dm, Ff, sBF,
        nullptr, hh, nullptr, nullptr, 0);

    // 3) FFN2 (plain fp16): y[s] = h[s] @ w2t[s]^T -> split fp16
    mma_gemm<0,1><<<dim3(Dm/BN, Bsz/BM, Ssup), 256, SM1>>>(
        hh, nullptr, Ff, sBF, w2, Ff, (size_t)Dm*Ff, Ff, Dm, sBD,
        nullptr, yh, yl, nullptr, 0);

    // 4) q = x @ wq + bq -> split fp16  (x2)
    mma_gemm<3,2><<<dim3(Dm/BN, Bsz/BM, 1), 256, SM2>>>(
        xh, xl, Dm, 0, wqp, Dm, 0, Dm, Dm, 0,
        nullptr, qh, ql, bq, 0);

    // 5) t[h] = q[:,h-block] @ wk[:,h-block]^T  (x2), batched over h
    mma_gemm<4,2><<<dim3(Dm/BN, Bsz/BM, Hh), 256, SM2>>>(
        qh, ql, Dm, HD, wk2, Dm, HD, HD, Dm, sBD,
        t, nullptr, nullptr, nullptr, 0);

    // 6) scores + softmax + z
    attn_collapse<<<Bsz, 256>>>(qh, ql, t, yh, yl, bk, zh, zl);

    // 7) o[:,h-block] = z[h] @ wv[:,h-block]^T + bv  (x2)
    mma_gemm<3,2><<<dim3(1, Bsz/BM, Hh), 256, SM2>>>(
        zh, zl, Dm, sBD, wvp, Dm, (size_t)HD*Dm, Dm, Dm, (size_t)HD,
        nullptr, oh, ol, bv, HD);

    // 8) out = o @ wo + bo (fp32)  (x2)
    mma_gemm<2,2><<<dim3(Dm/BN, Bsz/BM, 1), 256, SM2>>>(
        oh, ol, Dm, 0, wop, Dm, 0, Dm, Dm, 0,
        out, nullptr, nullptr, bo, 0);
}

// round 9
// speedup vs baseline: 5.0499x; 1.0353x over previous
#include <cuda_runtime.h>
#include <cuda_fp16.h>
#include <math.h>
#include <stdint.h>

// ---------------- problem constants ----------------
#define Bsz 8192
#define Dm  1024
#define Ff  4096
#define Ssup 4
#define Hh  4
#define HD  256

// ---------------- GEMM tiling ----------------
#define BM 128
#define BK 64                    // fp16 elems per k-tile (128B rows)
#define NST 3
#define A_B   (BM * BK * 2)      // 16384 bytes per A matrix (hi or lo)

// ---------------- scratch (device globals) ----------------
__device__ __half g_xh [(size_t)Bsz*Dm],     g_xl [(size_t)Bsz*Dm];
__device__ __half g_w1 [(size_t)Ssup*Ff*Dm];   // [s][f][d] (transposed)
__device__ __half g_w2 [(size_t)Ssup*Dm*Ff];   // [s][d][f]
__device__ __half g_wq [(size_t)Dm*Dm];        // transposed [n][k]
__device__ __half g_wk2[(size_t)Dm*Dm];        // straight [m][d]
__device__ __half g_wv [(size_t)Dm*Dm];        // transposed
__device__ __half g_wo [(size_t)Dm*Dm];        // transposed
__device__ __half g_hh [(size_t)Ssup*Bsz*Ff];                             // h single fp16
__device__ __half g_yh [(size_t)Ssup*Bsz*Dm],  g_yl [(size_t)Ssup*Bsz*Dm];
__device__ __half g_qh [(size_t)Bsz*Dm],       g_ql [(size_t)Bsz*Dm];
__device__ __half g_zh [(size_t)Hh*Bsz*Dm],    g_zl [(size_t)Hh*Bsz*Dm];  // [h][b][m]
__device__ __half g_oh [(size_t)Bsz*Dm],       g_ol [(size_t)Bsz*Dm];
__device__ float g_t [(size_t)Hh*Bsz*Dm];      // [h][b][m]

// ---------------- asm helpers (generic-target PTX, sm_80+) ----------------
__device__ __forceinline__ uint32_t smem_u32(const void* p) {
    uint32_t a;
    asm("{ .reg .u64 t; cvta.to.shared.u64 t, %1; cvt.u32.u64 %0, t; }" : "=r"(a) : "l"(p));
    return a;
}
__device__ __forceinline__ void cp16(uint32_t dst, const void* src) {
    asm volatile("cp.async.cg.shared.global [%0], [%1], 16;" :: "r"(dst), "l"(src));
}
#define CP_COMMIT() asm volatile("cp.async.commit_group;" ::: "memory")
#define CP_WAIT(n)  asm volatile("cp.async.wait_group %0;" :: "n"(n) : "memory")
#define LDSM4(r, a) asm volatile("ldmatrix.sync.aligned.m8n8.x4.shared.b16 {%0,%1,%2,%3}, [%4];" \
    : "=r"((r)[0]), "=r"((r)[1]), "=r"((r)[2]), "=r"((r)[3]) : "r"(a))
#define MMA16816(ac, a, b0, b1) \
    asm volatile("mma.sync.aligned.m16n8k16.row.col.f32.f16.f16.f32 " \
        "{%0,%1,%2,%3}, {%4,%5,%6,%7}, {%8,%9}, {%0,%1,%2,%3};" \
        : "+f"((ac)[0]), "+f"((ac)[1]), "+f"((ac)[2]), "+f"((ac)[3]) \
        : "r"((a)[0]), "r"((a)[1]), "r"((a)[2]), "r"((a)[3]), "r"(b0), "r"(b1))

__device__ __forceinline__ float gelu_exact(float x) {
    return 0.5f * x * (1.0f + erff(x * 0.70710678118654752440f));
}
__device__ __forceinline__ void split2(float v, __half* h, __half* l) {
    __half hb = __float2half(v);
    *h = hb;
    *l = __float2half(v - __half2float(hb));
}
// 16B-chunk swizzle for 128B rows (8 chunks per row): chunk' = chunk ^ (row & 7)
__device__ __forceinline__ uint32_t swz(int row, int c16) {
    return (uint32_t)(row * 8 + (c16 ^ (row & 7))) * 16u;
}

// ---------------- conversion / build kernels ----------------
__global__ void split_arr(const float* __restrict__ in, __half* __restrict__ hi,
                          __half* __restrict__ lo, size_t n) {
    size_t i = (size_t)blockIdx.x * blockDim.x + threadIdx.x;
    if (i < n) split2(in[i], &hi[i], &lo[i]);
}
__global__ void half_arr(const float* __restrict__ in, __half* __restrict__ o, size_t n) {
    size_t i = (size_t)blockIdx.x * blockDim.x + threadIdx.x;
    if (i < n) o[i] = __float2half(in[i]);
}
__global__ void thalf_w(const float* __restrict__ w, __half* __restrict__ o) {
    size_t e = (size_t)blockIdx.x * blockDim.x + threadIdx.x;
    int n = (int)(e >> 10), k = (int)(e & 1023);
    o[e] = __float2half(w[(size_t)k * Dm + n]);
}

// smem-tiled w1 build: block (o1, s). Stages full g1b[s] (padded) + A row slab.
#define W1_SMEM ((16*32*65 + 512) * 4)
__global__ __launch_bounds__(256)
void build_w1_tiled(const float* __restrict__ g1a, const float* __restrict__ g1b,
                    __half* __restrict__ o)
{
    extern __shared__ float dsm[];
    float* Bs = dsm;                 // [r][i2][o2] stride 65
    float* As = dsm + 16 * 32 * 65;  // [i1][r]
    const int tid = threadIdx.x;
    const int o1 = blockIdx.x, s = blockIdx.y;

    for (int idx = tid; idx < 32768; idx += 256) {
        int r = idx >> 11, i2 = (idx >> 6) & 31, o2 = idx & 63;
        Bs[(r * 32 + i2) * 65 + o2] = g1b[(size_t)s * 32768 + idx];
    }
    for (int idx = tid; idx < 512; idx += 256) {
        int i1 = idx >> 4, r = idx & 15;
        As[idx] = g1a[(((size_t)s * 32 + i1) * 64 + o1) * 16 + r];
    }
    __syncthreads();

    const size_t ob = ((size_t)s * Ff + (size_t)o1 * 64) * Dm;
#pragma unroll 4
    for (int it = 0; it < 256; it++) {
        int idx = tid + (it << 8);
        int o2 = idx >> 10, d = idx & 1023;
        int i1 = d >> 5, i2 = d & 31;
        const float* ap = As + i1 * 16;
        const float* bp = Bs + i2 * 65 + o2;
        float sum = 0.f;
#pragma unroll
        for (int r = 0; r < 16; r++) sum += ap[r] * bp[r * 2080];
        o[ob + (size_t)o2 * Dm + d] = __float2half(sum);
    }
}

__global__ void build_w2t(const float* __restrict__ g2a, const float* __restrict__ g2b,
                          __half* __restrict__ o) {
    size_t e = (size_t)blockIdx.x * blockDim.x + threadIdx.x;
    int s = (int)(e >> 22), d = (int)((e >> 12) & 1023), f = (int)(e & 4095);
    int o1 = f >> 6, o2 = f & 63, i1 = d >> 5, i2 = d & 31;
    const float* a = g2a + (((size_t)s * 64 + o1) * 32 + i1) * 16;
    const float* b = g2b + (size_t)s * 32768 + (size_t)o2 * 32 + i2;
    float sum = 0.f;
#pragma unroll
    for (int r = 0; r < 16; r++) sum += a[r] * b[(size_t)r * 2048];
    o[e] = __float2half(sum);
}

// ---------------- fp16 HMMA GEMM body (templated on BN tile) ----------------
// C = A * B^T. XA=1 plain A, XA=2 compensated A (Ah+Al).
// EPI: 0 split, 1 gelu+single, 2 bias+fp32, 3 bias+split, 4 fp32
template <int EPI, int XA, int BNT>
__device__ __forceinline__
void gemm_body(const __half* __restrict__ Ah, const __half* __restrict__ Al,
               int lda, size_t aBS,
               const __half* __restrict__ Bh, int ldb, size_t bBS,
               int K, int ldc, size_t cBS,
               float* __restrict__ Cf,
               __half* __restrict__ Chi, __half* __restrict__ Clo,
               const float* __restrict__ bias, size_t biasBS)
{
    constexpr uint32_t B_Bt = BNT * BK * 2;
    constexpr uint32_t STG  = XA * A_B + B_Bt;
    constexpr int P = BNT / 64;          // p-loop count (16 cols per p)
    extern __shared__ char smem[];
    const uint32_t sb = smem_u32(smem);
    const int tid = threadIdx.x, wid = tid >> 5, lane = tid & 31;
    const int zz = blockIdx.z;
    const int m0 = blockIdx.y * BM, n0 = blockIdx.x * BNT;

    const __half* pAh = Ah + (size_t)zz * aBS;
    const __half* pAl = (XA == 2) ? Al + (size_t)zz * aBS : nullptr;
    const __half* pBh = Bh + (size_t)zz * bBS;

    const int mwarp = (wid & 1) * 64;          // 2 warps over M
    const int nwarp = (wid >> 1) * (BNT / 4);  // 4 warps over N

    float acc[4][2 * P][4];
#pragma unroll
    for (int i = 0; i < 4; i++)
#pragma unroll
        for (int j = 0; j < 2 * P; j++)
#pragma unroll
            for (int c = 0; c < 4; c++) acc[i][j][c] = 0.f;

    const int nk = K / BK;
    const int fr = tid >> 3, fc = tid & 7;   // 32 rows per pass, 8 chunk-cols

    auto fill = [&](int kt, int st) {
        const int k0 = kt * BK;
        const uint32_t base = sb + st * STG;
#pragma unroll
        for (int i = 0; i < 4; i++) {
            int r = fr + i * 32;
            cp16(base + swz(r, fc), pAh + (size_t)(m0 + r) * lda + k0 + fc * 8);
            if (XA == 2)
                cp16(base + A_B + swz(r, fc), pAl + (size_t)(m0 + r) * lda + k0 + fc * 8);
        }
#pragma unroll
        for (int i = 0; i < BNT / 32; i++) {
            int r = fr + i * 32;
            cp16(base + XA*A_B + swz(r, fc), pBh + (size_t)(n0 + r) * ldb + k0 + fc * 8);
        }
        CP_COMMIT();
    };

    fill(0, 0);
    if (nk > 1) fill(1, 1);

    const int ra = lane & 15, ca = lane >> 4;
    const int gb = lane >> 3, rb = lane & 7;

    for (int kt = 0; kt < nk; kt++) {
        if (kt + 1 >= nk) { CP_WAIT(0); } else { CP_WAIT(1); }
        __syncthreads();
        if (kt + 2 < nk) fill(kt + 2, (kt + 2) % NST);

        const uint32_t base = sb + (kt % NST) * STG;
        const uint32_t sAh = base, sAl = base + A_B;
        const uint32_t sBh = base + XA * A_B;

#pragma unroll
        for (int kk = 0; kk < 4; kk++) {
            uint32_t ah[4][4], al[4][4];
#pragma unroll
            for (int mt = 0; mt < 4; mt++) {
                uint32_t off = swz(mwarp + mt * 16 + ra, kk * 2 + ca);
                LDSM4(ah[mt], sAh + off);
                if (XA == 2) LDSM4(al[mt], sAl + off);
            }
#pragma unroll
            for (int p = 0; p < P; p++) {
                uint32_t bh[4];
                uint32_t off = swz(nwarp + p * 16 + (gb & 1) * 8 + rb, kk * 2 + (gb >> 1));
                LDSM4(bh, sBh + off);
#pragma unroll
                for (int mt = 0; mt < 4; mt++) {
                    MMA16816(acc[mt][2*p],   ah[mt], bh[0], bh[2]);
                    MMA16816(acc[mt][2*p+1], ah[mt], bh[1], bh[3]);
                    if (XA == 2) {
                        MMA16816(acc[mt][2*p],   al[mt], bh[0], bh[2]);
                        MMA16816(acc[mt][2*p+1], al[mt], bh[1], bh[3]);
                    }
                }
            }
        }
    }

    // ---------------- epilogue ----------------
    float* Cfp = Cf ? Cf + (size_t)zz * cBS : nullptr;
    __half* Chp = Chi ? Chi + (size_t)zz * cBS : nullptr;
    __half* Clp = Clo ? Clo + (size_t)zz * cBS : nullptr;
    const float* bp = bias ? bias + (size_t)zz * biasBS : nullptr;
    const int g4 = lane >> 2, q2 = (lane & 3) * 2;

#pragma unroll
    for (int mt = 0; mt < 4; mt++) {
#pragma unroll
        for (int nt = 0; nt < 2 * P; nt++) {
            int r0 = m0 + mwarp + mt * 16 + g4;
            int c  = n0 + nwarp + nt * 8 + q2;
#pragma unroll
            for (int half = 0; half < 2; half++) {
                int rr = r0 + half * 8;
                float v0 = acc[mt][nt][half * 2 + 0];
                float v1 = acc[mt][nt][half * 2 + 1];
                size_t off = (size_t)rr * ldc + c;
                if (EPI == 2) {
                    *reinterpret_cast<float2*>(&Cfp[off]) =
                        make_float2(v0 + bp[c], v1 + bp[c + 1]);
                } else if (EPI == 4) {
                    *reinterpret_cast<float2*>(&Cfp[off]) = make_float2(v0, v1);
                } else if (EPI == 1) {
                    __half2 h2;
                    h2.x = __float2half(gelu_exact(v0));
                    h2.y = __float2half(gelu_exact(v1));
                    *reinterpret_cast<__half2*>(&Chp[off]) = h2;
                } else {
                    if (EPI == 3) { v0 += bp[c]; v1 += bp[c + 1]; }
                    __half2 h2, l2;
                    split2(v0, &h2.x, &l2.x);
                    split2(v1, &h2.y, &l2.y);
                    *reinterpret_cast<__half2*>(&Chp[off]) = h2;
                    *reinterpret_cast<__half2*>(&Clp[off]) = l2;
                }
            }
        }
    }
}

// occupancy-1 shell (BN=256)
template <int EPI, int XA>
__global__ __launch_bounds__(256, 1)
void mma_gemm(const __half* __restrict__ Ah, const __half* __restrict__ Al,
              int lda, size_t aBS,
              const __half* __restrict__ Bh, int ldb, size_t bBS,
              int K, int ldc, size_t cBS,
              float* __restrict__ Cf,
              __half* __restrict__ Chi, __half* __restrict__ Clo,
              const float* __restrict__ bias, size_t biasBS)
{
    gemm_body<EPI, XA, 256>(Ah, Al, lda, aBS, Bh, ldb, bBS, K, ldc, cBS,
                            Cf, Chi, Clo, bias, biasBS);
}

// occupancy-2 shell (BN=128) — used by the big FFN GEMMs
template <int EPI, int XA>
__global__ __launch_bounds__(256, 2)
void mma_gemm2(const __half* __restrict__ Ah, const __half* __restrict__ Al,
               int lda, size_t aBS,
               const __half* __restrict__ Bh, int ldb, size_t bBS,
               int K, int ldc, size_t cBS,
               float* __restrict__ Cf,
               __half* __restrict__ Chi, __half* __restrict__ Clo,
               const float* __restrict__ bias, size_t biasBS)
{
    gemm_body<EPI, XA, 128>(Ah, Al, lda, aBS, Bh, ldb, bBS, K, ldc, cBS,
                            Cf, Chi, Clo, bias, biasBS);
}

// ---------------- attention collapse: scores, softmax, z ----------------
__global__ __launch_bounds__(256)
void attn_collapse(const __half* __restrict__ qh, const __half* __restrict__ ql,
                   const float* __restrict__ t,
                   const __half* __restrict__ yh, const __half* __restrict__ yl,
                   const float* __restrict__ bk,
                   __half* __restrict__ zh, __half* __restrict__ zl)
{
    const int b = blockIdx.x, tid = threadIdx.x;
    const int wid = tid >> 5, lane = tid & 31;
    __shared__ float ys[Ssup][Dm];
    __shared__ float sc[16], qb[Hh], attn[16];

#pragma unroll
    for (int it = 0; it < 8; it++) {
        int idx = tid + it * 256;
        int s = idx >> 9, mm = idx & 511;
        size_t g = ((size_t)s * Bsz + b) * Dm + mm * 2;
        __half2 h2 = *reinterpret_cast<const __half2*>(&yh[g]);
        __half2 l2 = *reinterpret_cast<const __half2*>(&yl[g]);
        ys[s][mm * 2]     = __half2float(h2.x) + __half2float(l2.x);
        ys[s][mm * 2 + 1] = __half2float(h2.y) + __half2float(l2.y);
    }
    if (wid < Hh) {
        float sum = 0.f;
        for (int j = lane; j < HD; j += 32) {
            size_t g = (size_t)b * Dm + wid * HD + j;
            float qv = __half2float(qh[g]) + __half2float(ql[g]);
            sum = fmaf(qv, bk[wid * HD + j], sum);
        }
#pragma unroll
        for (int o = 16; o; o >>= 1) sum += __shfl_xor_sync(0xffffffffu, sum, o);
        if (lane == 0) qb[wid] = sum;
    }
    __syncthreads();

#pragma unroll
    for (int i = 0; i < 2; i++) {
        int p = wid * 2 + i;
        int h = p >> 2, s = p & 3;
        const float* tp = t + ((size_t)h * Bsz + b) * Dm;
        float sum = 0.f;
        for (int m = lane; m < Dm; m += 32) sum = fmaf(ys[s][m], tp[m], sum);
#pragma unroll
        for (int o = 16; o; o >>= 1) sum += __shfl_xor_sync(0xffffffffu, sum, o);
        if (lane == 0) sc[p] = sum;
    }
    __syncthreads();

    if (tid < Hh) {
        int h = tid;
        float s0 = (sc[h*4+0] + qb[h]) * 0.0625f;
        float s1 = (sc[h*4+1] + qb[h]) * 0.0625f;
        float s2 = (sc[h*4+2] + qb[h]) * 0.0625f;
        float s3 = (sc[h*4+3] + qb[h]) * 0.0625f;
        float m = fmaxf(fmaxf(s0, s1), fmaxf(s2, s3));
        float e0 = expf(s0-m), e1 = expf(s1-m), e2 = expf(s2-m), e3 = expf(s3-m);
        float inv = 1.f / (e0 + e1 + e2 + e3);
        attn[h*4+0] = e0*inv; attn[h*4+1] = e1*inv;
        attn[h*4+2] = e2*inv; attn[h*4+3] = e3*inv;
    }
    __syncthreads();

#pragma unroll
    for (int it = 0; it < 8; it++) {
        int idx = tid + it * 256;
        int h = idx >> 9, mm = idx & 511;
        int m = mm * 2;
        float a0 = attn[h*4+0], a1 = attn[h*4+1], a2 = attn[h*4+2], a3 = attn[h*4+3];
        float z0 = a0*ys[0][m]   + a1*ys[1][m]   + a2*ys[2][m]   + a3*ys[3][m];
        float z1 = a0*ys[0][m+1] + a1*ys[1][m+1] + a2*ys[2][m+1] + a3*ys[3][m+1];
        size_t g = ((size_t)h * Bsz + b) * Dm + m;
        __half2 zh2, zl2;
        split2(z0, &zh2.x, &zl2.x);
        split2(z1, &zh2.y, &zl2.y);
        *reinterpret_cast<__half2*>(&zh[g]) = zh2;
        *reinterpret_cast<__half2*>(&zl[g]) = zl2;
    }
}

// ---------------- launch ----------------
extern "C" void kernel_launch(void* const* d_in, const int* in_sizes, int n_in,
                              void* d_out, int out_size)
{
    const float* x   = (const float*)d_in[0];
    const float* g1a = (const float*)d_in[1];
    const float* g1b = (const float*)d_in[2];
    const float* g2a = (const float*)d_in[3];
    const float* g2b = (const float*)d_in[4];
    const float* wq  = (const float*)d_in[5];
    const float* bq  = (const float*)d_in[6];
    const float* wk  = (const float*)d_in[7];
    const float* bk  = (const float*)d_in[8];
    const float* wv  = (const float*)d_in[9];
    const float* bv  = (const float*)d_in[10];
    const float* wo  = (const float*)d_in[11];
    const float* bo  = (const float*)d_in[12];
    float* out = (float*)d_out;

    __half *xh,*xl,*w1,*w2,*wqp,*wk2,*wvp,*wop,*hh,*yh,*yl,*qh,*ql,*zh,*zl,*oh,*ol;
    float *t;
    cudaGetSymbolAddress((void**)&xh, g_xh);   cudaGetSymbolAddress((void**)&xl, g_xl);
    cudaGetSymbolAddress((void**)&w1, g_w1);   cudaGetSymbolAddress((void**)&w2, g_w2);
    cudaGetSymbolAddress((void**)&wqp, g_wq);  cudaGetSymbolAddress((void**)&wk2, g_wk2);
    cudaGetSymbolAddress((void**)&wvp, g_wv);  cudaGetSymbolAddress((void**)&wop, g_wo);
    cudaGetSymbolAddress((void**)&hh, g_hh);
    cudaGetSymbolAddress((void**)&yh, g_yh);   cudaGetSymbolAddress((void**)&yl, g_yl);
    cudaGetSymbolAddress((void**)&qh, g_qh);   cudaGetSymbolAddress((void**)&ql, g_ql);
    cudaGetSymbolAddress((void**)&zh, g_zh);   cudaGetSymbolAddress((void**)&zl, g_zl);
    cudaGetSymbolAddress((void**)&oh, g_oh);   cudaGetSymbolAddress((void**)&ol, g_ol);
    cudaGetSymbolAddress((void**)&t, g_t);

    const int SM1b = NST * (A_B + 128 * BK * 2);     // 98304  (XA=1, BN=128, occ2)
    const int SM2  = NST * (2 * A_B + 256 * BK * 2); // 196608 (XA=2, BN=256)
    cudaFuncSetAttribute((const void*)mma_gemm2<1,1>, cudaFuncAttributeMaxDynamicSharedMemorySize, SM1b);
    cudaFuncSetAttribute((const void*)mma_gemm2<0,1>, cudaFuncAttributeMaxDynamicSharedMemorySize, SM1b);
    cudaFuncSetAttribute((const void*)mma_gemm<3,2>,  cudaFuncAttributeMaxDynamicSharedMemorySize, SM2);
    cudaFuncSetAttribute((const void*)mma_gemm<4,2>,  cudaFuncAttributeMaxDynamicSharedMemorySize, SM2);
    cudaFuncSetAttribute((const void*)mma_gemm<2,2>,  cudaFuncAttributeMaxDynamicSharedMemorySize, SM2);
    cudaFuncSetAttribute((const void*)build_w1_tiled, cudaFuncAttributeMaxDynamicSharedMemorySize, W1_SMEM);

    const size_t sBD = (size_t)Bsz * Dm, sBF = (size_t)Bsz * Ff;
    const size_t sDD = (size_t)Dm * Dm, sFD = (size_t)Ff * Dm;

    // 1) conversions / TT materialization
    split_arr<<<(Bsz * Dm) / 256, 256>>>(x, xh, xl, sBD);
    half_arr<<<(Dm * Dm) / 256, 256>>>(wk, wk2, sDD);
    thalf_w<<<(Dm * Dm) / 256, 256>>>(wq, wqp);
    thalf_w<<<(Dm * Dm) / 256, 256>>>(wv, wvp);
    thalf_w<<<(Dm * Dm) / 256, 256>>>(wo, wop);
    build_w1_tiled<<<dim3(64, Ssup), 256, W1_SMEM>>>(g1a, g1b, w1);
    build_w2t<<<(Ssup * Dm * Ff) / 256, 256>>>(g2a, g2b, w2);

    // 2) FFN1 (plain fp16, occ2): h[s] = gelu(x @ w1t[s]^T)
    mma_gemm2<1,1><<<dim3(Ff/128, Bsz/BM, Ssup), 256, SM1b>>>(
        xh, nullptr, Dm, 0, w1, Dm, sFD, Dm, Ff, sBF,
        nullptr, hh, nullptr, nullptr, 0);

    // 3) FFN2 (plain fp16, occ2): y[s] = h[s] @ w2t[s]^T -> split fp16
    mma_gemm2<0,1><<<dim3(Dm/128, Bsz/BM, Ssup), 256, SM1b>>>(
        hh, nullptr, Ff, sBF, w2, Ff, (size_t)Dm*Ff, Ff, Dm, sBD,
        nullptr, yh, yl, nullptr, 0);

    // 4) q = x @ wq + bq -> split fp16  (x2)
    mma_gemm<3,2><<<dim3(Dm/256, Bsz/BM, 1), 256, SM2>>>(
        xh, xl, Dm, 0, wqp, Dm, 0, Dm, Dm, 0,
        nullptr, qh, ql, bq, 0);

    // 5) t[h] = q[:,h-block] @ wk[:,h-block]^T  (x2), batched over h
    mma_gemm<4,2><<<dim3(Dm/256, Bsz/BM, Hh), 256, SM2>>>(
        qh, ql, Dm, HD, wk2, Dm, HD, HD, Dm, sBD,
        t, nullptr, nullptr, nullptr, 0);

    // 6) scores + softmax + z
    attn_collapse<<<Bsz, 256>>>(qh, ql, t, yh, yl, bk, zh, zl);

    // 7) o[:,h-block] = z[h] @ wv[:,h-block]^T + bv  (x2)
    mma_gemm<3,2><<<dim3(1, Bsz/BM, Hh), 256, SM2>>>(
        zh, zl, Dm, sBD, wvp, Dm, (size_t)HD*Dm, Dm, Dm, (size_t)HD,
        nullptr, oh, ol, bv, HD);

    // 8) out = o @ wo + bo (fp32)  (x2)
    mma_gemm<2,2><<<dim3(Dm/256, Bsz/BM, 1), 256, SM2>>>(
        oh, ol, Dm, 0, wop, Dm, 0, Dm, Dm, 0,
        out, nullptr, nullptr, bo, 0);
}

// round 10
// speedup vs baseline: 6.9566x; 1.3776x over previous
#include <cuda_runtime.h>
#include <cuda_fp16.h>
#include <math.h>
#include <stdint.h>

// ---------------- problem constants ----------------
#define Bsz 8192
#define Dm  1024
#define Ff  4096
#define Ssup 4
#define Hh  4
#define HD  256

// ---------------- GEMM tiling ----------------
#define BM 128
#define BK 64                    // fp16 elems per k-tile (128B rows)
#define NST 3
#define A_B   (BM * BK * 2)      // 16384 bytes per A matrix (hi or lo)

// ---------------- scratch (device globals) ----------------
__device__ __half g_xh [(size_t)Bsz*Dm],     g_xl [(size_t)Bsz*Dm];
__device__ __half g_w1 [(size_t)Ssup*Ff*Dm];   // [s][f][d] (transposed)
__device__ __half g_w2 [(size_t)Ssup*Dm*Ff];   // [s][d][f]
__device__ __half g_wq [(size_t)Dm*Dm];        // transposed [n][k]
__device__ __half g_wk2[(size_t)Dm*Dm];        // straight [m][d]
__device__ __half g_wv [(size_t)Dm*Dm];        // transposed
__device__ __half g_wo [(size_t)Dm*Dm];        // transposed
__device__ __half g_hh [(size_t)Ssup*Bsz*Ff];                             // h single fp16
__device__ __half g_yh [(size_t)Ssup*Bsz*Dm],  g_yl [(size_t)Ssup*Bsz*Dm];
__device__ __half g_qh [(size_t)Bsz*Dm],       g_ql [(size_t)Bsz*Dm];
__device__ __half g_zh [(size_t)Hh*Bsz*Dm],    g_zl [(size_t)Hh*Bsz*Dm];  // [h][b][m]
__device__ __half g_oh [(size_t)Bsz*Dm],       g_ol [(size_t)Bsz*Dm];
__device__ float g_t [(size_t)Hh*Bsz*Dm];      // [h][b][m]

// ---------------- asm helpers (generic-target PTX, sm_80+) ----------------
__device__ __forceinline__ uint32_t smem_u32(const void* p) {
    uint32_t a;
    asm("{ .reg .u64 t; cvta.to.shared.u64 t, %1; cvt.u32.u64 %0, t; }" : "=r"(a) : "l"(p));
    return a;
}
__device__ __forceinline__ void cp16(uint32_t dst, const void* src) {
    asm volatile("cp.async.cg.shared.global [%0], [%1], 16;" :: "r"(dst), "l"(src));
}
#define CP_COMMIT() asm volatile("cp.async.commit_group;" ::: "memory")
#define CP_WAIT(n)  asm volatile("cp.async.wait_group %0;" :: "n"(n) : "memory")
#define LDSM4(r, a) asm volatile("ldmatrix.sync.aligned.m8n8.x4.shared.b16 {%0,%1,%2,%3}, [%4];" \
    : "=r"((r)[0]), "=r"((r)[1]), "=r"((r)[2]), "=r"((r)[3]) : "r"(a))
#define MMA16816(ac, a, b0, b1) \
    asm volatile("mma.sync.aligned.m16n8k16.row.col.f32.f16.f16.f32 " \
        "{%0,%1,%2,%3}, {%4,%5,%6,%7}, {%8,%9}, {%0,%1,%2,%3};" \
        : "+f"((ac)[0]), "+f"((ac)[1]), "+f"((ac)[2]), "+f"((ac)[3]) \
        : "r"((a)[0]), "r"((a)[1]), "r"((a)[2]), "r"((a)[3]), "r"(b0), "r"(b1))

__device__ __forceinline__ float gelu_exact(float x) {
    return 0.5f * x * (1.0f + erff(x * 0.70710678118654752440f));
}
__device__ __forceinline__ void split2(float v, __half* h, __half* l) {
    __half hb = __float2half(v);
    *h = hb;
    *l = __float2half(v - __half2float(hb));
}
// 16B-chunk swizzle for 128B rows (8 chunks per row): chunk' = chunk ^ (row & 7)
__device__ __forceinline__ uint32_t swz(int row, int c16) {
    return (uint32_t)(row * 8 + (c16 ^ (row & 7))) * 16u;
}

// ---------------- conversion / build kernels ----------------
__global__ void split_arr(const float* __restrict__ in, __half* __restrict__ hi,
                          __half* __restrict__ lo, size_t n) {
    size_t i = (size_t)blockIdx.x * blockDim.x + threadIdx.x;
    if (i < n) split2(in[i], &hi[i], &lo[i]);
}
__global__ void half_arr(const float* __restrict__ in, __half* __restrict__ o, size_t n) {
    size_t i = (size_t)blockIdx.x * blockDim.x + threadIdx.x;
    if (i < n) o[i] = __float2half(in[i]);
}

// tiled fused transpose: wq/wv/wo [k][n] -> [n][k] fp16, one kernel
__global__ __launch_bounds__(256)
void ttile_w(const float* __restrict__ wq, const float* __restrict__ wv,
             const float* __restrict__ wo,
             __half* __restrict__ oq, __half* __restrict__ ov, __half* __restrict__ oo)
{
    __shared__ float tile[32][33];
    const float* w = blockIdx.z == 0 ? wq : (blockIdx.z == 1 ? wv : wo);
    __half* o      = blockIdx.z == 0 ? oq : (blockIdx.z == 1 ? ov : oo);
    const int bx = blockIdx.x * 32, by = blockIdx.y * 32;
    const int tx = threadIdx.x & 31, ty = threadIdx.x >> 5;  // 32x8
#pragma unroll
    for (int j = 0; j < 4; j++)
        tile[ty + j * 8][tx] = w[(size_t)(by + ty + j * 8) * Dm + bx + tx];
    __syncthreads();
#pragma unroll
    for (int j = 0; j < 4; j++)
        o[(size_t)(bx + ty + j * 8) * Dm + by + tx] = __float2half(tile[tx][ty + j * 8]);
}

// smem-tiled w1 build: block (o1, s). Stages full g1b[s] (padded) + A row slab.
#define W1_SMEM ((16*32*65 + 512) * 4)
__global__ __launch_bounds__(256)
void build_w1_tiled(const float* __restrict__ g1a, const float* __restrict__ g1b,
                    __half* __restrict__ o)
{
    extern __shared__ float dsm[];
    float* Bs = dsm;                 // [r][i2][o2] stride 65
    float* As = dsm + 16 * 32 * 65;  // [i1][r]
    const int tid = threadIdx.x;
    const int o1 = blockIdx.x, s = blockIdx.y;

    for (int idx = tid; idx < 32768; idx += 256) {
        int r = idx >> 11, i2 = (idx >> 6) & 31, o2 = idx & 63;
        Bs[(r * 32 + i2) * 65 + o2] = g1b[(size_t)s * 32768 + idx];
    }
    for (int idx = tid; idx < 512; idx += 256) {
        int i1 = idx >> 4, r = idx & 15;
        As[idx] = g1a[(((size_t)s * 32 + i1) * 64 + o1) * 16 + r];
    }
    __syncthreads();

    const size_t ob = ((size_t)s * Ff + (size_t)o1 * 64) * Dm;
#pragma unroll 4
    for (int it = 0; it < 256; it++) {
        int idx = tid + (it << 8);
        int o2 = idx >> 10, d = idx & 1023;
        int i1 = d >> 5, i2 = d & 31;
        const float* ap = As + i1 * 16;
        const float* bp = Bs + i2 * 65 + o2;
        float sum = 0.f;
#pragma unroll
        for (int r = 0; r < 16; r++) sum += ap[r] * bp[r * 2080];
        o[ob + (size_t)o2 * Dm + d] = __float2half(sum);
    }
}

// smem-tiled w2 build: block (o1, s). Same accumulation order as before (bit-exact).
// w2t[s][d][o1*64+o2] = sum_r g2a[s,o1,i1,r] * g2b[s,r,o2,i2],  d = i1*32+i2
#define W2_SMEM ((16*64*33 + 512) * 4)
__global__ __launch_bounds__(256)
void build_w2_tiled(const float* __restrict__ g2a, const float* __restrict__ g2b,
                    __half* __restrict__ o)
{
    extern __shared__ float dsm[];
    float* Bs = dsm;                 // [(r*64+o2)*33 + i2]
    float* As = dsm + 16 * 64 * 33;  // [i1][r]
    const int tid = threadIdx.x;
    const int o1 = blockIdx.x, s = blockIdx.y;

    for (int idx = tid; idx < 32768; idx += 256) {
        int r = idx >> 11, o2 = (idx >> 5) & 63, i2 = idx & 31;
        Bs[(r * 64 + o2) * 33 + i2] = g2b[(size_t)s * 32768 + idx];
    }
    for (int idx = tid; idx < 512; idx += 256) {
        int i1 = idx >> 4, r = idx & 15;
        As[idx] = g2a[(((size_t)s * 64 + o1) * 32 + i1) * 16 + r];
    }
    __syncthreads();

    const size_t ob = (size_t)s * Dm * Ff + (size_t)o1 * 64;
#pragma unroll 4
    for (int it = 0; it < 256; it++) {
        int idx = tid + (it << 8);
        int d = idx >> 6, o2 = idx & 63;
        int i1 = d >> 5, i2 = d & 31;
        const float* ap = As + i1 * 16;
        const float* bp = Bs + o2 * 33 + i2;
        float sum = 0.f;
#pragma unroll
        for (int r = 0; r < 16; r++) sum += ap[r] * bp[r * 2112];   // 64*33
        o[ob + (size_t)d * Ff + o2] = __float2half(sum);
    }
}

// ---------------- fp16 HMMA GEMM body (templated on BN tile) ----------------
// C = A * B^T. XA=1 plain A, XA=2 compensated A (Ah+Al).
// EPI: 0 split, 1 gelu+single, 2 bias+fp32, 3 bias+split, 4 fp32
template <int EPI, int XA, int BNT>
__device__ __forceinline__
void gemm_body(const __half* __restrict__ Ah, const __half* __restrict__ Al,
               int lda, size_t aBS,
               const __half* __restrict__ Bh, int ldb, size_t bBS,
               int K, int ldc, size_t cBS,
               float* __restrict__ Cf,
               __half* __restrict__ Chi, __half* __restrict__ Clo,
               const float* __restrict__ bias, size_t biasBS)
{
    constexpr uint32_t B_Bt = BNT * BK * 2;
    constexpr uint32_t STG  = XA * A_B + B_Bt;
    constexpr int P = BNT / 64;          // p-loop count (16 cols per p)
    extern __shared__ char smem[];
    const uint32_t sb = smem_u32(smem);
    const int tid = threadIdx.x, wid = tid >> 5, lane = tid & 31;
    const int zz = blockIdx.z;
    const int m0 = blockIdx.y * BM, n0 = blockIdx.x * BNT;

    const __half* pAh = Ah + (size_t)zz * aBS;
    const __half* pAl = (XA == 2) ? Al + (size_t)zz * aBS : nullptr;
    const __half* pBh = Bh + (size_t)zz * bBS;

    const int mwarp = (wid & 1) * 64;          // 2 warps over M
    const int nwarp = (wid >> 1) * (BNT / 4);  // 4 warps over N

    float acc[4][2 * P][4];
#pragma unroll
    for (int i = 0; i < 4; i++)
#pragma unroll
        for (int j = 0; j < 2 * P; j++)
#pragma unroll
            for (int c = 0; c < 4; c++) acc[i][j][c] = 0.f;

    const int nk = K / BK;
    const int fr = tid >> 3, fc = tid & 7;   // 32 rows per pass, 8 chunk-cols

    auto fill = [&](int kt, int st) {
        const int k0 = kt * BK;
        const uint32_t base = sb + st * STG;
#pragma unroll
        for (int i = 0; i < 4; i++) {
            int r = fr + i * 32;
            cp16(base + swz(r, fc), pAh + (size_t)(m0 + r) * lda + k0 + fc * 8);
            if (XA == 2)
                cp16(base + A_B + swz(r, fc), pAl + (size_t)(m0 + r) * lda + k0 + fc * 8);
        }
#pragma unroll
        for (int i = 0; i < BNT / 32; i++) {
            int r = fr + i * 32;
            cp16(base + XA*A_B + swz(r, fc), pBh + (size_t)(n0 + r) * ldb + k0 + fc * 8);
        }
        CP_COMMIT();
    };

    fill(0, 0);
    if (nk > 1) fill(1, 1);

    const int ra = lane & 15, ca = lane >> 4;
    const int gb = lane >> 3, rb = lane & 7;

    for (int kt = 0; kt < nk; kt++) {
        if (kt + 1 >= nk) { CP_WAIT(0); } else { CP_WAIT(1); }
        __syncthreads();
        if (kt + 2 < nk) fill(kt + 2, (kt + 2) % NST);

        const uint32_t base = sb + (kt % NST) * STG;
        const uint32_t sAh = base, sAl = base + A_B;
        const uint32_t sBh = base + XA * A_B;

#pragma unroll
        for (int kk = 0; kk < 4; kk++) {
            uint32_t ah[4][4], al[4][4];
#pragma unroll
            for (int mt = 0; mt < 4; mt++) {
                uint32_t off = swz(mwarp + mt * 16 + ra, kk * 2 + ca);
                LDSM4(ah[mt], sAh + off);
                if (XA == 2) LDSM4(al[mt], sAl + off);
            }
#pragma unroll
            for (int p = 0; p < P; p++) {
                uint32_t bh[4];
                uint32_t off = swz(nwarp + p * 16 + (gb & 1) * 8 + rb, kk * 2 + (gb >> 1));
                LDSM4(bh, sBh + off);
#pragma unroll
                for (int mt = 0; mt < 4; mt++) {
                    MMA16816(acc[mt][2*p],   ah[mt], bh[0], bh[2]);
                    MMA16816(acc[mt][2*p+1], ah[mt], bh[1], bh[3]);
                    if (XA == 2) {
                        MMA16816(acc[mt][2*p],   al[mt], bh[0], bh[2]);
                        MMA16816(acc[mt][2*p+1], al[mt], bh[1], bh[3]);
                    }
                }
            }
        }
    }

    // ---------------- epilogue ----------------
    float* Cfp = Cf ? Cf + (size_t)zz * cBS : nullptr;
    __half* Chp = Chi ? Chi + (size_t)zz * cBS : nullptr;
    __half* Clp = Clo ? Clo + (size_t)zz * cBS : nullptr;
    const float* bp = bias ? bias + (size_t)zz * biasBS : nullptr;
    const int g4 = lane >> 2, q2 = (lane & 3) * 2;

#pragma unroll
    for (int mt = 0; mt < 4; mt++) {
#pragma unroll
        for (int nt = 0; nt < 2 * P; nt++) {
            int r0 = m0 + mwarp + mt * 16 + g4;
            int c  = n0 + nwarp + nt * 8 + q2;
#pragma unroll
            for (int half = 0; half < 2; half++) {
                int rr = r0 + half * 8;
                float v0 = acc[mt][nt][half * 2 + 0];
                float v1 = acc[mt][nt][half * 2 + 1];
                size_t off = (size_t)rr * ldc + c;
                if (EPI == 2) {
                    *reinterpret_cast<float2*>(&Cfp[off]) =
                        make_float2(v0 + bp[c], v1 + bp[c + 1]);
                } else if (EPI == 4) {
                    *reinterpret_cast<float2*>(&Cfp[off]) = make_float2(v0, v1);
                } else if (EPI == 1) {
                    __half2 h2;
                    h2.x = __float2half(gelu_exact(v0));
                    h2.y = __float2half(gelu_exact(v1));
                    *reinterpret_cast<__half2*>(&Chp[off]) = h2;
                } else {
                    if (EPI == 3) { v0 += bp[c]; v1 += bp[c + 1]; }
                    __half2 h2, l2;
                    split2(v0, &h2.x, &l2.x);
                    split2(v1, &h2.y, &l2.y);
                    *reinterpret_cast<__half2*>(&Chp[off]) = h2;
                    *reinterpret_cast<__half2*>(&Clp[off]) = l2;
                }
            }
        }
    }
}

// occupancy-1 shell (BN=256)
template <int EPI, int XA>
__global__ __launch_bounds__(256, 1)
void mma_gemm(const __half* __restrict__ Ah, const __half* __restrict__ Al,
              int lda, size_t aBS,
              const __half* __restrict__ Bh, int ldb, size_t bBS,
              int K, int ldc, size_t cBS,
              float* __restrict__ Cf,
              __half* __restrict__ Chi, __half* __restrict__ Clo,
              const float* __restrict__ bias, size_t biasBS)
{
    gemm_body<EPI, XA, 256>(Ah, Al, lda, aBS, Bh, ldb, bBS, K, ldc, cBS,
                            Cf, Chi, Clo, bias, biasBS);
}

// occupancy-2 shell (BN=128) — used by the big FFN GEMMs
template <int EPI, int XA>
__global__ __launch_bounds__(256, 2)
void mma_gemm2(const __half* __restrict__ Ah, const __half* __restrict__ Al,
               int lda, size_t aBS,
               const __half* __restrict__ Bh, int ldb, size_t bBS,
               int K, int ldc, size_t cBS,
               float* __restrict__ Cf,
               __half* __restrict__ Chi, __half* __restrict__ Clo,
               const float* __restrict__ bias, size_t biasBS)
{
    gemm_body<EPI, XA, 128>(Ah, Al, lda, aBS, Bh, ldb, bBS, K, ldc, cBS,
                            Cf, Chi, Clo, bias, biasBS);
}

// ---------------- attention collapse: scores, softmax, z ----------------
__global__ __launch_bounds__(256)
void attn_collapse(const __half* __restrict__ qh, const __half* __restrict__ ql,
                   const float* __restrict__ t,
                   const __half* __restrict__ yh, const __half* __restrict__ yl,
                   const float* __restrict__ bk,
                   __half* __restrict__ zh, __half* __restrict__ zl)
{
    const int b = blockIdx.x, tid = threadIdx.x;
    const int wid = tid >> 5, lane = tid & 31;
    __shared__ float ys[Ssup][Dm];
    __shared__ float sc[16], qb[Hh], attn[16];

#pragma unroll
    for (int it = 0; it < 8; it++) {
        int idx = tid + it * 256;
        int s = idx >> 9, mm = idx & 511;
        size_t g = ((size_t)s * Bsz + b) * Dm + mm * 2;
        __half2 h2 = *reinterpret_cast<const __half2*>(&yh[g]);
        __half2 l2 = *reinterpret_cast<const __half2*>(&yl[g]);
        ys[s][mm * 2]     = __half2float(h2.x) + __half2float(l2.x);
        ys[s][mm * 2 + 1] = __half2float(h2.y) + __half2float(l2.y);
    }
    if (wid < Hh) {
        float sum = 0.f;
        for (int j = lane; j < HD; j += 32) {
            size_t g = (size_t)b * Dm + wid * HD + j;
            float qv = __half2float(qh[g]) + __half2float(ql[g]);
            sum = fmaf(qv, bk[wid * HD + j], sum);
        }
#pragma unroll
        for (int o = 16; o; o >>= 1) sum += __shfl_xor_sync(0xffffffffu, sum, o);
        if (lane == 0) qb[wid] = sum;
    }
    __syncthreads();

#pragma unroll
    for (int i = 0; i < 2; i++) {
        int p = wid * 2 + i;
        int h = p >> 2, s = p & 3;
        const float* tp = t + ((size_t)h * Bsz + b) * Dm;
        float sum = 0.f;
        for (int m = lane; m < Dm; m += 32) sum = fmaf(ys[s][m], tp[m], sum);
#pragma unroll
        for (int o = 16; o; o >>= 1) sum += __shfl_xor_sync(0xffffffffu, sum, o);
        if (lane == 0) sc[p] = sum;
    }
    __syncthreads();

    if (tid < Hh) {
        int h = tid;
        float s0 = (sc[h*4+0] + qb[h]) * 0.0625f;
        float s1 = (sc[h*4+1] + qb[h]) * 0.0625f;
        float s2 = (sc[h*4+2] + qb[h]) * 0.0625f;
        float s3 = (sc[h*4+3] + qb[h]) * 0.0625f;
        float m = fmaxf(fmaxf(s0, s1), fmaxf(s2, s3));
        float e0 = expf(s0-m), e1 = expf(s1-m), e2 = expf(s2-m), e3 = expf(s3-m);
        float inv = 1.f / (e0 + e1 + e2 + e3);
        attn[h*4+0] = e0*inv; attn[h*4+1] = e1*inv;
        attn[h*4+2] = e2*inv; attn[h*4+3] = e3*inv;
    }
    __syncthreads();

#pragma unroll
    for (int it = 0; it < 8; it++) {
        int idx = tid + it * 256;
        int h = idx >> 9, mm = idx & 511;
        int m = mm * 2;
        float a0 = attn[h*4+0], a1 = attn[h*4+1], a2 = attn[h*4+2], a3 = attn[h*4+3];
        float z0 = a0*ys[0][m]   + a1*ys[1][m]   + a2*ys[2][m]   + a3*ys[3][m];
        float z1 = a0*ys[0][m+1] + a1*ys[1][m+1] + a2*ys[2][m+1] + a3*ys[3][m+1];
        size_t g = ((size_t)h * Bsz + b) * Dm + m;
        __half2 zh2, zl2;
        split2(z0, &zh2.x, &zl2.x);
        split2(z1, &zh2.y, &zl2.y);
        *reinterpret_cast<__half2*>(&zh[g]) = zh2;
        *reinterpret_cast<__half2*>(&zl[g]) = zl2;
    }
}

// ---------------- launch ----------------
extern "C" void kernel_launch(void* const* d_in, const int* in_sizes, int n_in,
                              void* d_out, int out_size)
{
    const float* x   = (const float*)d_in[0];
    const float* g1a = (const float*)d_in[1];
    const float* g1b = (const float*)d_in[2];
    const float* g2a = (const float*)d_in[3];
    const float* g2b = (const float*)d_in[4];
    const float* wq  = (const float*)d_in[5];
    const float* bq  = (const float*)d_in[6];
    const float* wk  = (const float*)d_in[7];
    const float* bk  = (const float*)d_in[8];
    const float* wv  = (const float*)d_in[9];
    const float* bv  = (const float*)d_in[10];
    const float* wo  = (const float*)d_in[11];
    const float* bo  = (const float*)d_in[12];
    float* out = (float*)d_out;

    __half *xh,*xl,*w1,*w2,*wqp,*wk2,*wvp,*wop,*hh,*yh,*yl,*qh,*ql,*zh,*zl,*oh,*ol;
    float *t;
    cudaGetSymbolAddress((void**)&xh, g_xh);   cudaGetSymbolAddress((void**)&xl, g_xl);
    cudaGetSymbolAddress((void**)&w1, g_w1);   cudaGetSymbolAddress((void**)&w2, g_w2);
    cudaGetSymbolAddress((void**)&wqp, g_wq);  cudaGetSymbolAddress((void**)&wk2, g_wk2);
    cudaGetSymbolAddress((void**)&wvp, g_wv);  cudaGetSymbolAddress((void**)&wop, g_wo);
    cudaGetSymbolAddress((void**)&hh, g_hh);
    cudaGetSymbolAddress((void**)&yh, g_yh);   cudaGetSymbolAddress((void**)&yl, g_yl);
    cudaGetSymbolAddress((void**)&qh, g_qh);   cudaGetSymbolAddress((void**)&ql, g_ql);
    cudaGetSymbolAddress((void**)&zh, g_zh);   cudaGetSymbolAddress((void**)&zl, g_zl);
    cudaGetSymbolAddress((void**)&oh, g_oh);   cudaGetSymbolAddress((void**)&ol, g_ol);
    cudaGetSymbolAddress((void**)&t, g_t);

    const int SM1b = NST * (A_B + 128 * BK * 2);     // 98304  (XA=1, BN=128, occ2)
    const int SM2  = NST * (2 * A_B + 256 * BK * 2); // 196608 (XA=2, BN=256)
    cudaFuncSetAttribute((const void*)mma_gemm2<1,1>, cudaFuncAttributeMaxDynamicSharedMemorySize, SM1b);
    cudaFuncSetAttribute((const void*)mma_gemm2<0,1>, cudaFuncAttributeMaxDynamicSharedMemorySize, SM1b);
    cudaFuncSetAttribute((const void*)mma_gemm<3,2>,  cudaFuncAttributeMaxDynamicSharedMemorySize, SM2);
    cudaFuncSetAttribute((const void*)mma_gemm<4,2>,  cudaFuncAttributeMaxDynamicSharedMemorySize, SM2);
    cudaFuncSetAttribute((const void*)mma_gemm<2,2>,  cudaFuncAttributeMaxDynamicSharedMemorySize, SM2);
    cudaFuncSetAttribute((const void*)build_w1_tiled, cudaFuncAttributeMaxDynamicSharedMemorySize, W1_SMEM);
    cudaFuncSetAttribute((const void*)build_w2_tiled, cudaFuncAttributeMaxDynamicSharedMemorySize, W2_SMEM);

    const size_t sBD = (size_t)Bsz * Dm, sBF = (size_t)Bsz * Ff;
    const size_t sDD = (size_t)Dm * Dm, sFD = (size_t)Ff * Dm;

    // side stream for the q->t chain (independent of FFN). Fallback: stream 0.
    cudaStream_t s1 = 0;
    cudaEvent_t evF = 0, evJ = 0;
    bool forked = (cudaStreamCreateWithFlags(&s1, cudaStreamNonBlocking) == cudaSuccess);
    if (forked && cudaEventCreateWithFlags(&evF, cudaEventDisableTiming) != cudaSuccess) {
        cudaStreamDestroy(s1); s1 = 0; forked = false;
    }
    if (forked && cudaEventCreateWithFlags(&evJ, cudaEventDisableTiming) != cudaSuccess) {
        cudaEventDestroy(evF); cudaStreamDestroy(s1); s1 = 0; forked = false;
    }

    // 1) conversions / TT materialization (main stream)
    split_arr<<<(Bsz * Dm) / 256, 256>>>(x, xh, xl, sBD);
    half_arr<<<(Dm * Dm) / 256, 256>>>(wk, wk2, sDD);
    ttile_w<<<dim3(32, 32, 3), 256>>>(wq, wv, wo, wqp, wvp, wop);
    build_w1_tiled<<<dim3(64, Ssup), 256, W1_SMEM>>>(g1a, g1b, w1);
    build_w2_tiled<<<dim3(64, Ssup), 256, W2_SMEM>>>(g2a, g2b, w2);

    // fork: q and t depend only on x/wq/wk — run them beside the FFN chain
    if (forked) { cudaEventRecord(evF, 0); cudaStreamWaitEvent(s1, evF, 0); }

    // side: q = x @ wq + bq -> split fp16 (x2);  t[h] = q[:,hb] @ wk[:,hb]^T
    mma_gemm<3,2><<<dim3(Dm/256, Bsz/BM, 1), 256, SM2, s1>>>(
        xh, xl, Dm, 0, wqp, Dm, 0, Dm, Dm, 0,
        nullptr, qh, ql, bq, 0);
    mma_gemm<4,2><<<dim3(Dm/256, Bsz/BM, Hh), 256, SM2, s1>>>(
        qh, ql, Dm, HD, wk2, Dm, HD, HD, Dm, sBD,
        t, nullptr, nullptr, nullptr, 0);
    if (forked) cudaEventRecord(evJ, s1);

    // main: FFN1 (plain fp16, occ2): h[s] = gelu(x @ w1t[s]^T)
    mma_gemm2<1,1><<<dim3(Ff/128, Bsz/BM, Ssup), 256, SM1b>>>(
        xh, nullptr, Dm, 0, w1, Dm, sFD, Dm, Ff, sBF,
        nullptr, hh, nullptr, nullptr, 0);
    // main: FFN2 (plain fp16, occ2): y[s] = h[s] @ w2t[s]^T -> split fp16
    mma_gemm2<0,1><<<dim3(Dm/128, Bsz/BM, Ssup), 256, SM1b>>>(
        hh, nullptr, Ff, sBF, w2, Ff, (size_t)Dm*Ff, Ff, Dm, sBD,
        nullptr, yh, yl, nullptr, 0);

    // join: attn needs y (main) + t (side)
    if (forked) cudaStreamWaitEvent(0, evJ, 0);

    // scores + softmax + z
    attn_collapse<<<Bsz, 256>>>(qh, ql, t, yh, yl, bk, zh, zl);

    // o[:,h-block] = z[h] @ wv[:,h-block]^T + bv  (x2)
    mma_gemm<3,2><<<dim3(1, Bsz/BM, Hh), 256, SM2>>>(
        zh, zl, Dm, sBD, wvp, Dm, (size_t)HD*Dm, Dm, Dm, (size_t)HD,
        nullptr, oh, ol, bv, HD);

    // out = o @ wo + bo (fp32)  (x2)
    mma_gemm<2,2><<<dim3(Dm/256, Bsz/BM, 1), 256, SM2>>>(
        oh, ol, Dm, 0, wop, Dm, 0, Dm, Dm, 0,
        out, nullptr, nullptr, bo, 0);

    if (forked) {
        cudaEventDestroy(evF);
        cudaEventDestroy(evJ);
        cudaStreamDestroy(s1);
    }
}

// round 12
// speedup vs baseline: 7.3062x; 1.0502x over previous
#include <cuda_runtime.h>
#include <cuda_fp16.h>
#include <math.h>
#include <stdint.h>

// ---------------- problem constants ----------------
#define Bsz 8192
#define Dm  1024
#define Ff  4096
#define Ssup 4
#define Hh  4
#define HD  256

// ---------------- GEMM tiling ----------------
#define BM 128
#define BK 64                    // fp16 elems per k-tile (128B rows)
#define NST 3
#define A_B   (BM * BK * 2)      // 16384 bytes per A matrix (hi or lo)

// ---------------- scratch (device globals) ----------------
__device__ __half g_xh [(size_t)Bsz*Dm],     g_xl [(size_t)Bsz*Dm];
__device__ __half g_w1 [(size_t)Ssup*Ff*Dm];   // [s][f][d] (transposed)
__device__ __half g_w2 [(size_t)Ssup*Dm*Ff];   // [s][d][f]
__device__ __half g_wq [(size_t)Dm*Dm];        // transposed [n][k]
__device__ __half g_wk2[(size_t)Dm*Dm];        // straight [m][d]
__device__ __half g_wv [(size_t)Dm*Dm];        // transposed
__device__ __half g_wo [(size_t)Dm*Dm];        // transposed
__device__ __half g_hh [(size_t)Ssup*Bsz*Ff];                             // h single fp16
__device__ __half g_yh [(size_t)Ssup*Bsz*Dm],  g_yl [(size_t)Ssup*Bsz*Dm];
__device__ __half g_qh [(size_t)Bsz*Dm],       g_ql [(size_t)Bsz*Dm];
__device__ __half g_zh [(size_t)Hh*Bsz*Dm],    g_zl [(size_t)Hh*Bsz*Dm];  // [h][b][m]
__device__ __half g_oh [(size_t)Bsz*Dm],       g_ol [(size_t)Bsz*Dm];
__device__ float g_t [(size_t)Hh*Bsz*Dm];      // [h][b][m]

// ---------------- asm helpers (generic-target PTX, sm_80+) ----------------
__device__ __forceinline__ uint32_t smem_u32(const void* p) {
    uint32_t a;
    asm("{ .reg .u64 t; cvta.to.shared.u64 t, %1; cvt.u32.u64 %0, t; }" : "=r"(a) : "l"(p));
    return a;
}
__device__ __forceinline__ void cp16(uint32_t dst, const void* src) {
    asm volatile("cp.async.cg.shared.global [%0], [%1], 16;" :: "r"(dst), "l"(src));
}
#define CP_COMMIT() asm volatile("cp.async.commit_group;" ::: "memory")
#define CP_WAIT(n)  asm volatile("cp.async.wait_group %0;" :: "n"(n) : "memory")
#define LDSM4(r, a) asm volatile("ldmatrix.sync.aligned.m8n8.x4.shared.b16 {%0,%1,%2,%3}, [%4];" \
    : "=r"((r)[0]), "=r"((r)[1]), "=r"((r)[2]), "=r"((r)[3]) : "r"(a))
#define MMA16816(ac, a, b0, b1) \
    asm volatile("mma.sync.aligned.m16n8k16.row.col.f32.f16.f16.f32 " \
        "{%0,%1,%2,%3}, {%4,%5,%6,%7}, {%8,%9}, {%0,%1,%2,%3};" \
        : "+f"((ac)[0]), "+f"((ac)[1]), "+f"((ac)[2]), "+f"((ac)[3]) \
        : "r"((a)[0]), "r"((a)[1]), "r"((a)[2]), "r"((a)[3]), "r"(b0), "r"(b1))

__device__ __forceinline__ float gelu_exact(float x) {
    return 0.5f * x * (1.0f + erff(x * 0.70710678118654752440f));
}
__device__ __forceinline__ void split2(float v, __half* h, __half* l) {
    __half hb = __float2half(v);
    *h = hb;
    *l = __float2half(v - __half2float(hb));
}
// 16B-chunk swizzle for 128B rows (8 chunks per row): chunk' = chunk ^ (row & 7)
__device__ __forceinline__ uint32_t swz(int row, int c16) {
    return (uint32_t)(row * 8 + (c16 ^ (row & 7))) * 16u;
}

// ---------------- conversion / build kernels ----------------
__global__ void split_arr(const float* __restrict__ in, __half* __restrict__ hi,
                          __half* __restrict__ lo, size_t n) {
    size_t i = (size_t)blockIdx.x * blockDim.x + threadIdx.x;
    if (i < n) split2(in[i], &hi[i], &lo[i]);
}
__global__ void half_arr(const float* __restrict__ in, __half* __restrict__ o, size_t n) {
    size_t i = (size_t)blockIdx.x * blockDim.x + threadIdx.x;
    if (i < n) o[i] = __float2half(in[i]);
}

// tiled fused transpose: wq/wv/wo [k][n] -> [n][k] fp16, one kernel
__global__ __launch_bounds__(256)
void ttile_w(const float* __restrict__ wq, const float* __restrict__ wv,
             const float* __restrict__ wo,
             __half* __restrict__ oq, __half* __restrict__ ov, __half* __restrict__ oo)
{
    __shared__ float tile[32][33];
    const float* w = blockIdx.z == 0 ? wq : (blockIdx.z == 1 ? wv : wo);
    __half* o      = blockIdx.z == 0 ? oq : (blockIdx.z == 1 ? ov : oo);
    const int bx = blockIdx.x * 32, by = blockIdx.y * 32;
    const int tx = threadIdx.x & 31, ty = threadIdx.x >> 5;  // 32x8
#pragma unroll
    for (int j = 0; j < 4; j++)
        tile[ty + j * 8][tx] = w[(size_t)(by + ty + j * 8) * Dm + bx + tx];
    __syncthreads();
#pragma unroll
    for (int j = 0; j < 4; j++)
        o[(size_t)(bx + ty + j * 8) * Dm + by + tx] = __float2half(tile[tx][ty + j * 8]);
}

// smem-tiled w1 build, 4x finer: block (o1, o2-quad q, s). Stages 16-o2 slice of g1b[s].
// w1t[s][o1*64+q*16+o2l][d] = sum_r g1a[s,i1,o1,r] * g1b[s,r,i2,q*16+o2l]
#define W1_SMEM ((16*32*17 + 512) * 4)
__global__ __launch_bounds__(256)
void build_w1_tiled(const float* __restrict__ g1a, const float* __restrict__ g1b,
                    __half* __restrict__ o)
{
    extern __shared__ float dsm[];
    float* Bs = dsm;                 // [(r*32+i2)*17 + o2l]
    float* As = dsm + 16 * 32 * 17;  // [i1][r]
    const int tid = threadIdx.x;
    const int o1 = blockIdx.x, q = blockIdx.y, s = blockIdx.z;

    for (int idx = tid; idx < 8192; idx += 256) {
        int r = idx >> 9, i2 = (idx >> 4) & 31, o2l = idx & 15;
        Bs[(r * 32 + i2) * 17 + o2l] =
            g1b[(size_t)s * 32768 + (size_t)r * 2048 + i2 * 64 + q * 16 + o2l];
    }
    for (int idx = tid; idx < 512; idx += 256) {
        int i1 = idx >> 4, r = idx & 15;
        As[idx] = g1a[(((size_t)s * 32 + i1) * 64 + o1) * 16 + r];
    }
    __syncthreads();

    const size_t ob = ((size_t)s * Ff + (size_t)o1 * 64 + q * 16) * Dm;
#pragma unroll 4
    for (int it = 0; it < 64; it++) {
        int idx = tid + (it << 8);
        int o2l = idx >> 10, d = idx & 1023;
        int i1 = d >> 5, i2 = d & 31;
        const float* ap = As + i1 * 16;
        const float* bp = Bs + i2 * 17 + o2l;
        float sum = 0.f;
#pragma unroll
        for (int r = 0; r < 16; r++) sum += ap[r] * bp[r * 544];   // 32*17
        o[ob + (size_t)o2l * Dm + d] = __float2half(sum);
    }
}

// smem-tiled w2 build, 4x finer: block (o1, o2-quad q, s). Same r-order (bit-exact).
// w2t[s][d][o1*64+q*16+o2l] = sum_r g2a[s,o1,i1,r] * g2b[s,r,q*16+o2l,i2]
#define W2_SMEM ((16*16*33 + 512) * 4)
__global__ __launch_bounds__(256)
void build_w2_tiled(const float* __restrict__ g2a, const float* __restrict__ g2b,
                    __half* __restrict__ o)
{
    extern __shared__ float dsm[];
    float* Bs = dsm;                 // [(r*16+o2l)*33 + i2]
    float* As = dsm + 16 * 16 * 33;  // [i1][r]
    const int tid = threadIdx.x;
    const int o1 = blockIdx.x, q = blockIdx.y, s = blockIdx.z;

    for (int idx = tid; idx < 8192; idx += 256) {
        int r = idx >> 9, o2l = (idx >> 5) & 15, i2 = idx & 31;
        Bs[(r * 16 + o2l) * 33 + i2] =
            g2b[(size_t)s * 32768 + (size_t)r * 2048 + (q * 16 + o2l) * 32 + i2];
    }
    for (int idx = tid; idx < 512; idx += 256) {
        int i1 = idx >> 4, r = idx & 15;
        As[idx] = g2a[(((size_t)s * 64 + o1) * 32 + i1) * 16 + r];
    }
    __syncthreads();

    const size_t ob = (size_t)s * Dm * Ff + (size_t)o1 * 64 + q * 16;
#pragma unroll 4
    for (int it = 0; it < 64; it++) {
        int idx = tid + (it << 8);
        int d = idx >> 4, o2l = idx & 15;
        int i1 = d >> 5, i2 = d & 31;
        const float* ap = As + i1 * 16;
        const float* bp = Bs + o2l * 33 + i2;
        float sum = 0.f;
#pragma unroll
        for (int r = 0; r < 16; r++) sum += ap[r] * bp[r * 528];   // 16*33
        o[ob + (size_t)d * Ff + o2l] = __float2half(sum);
    }
}

// ---------------- fp16 HMMA GEMM body (templated on BN tile) ----------------
// C = A * B^T. XA=1 plain A, XA=2 compensated A (Ah+Al).
// EPI: 0 split, 1 gelu+single, 2 bias+fp32, 3 bias+split, 4 fp32
template <int EPI, int XA, int BNT>
__device__ __forceinline__
void gemm_body(const __half* __restrict__ Ah, const __half* __restrict__ Al,
               int lda, size_t aBS,
               const __half* __restrict__ Bh, int ldb, size_t bBS,
               int K, int ldc, size_t cBS,
               float* __restrict__ Cf,
               __half* __restrict__ Chi, __half* __restrict__ Clo,
               const float* __restrict__ bias, size_t biasBS)
{
    constexpr uint32_t B_Bt = BNT * BK * 2;
    constexpr uint32_t STG  = XA * A_B + B_Bt;
    constexpr int P = BNT / 64;          // p-loop count (16 cols per p)
    extern __shared__ char smem[];
    const uint32_t sb = smem_u32(smem);
    const int tid = threadIdx.x, wid = tid >> 5, lane = tid & 31;
    const int zz = blockIdx.z;
    const int m0 = blockIdx.y * BM, n0 = blockIdx.x * BNT;

    const __half* pAh = Ah + (size_t)zz * aBS;
    const __half* pAl = (XA == 2) ? Al + (size_t)zz * aBS : nullptr;
    const __half* pBh = Bh + (size_t)zz * bBS;

    const int mwarp = (wid & 1) * 64;          // 2 warps over M
    const int nwarp = (wid >> 1) * (BNT / 4);  // 4 warps over N

    float acc[4][2 * P][4];
#pragma unroll
    for (int i = 0; i < 4; i++)
#pragma unroll
        for (int j = 0; j < 2 * P; j++)
#pragma unroll
            for (int c = 0; c < 4; c++) acc[i][j][c] = 0.f;

    const int nk = K / BK;
    const int fr = tid >> 3, fc = tid & 7;   // 32 rows per pass, 8 chunk-cols

    auto fill = [&](int kt, int st) {
        const int k0 = kt * BK;
        const uint32_t base = sb + st * STG;
#pragma unroll
        for (int i = 0; i < 4; i++) {
            int r = fr + i * 32;
            cp16(base + swz(r, fc), pAh + (size_t)(m0 + r) * lda + k0 + fc * 8);
            if (XA == 2)
                cp16(base + A_B + swz(r, fc), pAl + (size_t)(m0 + r) * lda + k0 + fc * 8);
        }
#pragma unroll
        for (int i = 0; i < BNT / 32; i++) {
            int r = fr + i * 32;
            cp16(base + XA*A_B + swz(r, fc), pBh + (size_t)(n0 + r) * ldb + k0 + fc * 8);
        }
        CP_COMMIT();
    };

    fill(0, 0);
    if (nk > 1) fill(1, 1);

    const int ra = lane & 15, ca = lane >> 4;
    const int gb = lane >> 3, rb = lane & 7;

    for (int kt = 0; kt < nk; kt++) {
        if (kt + 1 >= nk) { CP_WAIT(0); } else { CP_WAIT(1); }
        __syncthreads();
        if (kt + 2 < nk) fill(kt + 2, (kt + 2) % NST);

        const uint32_t base = sb + (kt % NST) * STG;
        const uint32_t sAh = base, sAl = base + A_B;
        const uint32_t sBh = base + XA * A_B;

#pragma unroll
        for (int kk = 0; kk < 4; kk++) {
            uint32_t ah[4][4], al[4][4];
#pragma unroll
            for (int mt = 0; mt < 4; mt++) {
                uint32_t off = swz(mwarp + mt * 16 + ra, kk * 2 + ca);
                LDSM4(ah[mt], sAh + off);
                if (XA == 2) LDSM4(al[mt], sAl + off);
            }
#pragma unroll
            for (int p = 0; p < P; p++) {
                uint32_t bh[4];
                uint32_t off = swz(nwarp + p * 16 + (gb & 1) * 8 + rb, kk * 2 + (gb >> 1));
                LDSM4(bh, sBh + off);
#pragma unroll
                for (int mt = 0; mt < 4; mt++) {
                    MMA16816(acc[mt][2*p],   ah[mt], bh[0], bh[2]);
                    MMA16816(acc[mt][2*p+1], ah[mt], bh[1], bh[3]);
                    if (XA == 2) {
                        MMA16816(acc[mt][2*p],   al[mt], bh[0], bh[2]);
                        MMA16816(acc[mt][2*p+1], al[mt], bh[1], bh[3]);
                    }
                }
            }
        }
    }

    // ---------------- epilogue ----------------
    float* Cfp = Cf ? Cf + (size_t)zz * cBS : nullptr;
    __half* Chp = Chi ? Chi + (size_t)zz * cBS : nullptr;
    __half* Clp = Clo ? Clo + (size_t)zz * cBS : nullptr;
    const float* bp = bias ? bias + (size_t)zz * biasBS : nullptr;
    const int g4 = lane >> 2, q2 = (lane & 3) * 2;

#pragma unroll
    for (int mt = 0; mt < 4; mt++) {
#pragma unroll
        for (int nt = 0; nt < 2 * P; nt++) {
            int r0 = m0 + mwarp + mt * 16 + g4;
            int c  = n0 + nwarp + nt * 8 + q2;
#pragma unroll
            for (int half = 0; half < 2; half++) {
                int rr = r0 + half * 8;
                float v0 = acc[mt][nt][half * 2 + 0];
                float v1 = acc[mt][nt][half * 2 + 1];
                size_t off = (size_t)rr * ldc + c;
                if (EPI == 2) {
                    *reinterpret_cast<float2*>(&Cfp[off]) =
                        make_float2(v0 + bp[c], v1 + bp[c + 1]);
                } else if (EPI == 4) {
                    *reinterpret_cast<float2*>(&Cfp[off]) = make_float2(v0, v1);
                } else if (EPI == 1) {
                    __half2 h2;
                    h2.x = __float2half(gelu_exact(v0));
                    h2.y = __float2half(gelu_exact(v1));
                    *reinterpret_cast<__half2*>(&Chp[off]) = h2;
                } else {
                    if (EPI == 3) { v0 += bp[c]; v1 += bp[c + 1]; }
                    __half2 h2, l2;
                    split2(v0, &h2.x, &l2.x);
                    split2(v1, &h2.y, &l2.y);
                    *reinterpret_cast<__half2*>(&Chp[off]) = h2;
                    *reinterpret_cast<__half2*>(&Clp[off]) = l2;
                }
            }
        }
    }
}

// occupancy-1 shell (BN=256)
template <int EPI, int XA>
__global__ __launch_bounds__(256, 1)
void mma_gemm(const __half* __restrict__ Ah, const __half* __restrict__ Al,
              int lda, size_t aBS,
              const __half* __restrict__ Bh, int ldb, size_t bBS,
              int K, int ldc, size_t cBS,
              float* __restrict__ Cf,
              __half* __restrict__ Chi, __half* __restrict__ Clo,
              const float* __restrict__ bias, size_t biasBS)
{
    gemm_body<EPI, XA, 256>(Ah, Al, lda, aBS, Bh, ldb, bBS, K, ldc, cBS,
                            Cf, Chi, Clo, bias, biasBS);
}

// occupancy-2 shell (BN=128) — used by the big FFN GEMMs
template <int EPI, int XA>
__global__ __launch_bounds__(256, 2)
void mma_gemm2(const __half* __restrict__ Ah, const __half* __restrict__ Al,
               int lda, size_t aBS,
               const __half* __restrict__ Bh, int ldb, size_t bBS,
               int K, int ldc, size_t cBS,
               float* __restrict__ Cf,
               __half* __restrict__ Chi, __half* __restrict__ Clo,
               const float* __restrict__ bias, size_t biasBS)
{
    gemm_body<EPI, XA, 128>(Ah, Al, lda, aBS, Bh, ldb, bBS, K, ldc, cBS,
                            Cf, Chi, Clo, bias, biasBS);
}

// ---------------- attention collapse: scores, softmax, z ----------------
__global__ __launch_bounds__(256)
void attn_collapse(const __half* __restrict__ qh, const __half* __restrict__ ql,
                   const float* __restrict__ t,
                   const __half* __restrict__ yh, const __half* __restrict__ yl,
                   const float* __restrict__ bk,
                   __half* __restrict__ zh, __half* __restrict__ zl)
{
    const int b = blockIdx.x, tid = threadIdx.x;
    const int wid = tid >> 5, lane = tid & 31;
    __shared__ float ys[Ssup][Dm];
    __shared__ float sc[16], qb[Hh], attn[16];

#pragma unroll
    for (int it = 0; it < 8; it++) {
        int idx = tid + it * 256;
        int s = idx >> 9, mm = idx & 511;
        size_t g = ((size_t)s * Bsz + b) * Dm + mm * 2;
        __half2 h2 = *reinterpret_cast<const __half2*>(&yh[g]);
        __half2 l2 = *reinterpret_cast<const __half2*>(&yl[g]);
        ys[s][mm * 2]     = __half2float(h2.x) + __half2float(l2.x);
        ys[s][mm * 2 + 1] = __half2float(h2.y) + __half2float(l2.y);
    }
    if (wid < Hh) {
        float sum = 0.f;
        for (int j = lane; j < HD; j += 32) {
            size_t g = (size_t)b * Dm + wid * HD + j;
            float qv = __half2float(qh[g]) + __half2float(ql[g]);
            sum = fmaf(qv, bk[wid * HD + j], sum);
        }
#pragma unroll
        for (int o = 16; o; o >>= 1) sum += __shfl_xor_sync(0xffffffffu, sum, o);
        if (lane == 0) qb[wid] = sum;
    }
    __syncthreads();

#pragma unroll
    for (int i = 0; i < 2; i++) {
        int p = wid * 2 + i;
        int h = p >> 2, s = p & 3;
        const float* tp = t + ((size_t)h * Bsz + b) * Dm;
        float sum = 0.f;
        for (int m = lane; m < Dm; m += 32) sum = fmaf(ys[s][m], tp[m], sum);
#pragma unroll
        for (int o = 16; o; o >>= 1) sum += __shfl_xor_sync(0xffffffffu, sum, o);
        if (lane == 0) sc[p] = sum;
    }
    __syncthreads();

    if (tid < Hh) {
        int h = tid;
        float s0 = (sc[h*4+0] + qb[h]) * 0.0625f;
        float s1 = (sc[h*4+1] + qb[h]) * 0.0625f;
        float s2 = (sc[h*4+2] + qb[h]) * 0.0625f;
        float s3 = (sc[h*4+3] + qb[h]) * 0.0625f;
        float m = fmaxf(fmaxf(s0, s1), fmaxf(s2, s3));
        float e0 = expf(s0-m), e1 = expf(s1-m), e2 = expf(s2-m), e3 = expf(s3-m);
        float inv = 1.f / (e0 + e1 + e2 + e3);
        attn[h*4+0] = e0*inv; attn[h*4+1] = e1*inv;
        attn[h*4+2] = e2*inv; attn[h*4+3] = e3*inv;
    }
    __syncthreads();

#pragma unroll
    for (int it = 0; it < 8; it++) {
        int idx = tid + it * 256;
        int h = idx >> 9, mm = idx & 511;
        int m = mm * 2;
        float a0 = attn[h*4+0], a1 = attn[h*4+1], a2 = attn[h*4+2], a3 = attn[h*4+3];
        float z0 = a0*ys[0][m]   + a1*ys[1][m]   + a2*ys[2][m]   + a3*ys[3][m];
        float z1 = a0*ys[0][m+1] + a1*ys[1][m+1] + a2*ys[2][m+1] + a3*ys[3][m+1];
        size_t g = ((size_t)h * Bsz + b) * Dm + m;
        __half2 zh2, zl2;
        split2(z0, &zh2.x, &zl2.x);
        split2(z1, &zh2.y, &zl2.y);
        *reinterpret_cast<__half2*>(&zh[g]) = zh2;
        *reinterpret_cast<__half2*>(&zl[g]) = zl2;
    }
}

// ---------------- launch ----------------
extern "C" void kernel_launch(void* const* d_in, const int* in_sizes, int n_in,
                              void* d_out, int out_size)
{
    const float* x   = (const float*)d_in[0];
    const float* g1a = (const float*)d_in[1];
    const float* g1b = (const float*)d_in[2];
    const float* g2a = (const float*)d_in[3];
    const float* g2b = (const float*)d_in[4];
    const float* wq  = (const float*)d_in[5];
    const float* bq  = (const float*)d_in[6];
    const float* wk  = (const float*)d_in[7];
    const float* bk  = (const float*)d_in[8];
    const float* wv  = (const float*)d_in[9];
    const float* bv  = (const float*)d_in[10];
    const float* wo  = (const float*)d_in[11];
    const float* bo  = (const float*)d_in[12];
    float* out = (float*)d_out;

    __half *xh,*xl,*w1,*w2,*wqp,*wk2,*wvp,*wop,*hh,*yh,*yl,*qh,*ql,*zh,*zl,*oh,*ol;
    float *t;
    cudaGetSymbolAddress((void**)&xh, g_xh);   cudaGetSymbolAddress((void**)&xl, g_xl);
    cudaGetSymbolAddress((void**)&w1, g_w1);   cudaGetSymbolAddress((void**)&w2, g_w2);
    cudaGetSymbolAddress((void**)&wqp, g_wq);  cudaGetSymbolAddress((void**)&wk2, g_wk2);
    cudaGetSymbolAddress((void**)&wvp, g_wv);  cudaGetSymbolAddress((void**)&wop, g_wo);
    cudaGetSymbolAddress((void**)&hh, g_hh);
    cudaGetSymbolAddress((void**)&yh, g_yh);   cudaGetSymbolAddress((void**)&yl, g_yl);
    cudaGetSymbolAddress((void**)&qh, g_qh);   cudaGetSymbolAddress((void**)&ql, g_ql);
    cudaGetSymbolAddress((void**)&zh, g_zh);   cudaGetSymbolAddress((void**)&zl, g_zl);
    cudaGetSymbolAddress((void**)&oh, g_oh);   cudaGetSymbolAddress((void**)&ol, g_ol);
    cudaGetSymbolAddress((void**)&t, g_t);

    const int SM1b = NST * (A_B + 128 * BK * 2);     // 98304  (XA=1, BN=128, occ2)
    const int SM2  = NST * (2 * A_B + 256 * BK * 2); // 196608 (XA=2, BN=256)
    cudaFuncSetAttribute((const void*)mma_gemm2<1,1>, cudaFuncAttributeMaxDynamicSharedMemorySize, SM1b);
    cudaFuncSetAttribute((const void*)mma_gemm2<0,1>, cudaFuncAttributeMaxDynamicSharedMemorySize, SM1b);
    cudaFuncSetAttribute((const void*)mma_gemm<3,2>,  cudaFuncAttributeMaxDynamicSharedMemorySize, SM2);
    cudaFuncSetAttribute((const void*)mma_gemm<4,2>,  cudaFuncAttributeMaxDynamicSharedMemorySize, SM2);
    cudaFuncSetAttribute((const void*)mma_gemm<2,2>,  cudaFuncAttributeMaxDynamicSharedMemorySize, SM2);
    cudaFuncSetAttribute((const void*)build_w1_tiled, cudaFuncAttributeMaxDynamicSharedMemorySize, W1_SMEM);
    cudaFuncSetAttribute((const void*)build_w2_tiled, cudaFuncAttributeMaxDynamicSharedMemorySize, W2_SMEM);

    const size_t sBD = (size_t)Bsz * Dm, sBF = (size_t)Bsz * Ff;
    const size_t sDD = (size_t)Dm * Dm, sFD = (size_t)Ff * Dm;

    // streams: s1 = q/t chain (+its weight preps), s2 = build_w2. Fallback: all on 0.
    cudaStream_t s1 = 0, s2 = 0;
    cudaEvent_t evX = 0, evJ = 0, evW2 = 0;
    bool forked = (cudaStreamCreateWithFlags(&s1, cudaStreamNonBlocking) == cudaSuccess);
    if (forked && cudaStreamCreateWithFlags(&s2, cudaStreamNonBlocking) != cudaSuccess) {
        cudaStreamDestroy(s1); s1 = 0; forked = false;
    }
    if (forked && (cudaEventCreateWithFlags(&evX, cudaEventDisableTiming) != cudaSuccess ||
                   cudaEventCreateWithFlags(&evJ, cudaEventDisableTiming) != cudaSuccess ||
                   cudaEventCreateWithFlags(&evW2, cudaEventDisableTiming) != cudaSuccess)) {
        if (evX) cudaEventDestroy(evX);
        if (evJ) cudaEventDestroy(evJ);
        if (evW2) cudaEventDestroy(evW2);
        cudaStreamDestroy(s1); cudaStreamDestroy(s2);
        s1 = s2 = 0; evX = evJ = evW2 = 0; forked = false;
    }

    // main: x split (needed by FFN1 and q)
    split_arr<<<(Bsz * Dm) / 256, 256>>>(x, xh, xl, sBD);
    // fork BOTH side streams from the origin — mandatory under graph capture
    if (forked) {
        cudaEventRecord(evX, 0);
        cudaStreamWaitEvent(s1, evX, 0);
        cudaStreamWaitEvent(s2, evX, 0);
    }

    // s2: w2 build (only FFN2 needs it)
    build_w2_tiled<<<dim3(64, 4, Ssup), 256, W2_SMEM, s2>>>(g2a, g2b, w2);
    if (forked) cudaEventRecord(evW2, s2);

    // s1: weight preps for attention path, then q -> t
    ttile_w<<<dim3(32, 32, 3), 256, 0, s1>>>(wq, wv, wo, wqp, wvp, wop);
    half_arr<<<(Dm * Dm) / 256, 256, 0, s1>>>(wk, wk2, sDD);
    mma_gemm<3,2><<<dim3(Dm/256, Bsz/BM, 1), 256, SM2, s1>>>(
        xh, xl, Dm, 0, wqp, Dm, 0, Dm, Dm, 0,
        nullptr, qh, ql, bq, 0);
    mma_gemm<4,2><<<dim3(Dm/256, Bsz/BM, Hh), 256, SM2, s1>>>(
        qh, ql, Dm, HD, wk2, Dm, HD, HD, Dm, sBD,
        t, nullptr, nullptr, nullptr, 0);
    if (forked) cudaEventRecord(evJ, s1);

    // main: w1 build, FFN1
    build_w1_tiled<<<dim3(64, 4, Ssup), 256, W1_SMEM>>>(g1a, g1b, w1);
    mma_gemm2<1,1><<<dim3(Ff/128, Bsz/BM, Ssup), 256, SM1b>>>(
        xh, nullptr, Dm, 0, w1, Dm, sFD, Dm, Ff, sBF,
        nullptr, hh, nullptr, nullptr, 0);

    // main: FFN2 (needs w2 from s2)
    if (forked) cudaStreamWaitEvent(0, evW2, 0);
    mma_gemm2<0,1><<<dim3(Dm/128, Bsz/BM, Ssup), 256, SM1b>>>(
        hh, nullptr, Ff, sBF, w2, Ff, (size_t)Dm*Ff, Ff, Dm, sBD,
        nullptr, yh, yl, nullptr, 0);

    // join: attn needs y (main) + t, and later wvp/wop (s1)
    if (forked) cudaStreamWaitEvent(0, evJ, 0);

    attn_collapse<<<Bsz, 256>>>(qh, ql, t, yh, yl, bk, zh, zl);

    mma_gemm<3,2><<<dim3(1, Bsz/BM, Hh), 256, SM2>>>(
        zh, zl, Dm, sBD, wvp, Dm, (size_t)HD*Dm, Dm, Dm, (size_t)HD,
        nullptr, oh, ol, bv, HD);

    mma_gemm<2,2><<<dim3(Dm/256, Bsz/BM, 1), 256, SM2>>>(
        oh, ol, Dm, 0, wop, Dm, 0, Dm, Dm, 0,
        out, nullptr, nullptr, bo, 0);

    if (forked) {
        cudaEventDestroy(evX);
        cudaEventDestroy(evJ);
        cudaEventDestroy(evW2);
        cudaStreamDestroy(s1);
        cudaStreamDestroy(s2);
    }
}

// round 13
// speedup vs baseline: 8.0003x; 1.0950x over previous
#include <cuda_runtime.h>
#include <cuda_fp16.h>
#include <math.h>
#include <stdint.h>

// ---------------- problem constants ----------------
#define Bsz 8192
#define Dm  1024
#define Ff  4096
#define Ssup 4
#define Hh  4
#define HD  256

// ---------------- GEMM tiling ----------------
#define BM 128
#define BK 64                    // fp16 elems per k-tile (128B rows)
#define NST 3
#define A_B   (BM * BK * 2)      // 16384 bytes per A matrix (hi or lo)

// ---------------- scratch (device globals) ----------------
__device__ __half g_xh [(size_t)Bsz*Dm];
__device__ __half g_w1 [(size_t)Ssup*Ff*Dm];   // [s][f][d] (transposed)
__device__ __half g_w2 [(size_t)Ssup*Dm*Ff];   // [s][d][f]
__device__ __half g_wq [(size_t)Dm*Dm];        // transposed [n][k]
__device__ __half g_wk2[(size_t)Dm*Dm];        // straight [m][d]
__device__ __half g_wv [(size_t)Dm*Dm];        // transposed
__device__ __half g_wo [(size_t)Dm*Dm];        // transposed
__device__ __half g_hh [(size_t)Ssup*Bsz*Ff];                             // h single fp16
__device__ __half g_yh [(size_t)Ssup*Bsz*Dm],  g_yl [(size_t)Ssup*Bsz*Dm];
__device__ __half g_qh [(size_t)Bsz*Dm];
__device__ __half g_zh [(size_t)Hh*Bsz*Dm];    // [h][b][m]
__device__ __half g_oh [(size_t)Bsz*Dm];
__device__ float g_t [(size_t)Hh*Bsz*Dm];      // [h][b][m]

// ---------------- asm helpers (generic-target PTX, sm_80+) ----------------
__device__ __forceinline__ uint32_t smem_u32(const void* p) {
    uint32_t a;
    asm("{ .reg .u64 t; cvta.to.shared.u64 t, %1; cvt.u32.u64 %0, t; }" : "=r"(a) : "l"(p));
    return a;
}
__device__ __forceinline__ void cp16(uint32_t dst, const void* src) {
    asm volatile("cp.async.cg.shared.global [%0], [%1], 16;" :: "r"(dst), "l"(src));
}
#define CP_COMMIT() asm volatile("cp.async.commit_group;" ::: "memory")
#define CP_WAIT(n)  asm volatile("cp.async.wait_group %0;" :: "n"(n) : "memory")
#define LDSM4(r, a) asm volatile("ldmatrix.sync.aligned.m8n8.x4.shared.b16 {%0,%1,%2,%3}, [%4];" \
    : "=r"((r)[0]), "=r"((r)[1]), "=r"((r)[2]), "=r"((r)[3]) : "r"(a))
#define MMA16816(ac, a, b0, b1) \
    asm volatile("mma.sync.aligned.m16n8k16.row.col.f32.f16.f16.f32 " \
        "{%0,%1,%2,%3}, {%4,%5,%6,%7}, {%8,%9}, {%0,%1,%2,%3};" \
        : "+f"((ac)[0]), "+f"((ac)[1]), "+f"((ac)[2]), "+f"((ac)[3]) \
        : "r"((a)[0]), "r"((a)[1]), "r"((a)[2]), "r"((a)[3]), "r"(b0), "r"(b1))

__device__ __forceinline__ float gelu_exact(float x) {
    return 0.5f * x * (1.0f + erff(x * 0.70710678118654752440f));
}
__device__ __forceinline__ void split2(float v, __half* h, __half* l) {
    __half hb = __float2half(v);
    *h = hb;
    *l = __float2half(v - __half2float(hb));
}
// 16B-chunk swizzle for 128B rows (8 chunks per row): chunk' = chunk ^ (row & 7)
__device__ __forceinline__ uint32_t swz(int row, int c16) {
    return (uint32_t)(row * 8 + (c16 ^ (row & 7))) * 16u;
}

// ---------------- conversion / build kernels ----------------
__global__ void half_arr(const float* __restrict__ in, __half* __restrict__ o, size_t n) {
    size_t i = (size_t)blockIdx.x * blockDim.x + threadIdx.x;
    if (i < n) o[i] = __float2half(in[i]);
}

// tiled fused transpose: wq/wv/wo [k][n] -> [n][k] fp16, one kernel
__global__ __launch_bounds__(256)
void ttile_w(const float* __restrict__ wq, const float* __restrict__ wv,
             const float* __restrict__ wo,
             __half* __restrict__ oq, __half* __restrict__ ov, __half* __restrict__ oo)
{
    __shared__ float tile[32][33];
    const float* w = blockIdx.z == 0 ? wq : (blockIdx.z == 1 ? wv : wo);
    __half* o      = blockIdx.z == 0 ? oq : (blockIdx.z == 1 ? ov : oo);
    const int bx = blockIdx.x * 32, by = blockIdx.y * 32;
    const int tx = threadIdx.x & 31, ty = threadIdx.x >> 5;  // 32x8
#pragma unroll
    for (int j = 0; j < 4; j++)
        tile[ty + j * 8][tx] = w[(size_t)(by + ty + j * 8) * Dm + bx + tx];
    __syncthreads();
#pragma unroll
    for (int j = 0; j < 4; j++)
        o[(size_t)(bx + ty + j * 8) * Dm + by + tx] = __float2half(tile[tx][ty + j * 8]);
}

// smem-tiled w1 build, 4x finer: block (o1, o2-quad q, s). Stages 16-o2 slice of g1b[s].
#define W1_SMEM ((16*32*17 + 512) * 4)
__global__ __launch_bounds__(256)
void build_w1_tiled(const float* __restrict__ g1a, const float* __restrict__ g1b,
                    __half* __restrict__ o)
{
    extern __shared__ float dsm[];
    float* Bs = dsm;                 // [(r*32+i2)*17 + o2l]
    float* As = dsm + 16 * 32 * 17;  // [i1][r]
    const int tid = threadIdx.x;
    const int o1 = blockIdx.x, q = blockIdx.y, s = blockIdx.z;

    for (int idx = tid; idx < 8192; idx += 256) {
        int r = idx >> 9, i2 = (idx >> 4) & 31, o2l = idx & 15;
        Bs[(r * 32 + i2) * 17 + o2l] =
            g1b[(size_t)s * 32768 + (size_t)r * 2048 + i2 * 64 + q * 16 + o2l];
    }
    for (int idx = tid; idx < 512; idx += 256) {
        int i1 = idx >> 4, r = idx & 15;
        As[idx] = g1a[(((size_t)s * 32 + i1) * 64 + o1) * 16 + r];
    }
    __syncthreads();

    const size_t ob = ((size_t)s * Ff + (size_t)o1 * 64 + q * 16) * Dm;
#pragma unroll 4
    for (int it = 0; it < 64; it++) {
        int idx = tid + (it << 8);
        int o2l = idx >> 10, d = idx & 1023;
        int i1 = d >> 5, i2 = d & 31;
        const float* ap = As + i1 * 16;
        const float* bp = Bs + i2 * 17 + o2l;
        float sum = 0.f;
#pragma unroll
        for (int r = 0; r < 16; r++) sum += ap[r] * bp[r * 544];   // 32*17
        o[ob + (size_t)o2l * Dm + d] = __float2half(sum);
    }
}

// smem-tiled w2 build, 4x finer: block (o1, o2-quad q, s). Same r-order (bit-exact).
#define W2_SMEM ((16*16*33 + 512) * 4)
__global__ __launch_bounds__(256)
void build_w2_tiled(const float* __restrict__ g2a, const float* __restrict__ g2b,
                    __half* __restrict__ o)
{
    extern __shared__ float dsm[];
    float* Bs = dsm;                 // [(r*16+o2l)*33 + i2]
    float* As = dsm + 16 * 16 * 33;  // [i1][r]
    const int tid = threadIdx.x;
    const int o1 = blockIdx.x, q = blockIdx.y, s = blockIdx.z;

    for (int idx = tid; idx < 8192; idx += 256) {
        int r = idx >> 9, o2l = (idx >> 5) & 15, i2 = idx & 31;
        Bs[(r * 16 + o2l) * 33 + i2] =
            g2b[(size_t)s * 32768 + (size_t)r * 2048 + (q * 16 + o2l) * 32 + i2];
    }
    for (int idx = tid; idx < 512; idx += 256) {
        int i1 = idx >> 4, r = idx & 15;
        As[idx] = g2a[(((size_t)s * 64 + o1) * 32 + i1) * 16 + r];
    }
    __syncthreads();

    const size_t ob = (size_t)s * Dm * Ff + (size_t)o1 * 64 + q * 16;
#pragma unroll 4
    for (int it = 0; it < 64; it++) {
        int idx = tid + (it << 8);
        int d = idx >> 4, o2l = idx & 15;
        int i1 = d >> 5, i2 = d & 31;
        const float* ap = As + i1 * 16;
        const float* bp = Bs + o2l * 33 + i2;
        float sum = 0.f;
#pragma unroll
        for (int r = 0; r < 16; r++) sum += ap[r] * bp[r * 528];   // 16*33
        o[ob + (size_t)d * Ff + o2l] = __float2half(sum);
    }
}

// ---------------- fp16 HMMA GEMM body (templated on BN tile) ----------------
// C = A * B^T. XA=1 plain A, XA=2 compensated A (Ah+Al).
// EPI: 0 split, 1 gelu+single, 2 bias+fp32, 4 fp32, 5 bias+single
template <int EPI, int XA, int BNT>
__device__ __forceinline__
void gemm_body(const __half* __restrict__ Ah, const __half* __restrict__ Al,
               int lda, size_t aBS,
               const __half* __restrict__ Bh, int ldb, size_t bBS,
               int K, int ldc, size_t cBS,
               float* __restrict__ Cf,
               __half* __restrict__ Chi, __half* __restrict__ Clo,
               const float* __restrict__ bias, size_t biasBS)
{
    constexpr uint32_t B_Bt = BNT * BK * 2;
    constexpr uint32_t STG  = XA * A_B + B_Bt;
    constexpr int P = BNT / 64;          // p-loop count (16 cols per p)
    extern __shared__ char smem[];
    const uint32_t sb = smem_u32(smem);
    const int tid = threadIdx.x, wid = tid >> 5, lane = tid & 31;
    const int zz = blockIdx.z;
    const int m0 = blockIdx.y * BM, n0 = blockIdx.x * BNT;

    const __half* pAh = Ah + (size_t)zz * aBS;
    const __half* pAl = (XA == 2) ? Al + (size_t)zz * aBS : nullptr;
    const __half* pBh = Bh + (size_t)zz * bBS;

    const int mwarp = (wid & 1) * 64;          // 2 warps over M
    const int nwarp = (wid >> 1) * (BNT / 4);  // 4 warps over N

    float acc[4][2 * P][4];
#pragma unroll
    for (int i = 0; i < 4; i++)
#pragma unroll
        for (int j = 0; j < 2 * P; j++)
#pragma unroll
            for (int c = 0; c < 4; c++) acc[i][j][c] = 0.f;

    const int nk = K / BK;
    const int fr = tid >> 3, fc = tid & 7;   // 32 rows per pass, 8 chunk-cols

    auto fill = [&](int kt, int st) {
        const int k0 = kt * BK;
        const uint32_t base = sb + st * STG;
#pragma unroll
        for (int i = 0; i < 4; i++) {
            int r = fr + i * 32;
            cp16(base + swz(r, fc), pAh + (size_t)(m0 + r) * lda + k0 + fc * 8);
            if (XA == 2)
                cp16(base + A_B + swz(r, fc), pAl + (size_t)(m0 + r) * lda + k0 + fc * 8);
        }
#pragma unroll
        for (int i = 0; i < BNT / 32; i++) {
            int r = fr + i * 32;
            cp16(base + XA*A_B + swz(r, fc), pBh + (size_t)(n0 + r) * ldb + k0 + fc * 8);
        }
        CP_COMMIT();
    };

    fill(0, 0);
    if (nk > 1) fill(1, 1);

    const int ra = lane & 15, ca = lane >> 4;
    const int gb = lane >> 3, rb = lane & 7;

    for (int kt = 0; kt < nk; kt++) {
        if (kt + 1 >= nk) { CP_WAIT(0); } else { CP_WAIT(1); }
        __syncthreads();
        if (kt + 2 < nk) fill(kt + 2, (kt + 2) % NST);

        const uint32_t base = sb + (kt % NST) * STG;
        const uint32_t sAh = base, sAl = base + A_B;
        const uint32_t sBh = base + XA * A_B;

#pragma unroll
        for (int kk = 0; kk < 4; kk++) {
            uint32_t ah[4][4], al[4][4];
#pragma unroll
            for (int mt = 0; mt < 4; mt++) {
                uint32_t off = swz(mwarp + mt * 16 + ra, kk * 2 + ca);
                LDSM4(ah[mt], sAh + off);
                if (XA == 2) LDSM4(al[mt], sAl + off);
            }
#pragma unroll
            for (int p = 0; p < P; p++) {
                uint32_t bh[4];
                uint32_t off = swz(nwarp + p * 16 + (gb & 1) * 8 + rb, kk * 2 + (gb >> 1));
                LDSM4(bh, sBh + off);
#pragma unroll
                for (int mt = 0; mt < 4; mt++) {
                    MMA16816(acc[mt][2*p],   ah[mt], bh[0], bh[2]);
                    MMA16816(acc[mt][2*p+1], ah[mt], bh[1], bh[3]);
                    if (XA == 2) {
                        MMA16816(acc[mt][2*p],   al[mt], bh[0], bh[2]);
                        MMA16816(acc[mt][2*p+1], al[mt], bh[1], bh[3]);
                    }
                }
            }
        }
    }

    // ---------------- epilogue ----------------
    float* Cfp = Cf ? Cf + (size_t)zz * cBS : nullptr;
    __half* Chp = Chi ? Chi + (size_t)zz * cBS : nullptr;
    __half* Clp = Clo ? Clo + (size_t)zz * cBS : nullptr;
    const float* bp = bias ? bias + (size_t)zz * biasBS : nullptr;
    const int g4 = lane >> 2, q2 = (lane & 3) * 2;

#pragma unroll
    for (int mt = 0; mt < 4; mt++) {
#pragma unroll
        for (int nt = 0; nt < 2 * P; nt++) {
            int r0 = m0 + mwarp + mt * 16 + g4;
            int c  = n0 + nwarp + nt * 8 + q2;
#pragma unroll
            for (int half = 0; half < 2; half++) {
                int rr = r0 + half * 8;
                float v0 = acc[mt][nt][half * 2 + 0];
                float v1 = acc[mt][nt][half * 2 + 1];
                size_t off = (size_t)rr * ldc + c;
                if (EPI == 2) {
                    *reinterpret_cast<float2*>(&Cfp[off]) =
                        make_float2(v0 + bp[c], v1 + bp[c + 1]);
                } else if (EPI == 4) {
                    *reinterpret_cast<float2*>(&Cfp[off]) = make_float2(v0, v1);
                } else if (EPI == 1) {
                    __half2 h2;
                    h2.x = __float2half(gelu_exact(v0));
                    h2.y = __float2half(gelu_exact(v1));
                    *reinterpret_cast<__half2*>(&Chp[off]) = h2;
                } else if (EPI == 5) {
                    __half2 h2;
                    h2.x = __float2half(v0 + bp[c]);
                    h2.y = __float2half(v1 + bp[c + 1]);
                    *reinterpret_cast<__half2*>(&Chp[off]) = h2;
                } else {  // EPI == 0: split
                    __half2 h2, l2;
                    split2(v0, &h2.x, &l2.x);
                    split2(v1, &h2.y, &l2.y);
                    *reinterpret_cast<__half2*>(&Chp[off]) = h2;
                    *reinterpret_cast<__half2*>(&Clp[off]) = l2;
                }
            }
        }
    }
}

// occupancy-1 shell (BN=256)
template <int EPI, int XA>
__global__ __launch_bounds__(256, 1)
void mma_gemm(const __half* __restrict__ Ah, const __half* __restrict__ Al,
              int lda, size_t aBS,
              const __half* __restrict__ Bh, int ldb, size_t bBS,
              int K, int ldc, size_t cBS,
              float* __restrict__ Cf,
              __half* __restrict__ Chi, __half* __restrict__ Clo,
              const float* __restrict__ bias, size_t biasBS)
{
    gemm_body<EPI, XA, 256>(Ah, Al, lda, aBS, Bh, ldb, bBS, K, ldc, cBS,
                            Cf, Chi, Clo, bias, biasBS);
}

// occupancy-2 shell (BN=128) — used by the big FFN GEMMs
template <int EPI, int XA>
__global__ __launch_bounds__(256, 2)
void mma_gemm2(const __half* __restrict__ Ah, const __half* __restrict__ Al,
               int lda, size_t aBS,
               const __half* __restrict__ Bh, int ldb, size_t bBS,
               int K, int ldc, size_t cBS,
               float* __restrict__ Cf,
               __half* __restrict__ Chi, __half* __restrict__ Clo,
               const float* __restrict__ bias, size_t biasBS)
{
    gemm_body<EPI, XA, 128>(Ah, Al, lda, aBS, Bh, ldb, bBS, K, ldc, cBS,
                            Cf, Chi, Clo, bias, biasBS);
}

// ---------------- attention collapse: scores, softmax, z ----------------
__global__ __launch_bounds__(256)
void attn_collapse(const __half* __restrict__ qh,
                   const float* __restrict__ t,
                   const __half* __restrict__ yh, const __half* __restrict__ yl,
                   const float* __restrict__ bk,
                   __half* __restrict__ zh)
{
    const int b = blockIdx.x, tid = threadIdx.x;
    const int wid = tid >> 5, lane = tid & 31;
    __shared__ float ys[Ssup][Dm];
    __shared__ float sc[16], qb[Hh], attn[16];

#pragma unroll
    for (int it = 0; it < 8; it++) {
        int idx = tid + it * 256;
        int s = idx >> 9, mm = idx & 511;
        size_t g = ((size_t)s * Bsz + b) * Dm + mm * 2;
        __half2 h2 = *reinterpret_cast<const __half2*>(&yh[g]);
        __half2 l2 = *reinterpret_cast<const __half2*>(&yl[g]);
        ys[s][mm * 2]     = __half2float(h2.x) + __half2float(l2.x);
        ys[s][mm * 2 + 1] = __half2float(h2.y) + __half2float(l2.y);
    }
    if (wid < Hh) {
        float sum = 0.f;
        for (int j = lane; j < HD; j += 32) {
            size_t g = (size_t)b * Dm + wid * HD + j;
            sum = fmaf(__half2float(qh[g]), bk[wid * HD + j], sum);
        }
#pragma unroll
        for (int o = 16; o; o >>= 1) sum += __shfl_xor_sync(0xffffffffu, sum, o);
        if (lane == 0) qb[wid] = sum;
    }
    __syncthreads();

#pragma unroll
    for (int i = 0; i < 2; i++) {
        int p = wid * 2 + i;
        int h = p >> 2, s = p & 3;
        const float* tp = t + ((size_t)h * Bsz + b) * Dm;
        float sum = 0.f;
        for (int m = lane; m < Dm; m += 32) sum = fmaf(ys[s][m], tp[m], sum);
#pragma unroll
        for (int o = 16; o; o >>= 1) sum += __shfl_xor_sync(0xffffffffu, sum, o);
        if (lane == 0) sc[p] = sum;
    }
    __syncthreads();

    if (tid < Hh) {
        int h = tid;
        float s0 = (sc[h*4+0] + qb[h]) * 0.0625f;
        float s1 = (sc[h*4+1] + qb[h]) * 0.0625f;
        float s2 = (sc[h*4+2] + qb[h]) * 0.0625f;
        float s3 = (sc[h*4+3] + qb[h]) * 0.0625f;
        float m = fmaxf(fmaxf(s0, s1), fmaxf(s2, s3));
        float e0 = expf(s0-m), e1 = expf(s1-m), e2 = expf(s2-m), e3 = expf(s3-m);
        float inv = 1.f / (e0 + e1 + e2 + e3);
        attn[h*4+0] = e0*inv; attn[h*4+1] = e1*inv;
        attn[h*4+2] = e2*inv; attn[h*4+3] = e3*inv;
    }
    __syncthreads();

#pragma unroll
    for (int it = 0; it < 8; it++) {
        int idx = tid + it * 256;
        int h = idx >> 9, mm = idx & 511;
        int m = mm * 2;
        float a0 = attn[h*4+0], a1 = attn[h*4+1], a2 = attn[h*4+2], a3 = attn[h*4+3];
        float z0 = a0*ys[0][m]   + a1*ys[1][m]   + a2*ys[2][m]   + a3*ys[3][m];
        float z1 = a0*ys[0][m+1] + a1*ys[1][m+1] + a2*ys[2][m+1] + a3*ys[3][m+1];
        size_t g = ((size_t)h * Bsz + b) * Dm + m;
        __half2 z2;
        z2.x = __float2half(z0);
        z2.y = __float2half(z1);
        *reinterpret_cast<__half2*>(&zh[g]) = z2;
    }
}

// ---------------- launch ----------------
extern "C" void kernel_launch(void* const* d_in, const int* in_sizes, int n_in,
                              void* d_out, int out_size)
{
    const float* x   = (const float*)d_in[0];
    const float* g1a = (const float*)d_in[1];
    const float* g1b = (const float*)d_in[2];
    const float* g2a = (const float*)d_in[3];
    const float* g2b = (const float*)d_in[4];
    const float* wq  = (const float*)d_in[5];
    const float* bq  = (const float*)d_in[6];
    const float* wk  = (const float*)d_in[7];
    const float* bk  = (const float*)d_in[8];
    const float* wv  = (const float*)d_in[9];
    const float* bv  = (const float*)d_in[10];
    const float* wo  = (const float*)d_in[11];
    const float* bo  = (const float*)d_in[12];
    float* out = (float*)d_out;

    __half *xh,*w1,*w2,*wqp,*wk2,*wvp,*wop,*hh,*yh,*yl,*qh,*zh,*oh;
    float *t;
    cudaGetSymbolAddress((void**)&xh, g_xh);
    cudaGetSymbolAddress((void**)&w1, g_w1);   cudaGetSymbolAddress((void**)&w2, g_w2);
    cudaGetSymbolAddress((void**)&wqp, g_wq);  cudaGetSymbolAddress((void**)&wk2, g_wk2);
    cudaGetSymbolAddress((void**)&wvp, g_wv);  cudaGetSymbolAddress((void**)&wop, g_wo);
    cudaGetSymbolAddress((void**)&hh, g_hh);
    cudaGetSymbolAddress((void**)&yh, g_yh);   cudaGetSymbolAddress((void**)&yl, g_yl);
    cudaGetSymbolAddress((void**)&qh, g_qh);
    cudaGetSymbolAddress((void**)&zh, g_zh);
    cudaGetSymbolAddress((void**)&oh, g_oh);
    cudaGetSymbolAddress((void**)&t, g_t);

    const int SM1b = NST * (A_B + 128 * BK * 2);     // 98304  (XA=1, BN=128, occ2)
    const int SM1  = NST * (A_B + 256 * BK * 2);     // 147456 (XA=1, BN=256)
    cudaFuncSetAttribute((const void*)mma_gemm2<1,1>, cudaFuncAttributeMaxDynamicSharedMemorySize, SM1b);
    cudaFuncSetAttribute((const void*)mma_gemm2<0,1>, cudaFuncAttributeMaxDynamicSharedMemorySize, SM1b);
    cudaFuncSetAttribute((const void*)mma_gemm<5,1>,  cudaFuncAttributeMaxDynamicSharedMemorySize, SM1);
    cudaFuncSetAttribute((const void*)mma_gemm<4,1>,  cudaFuncAttributeMaxDynamicSharedMemorySize, SM1);
    cudaFuncSetAttribute((const void*)mma_gemm<2,1>,  cudaFuncAttributeMaxDynamicSharedMemorySize, SM1);
    cudaFuncSetAttribute((const void*)build_w1_tiled, cudaFuncAttributeMaxDynamicSharedMemorySize, W1_SMEM);
    cudaFuncSetAttribute((const void*)build_w2_tiled, cudaFuncAttributeMaxDynamicSharedMemorySize, W2_SMEM);

    const size_t sBD = (size_t)Bsz * Dm, sBF = (size_t)Bsz * Ff;
    const size_t sDD = (size_t)Dm * Dm, sFD = (size_t)Ff * Dm;

    // streams: s1 = q/t chain (+its weight preps), s2 = build_w2. Fallback: all on 0.
    cudaStream_t s1 = 0, s2 = 0;
    cudaEvent_t evX = 0, evJ = 0, evW2 = 0;
    bool forked = (cudaStreamCreateWithFlags(&s1, cudaStreamNonBlocking) == cudaSuccess);
    if (forked && cudaStreamCreateWithFlags(&s2, cudaStreamNonBlocking) != cudaSuccess) {
        cudaStreamDestroy(s1); s1 = 0; forked = false;
    }
    if (forked && (cudaEventCreateWithFlags(&evX, cudaEventDisableTiming) != cudaSuccess ||
                   cudaEventCreateWithFlags(&evJ, cudaEventDisableTiming) != cudaSuccess ||
                   cudaEventCreateWithFlags(&evW2, cudaEventDisableTiming) != cudaSuccess)) {
        if (evX) cudaEventDestroy(evX);
        if (evJ) cudaEventDestroy(evJ);
        if (evW2) cudaEventDestroy(evW2);
        cudaStreamDestroy(s1); cudaStreamDestroy(s2);
        s1 = s2 = 0; evX = evJ = evW2 = 0; forked = false;
    }

    // main: x -> fp16 (needed by FFN1 and q)
    half_arr<<<(Bsz * Dm) / 256, 256>>>(x, xh, sBD);
    // fork BOTH side streams from the origin — mandatory under graph capture
    if (forked) {
        cudaEventRecord(evX, 0);
        cudaStreamWaitEvent(s1, evX, 0);
        cudaStreamWaitEvent(s2, evX, 0);
    }

    // s2: w2 build (only FFN2 needs it)
    build_w2_tiled<<<dim3(64, 4, Ssup), 256, W2_SMEM, s2>>>(g2a, g2b, w2);
    if (forked) cudaEventRecord(evW2, s2);

    // s1: weight preps for attention path, then q -> t (plain fp16)
    ttile_w<<<dim3(32, 32, 3), 256, 0, s1>>>(wq, wv, wo, wqp, wvp, wop);
    half_arr<<<(Dm * Dm) / 256, 256, 0, s1>>>(wk, wk2, sDD);
    mma_gemm<5,1><<<dim3(Dm/256, Bsz/BM, 1), 256, SM1, s1>>>(
        xh, nullptr, Dm, 0, wqp, Dm, 0, Dm, Dm, 0,
        nullptr, qh, nullptr, bq, 0);
    mma_gemm<4,1><<<dim3(Dm/256, Bsz/BM, Hh), 256, SM1, s1>>>(
        qh, nullptr, Dm, HD, wk2, Dm, HD, HD, Dm, sBD,
        t, nullptr, nullptr, nullptr, 0);
    if (forked) cudaEventRecord(evJ, s1);

    // main: w1 build, FFN1
    build_w1_tiled<<<dim3(64, 4, Ssup), 256, W1_SMEM>>>(g1a, g1b, w1);
    mma_gemm2<1,1><<<dim3(Ff/128, Bsz/BM, Ssup), 256, SM1b>>>(
        xh, nullptr, Dm, 0, w1, Dm, sFD, Dm, Ff, sBF,
        nullptr, hh, nullptr, nullptr, 0);

    // main: FFN2 (needs w2 from s2)
    if (forked) cudaStreamWaitEvent(0, evW2, 0);
    mma_gemm2<0,1><<<dim3(Dm/128, Bsz/BM, Ssup), 256, SM1b>>>(
        hh, nullptr, Ff, sBF, w2, Ff, (size_t)Dm*Ff, Ff, Dm, sBD,
        nullptr, yh, yl, nullptr, 0);

    // join: attn needs y (main) + t, and later wvp/wop (s1)
    if (forked) cudaStreamWaitEvent(0, evJ, 0);

    attn_collapse<<<Bsz, 256>>>(qh, t, yh, yl, bk, zh);

    // o[:,h-block] = z[h] @ wv[:,h-block]^T + bv  (plain fp16)
    mma_gemm<5,1><<<dim3(1, Bsz/BM, Hh), 256, SM1>>>(
        zh, nullptr, Dm, sBD, wvp, Dm, (size_t)HD*Dm, Dm, Dm, (size_t)HD,
        nullptr, oh, nullptr, bv, HD);

    // out = o @ wo + bo (fp32, plain fp16 inputs)
    mma_gemm<2,1><<<dim3(Dm/256, Bsz/BM, 1), 256, SM1>>>(
        oh, nullptr, Dm, 0, wop, Dm, 0, Dm, Dm, 0,
        out, nullptr, nullptr, bo, 0);

    if (forked) {
        cudaEventDestroy(evX);
        cudaEventDestroy(evJ);
        cudaEventDestroy(evW2);
        cudaStreamDestroy(s1);
        cudaStreamDestroy(s2);
    }
}

// round 15
// speedup vs baseline: 8.0330x; 1.0041x over previous
#include <cuda_runtime.h>
#include <cuda_fp16.h>
#include <math.h>
#include <stdint.h>

// ---------------- problem constants ----------------
#define Bsz 8192
#define Dm  1024
#define Ff  4096
#define Ssup 4
#define Hh  4
#define HD  256
#define BHALF (Bsz / 2)

// ---------------- GEMM tiling ----------------
#define BM 128
#define BK 64                    // fp16 elems per k-tile (128B rows)
#define NST 3
#define A_B   (BM * BK * 2)      // 16384 bytes per A matrix (hi or lo)

// ---------------- scratch (device globals) ----------------
__device__ __half g_xh [(size_t)Bsz*Dm];
__device__ __half g_w1 [(size_t)Ssup*Ff*Dm];   // [s][f][d] (transposed)
__device__ __half g_w2 [(size_t)Ssup*Dm*Ff];   // [s][d][f]
__device__ __half g_wq [(size_t)Dm*Dm];        // transposed [n][k]
__device__ __half g_wk2[(size_t)Dm*Dm];        // straight [m][d]
__device__ __half g_wv [(size_t)Dm*Dm];        // transposed
__device__ __half g_wo [(size_t)Dm*Dm];        // transposed
__device__ __half g_hh [(size_t)Ssup*Bsz*Ff];                             // h single fp16
__device__ __half g_yh [(size_t)Ssup*Bsz*Dm],  g_yl [(size_t)Ssup*Bsz*Dm];
__device__ __half g_qh [(size_t)Bsz*Dm];
__device__ __half g_zh [(size_t)Hh*Bsz*Dm];    // [h][b][m]
__device__ __half g_oh [(size_t)Bsz*Dm];
__device__ float g_t [(size_t)Hh*Bsz*Dm];      // [h][b][m]

// ---------------- asm helpers (generic-target PTX, sm_80+) ----------------
__device__ __forceinline__ uint32_t smem_u32(const void* p) {
    uint32_t a;
    asm("{ .reg .u64 t; cvta.to.shared.u64 t, %1; cvt.u32.u64 %0, t; }" : "=r"(a) : "l"(p));
    return a;
}
__device__ __forceinline__ void cp16(uint32_t dst, const void* src) {
    asm volatile("cp.async.cg.shared.global [%0], [%1], 16;" :: "r"(dst), "l"(src));
}
#define CP_COMMIT() asm volatile("cp.async.commit_group;" ::: "memory")
#define CP_WAIT(n)  asm volatile("cp.async.wait_group %0;" :: "n"(n) : "memory")
#define LDSM4(r, a) asm volatile("ldmatrix.sync.aligned.m8n8.x4.shared.b16 {%0,%1,%2,%3}, [%4];" \
    : "=r"((r)[0]), "=r"((r)[1]), "=r"((r)[2]), "=r"((r)[3]) : "r"(a))
#define MMA16816(ac, a, b0, b1) \
    asm volatile("mma.sync.aligned.m16n8k16.row.col.f32.f16.f16.f32 " \
        "{%0,%1,%2,%3}, {%4,%5,%6,%7}, {%8,%9}, {%0,%1,%2,%3};" \
        : "+f"((ac)[0]), "+f"((ac)[1]), "+f"((ac)[2]), "+f"((ac)[3]) \
        : "r"((a)[0]), "r"((a)[1]), "r"((a)[2]), "r"((a)[3]), "r"(b0), "r"(b1))

__device__ __forceinline__ float gelu_exact(float x) {
    return 0.5f * x * (1.0f + erff(x * 0.70710678118654752440f));
}
__device__ __forceinline__ void split2(float v, __half* h, __half* l) {
    __half hb = __float2half(v);
    *h = hb;
    *l = __float2half(v - __half2float(hb));
}
// 16B-chunk swizzle for 128B rows (8 chunks per row): chunk' = chunk ^ (row & 7)
__device__ __forceinline__ uint32_t swz(int row, int c16) {
    return (uint32_t)(row * 8 + (c16 ^ (row & 7))) * 16u;
}

// ---------------- conversion / build kernels ----------------
__global__ void half_arr(const float* __restrict__ in, __half* __restrict__ o, size_t n) {
    size_t i = (size_t)blockIdx.x * blockDim.x + threadIdx.x;
    if (i < n) o[i] = __float2half(in[i]);
}

__global__ __launch_bounds__(256)
void ttile_w(const float* __restrict__ wq, const float* __restrict__ wv,
             const float* __restrict__ wo,
             __half* __restrict__ oq, __half* __restrict__ ov, __half* __restrict__ oo)
{
    __shared__ float tile[32][33];
    const float* w = blockIdx.z == 0 ? wq : (blockIdx.z == 1 ? wv : wo);
    __half* o      = blockIdx.z == 0 ? oq : (blockIdx.z == 1 ? ov : oo);
    const int bx = blockIdx.x * 32, by = blockIdx.y * 32;
    const int tx = threadIdx.x & 31, ty = threadIdx.x >> 5;  // 32x8
#pragma unroll
    for (int j = 0; j < 4; j++)
        tile[ty + j * 8][tx] = w[(size_t)(by + ty + j * 8) * Dm + bx + tx];
    __syncthreads();
#pragma unroll
    for (int j = 0; j < 4; j++)
        o[(size_t)(bx + ty + j * 8) * Dm + by + tx] = __float2half(tile[tx][ty + j * 8]);
}

#define W1_SMEM ((16*32*17 + 512) * 4)
__global__ __launch_bounds__(256)
void build_w1_tiled(const float* __restrict__ g1a, const float* __restrict__ g1b,
                    __half* __restrict__ o)
{
    extern __shared__ float dsm[];
    float* Bs = dsm;                 // [(r*32+i2)*17 + o2l]
    float* As = dsm + 16 * 32 * 17;  // [i1][r]
    const int tid = threadIdx.x;
    const int o1 = blockIdx.x, q = blockIdx.y, s = blockIdx.z;

    for (int idx = tid; idx < 8192; idx += 256) {
        int r = idx >> 9, i2 = (idx >> 4) & 31, o2l = idx & 15;
        Bs[(r * 32 + i2) * 17 + o2l] =
            g1b[(size_t)s * 32768 + (size_t)r * 2048 + i2 * 64 + q * 16 + o2l];
    }
    for (int idx = tid; idx < 512; idx += 256) {
        int i1 = idx >> 4, r = idx & 15;
        As[idx] = g1a[(((size_t)s * 32 + i1) * 64 + o1) * 16 + r];
    }
    __syncthreads();

    const size_t ob = ((size_t)s * Ff + (size_t)o1 * 64 + q * 16) * Dm;
#pragma unroll 4
    for (int it = 0; it < 64; it++) {
        int idx = tid + (it << 8);
        int o2l = idx >> 10, d = idx & 1023;
        int i1 = d >> 5, i2 = d & 31;
        const float* ap = As + i1 * 16;
        const float* bp = Bs + i2 * 17 + o2l;
        float sum = 0.f;
#pragma unroll
        for (int r = 0; r < 16; r++) sum += ap[r] * bp[r * 544];
        o[ob + (size_t)o2l * Dm + d] = __float2half(sum);
    }
}

#define W2_SMEM ((16*16*33 + 512) * 4)
__global__ __launch_bounds__(256)
void build_w2_tiled(const float* __restrict__ g2a, const float* __restrict__ g2b,
                    __half* __restrict__ o)
{
    extern __shared__ float dsm[];
    float* Bs = dsm;                 // [(r*16+o2l)*33 + i2]
    float* As = dsm + 16 * 16 * 33;  // [i1][r]
    const int tid = threadIdx.x;
    const int o1 = blockIdx.x, q = blockIdx.y, s = blockIdx.z;

    for (int idx = tid; idx < 8192; idx += 256) {
        int r = idx >> 9, o2l = (idx >> 5) & 15, i2 = idx & 31;
        Bs[(r * 16 + o2l) * 33 + i2] =
            g2b[(size_t)s * 32768 + (size_t)r * 2048 + (q * 16 + o2l) * 32 + i2];
    }
    for (int idx = tid; idx < 512; idx += 256) {
        int i1 = idx >> 4, r = idx & 15;
        As[idx] = g2a[(((size_t)s * 64 + o1) * 32 + i1) * 16 + r];
    }
    __syncthreads();

    const size_t ob = (size_t)s * Dm * Ff + (size_t)o1 * 64 + q * 16;
#pragma unroll 4
    for (int it = 0; it < 64; it++) {
        int idx = tid + (it << 8);
        int d = idx >> 4, o2l = idx & 15;
        int i1 = d >> 5, i2 = d & 31;
        const float* ap = As + i1 * 16;
        const float* bp = Bs + o2l * 33 + i2;
        float sum = 0.f;
#pragma unroll
        for (int r = 0; r < 16; r++) sum += ap[r] * bp[r * 528];
        o[ob + (size_t)d * Ff + o2l] = __float2half(sum);
    }
}

// ---------------- fp16 HMMA GEMM body ----------------
// EPI: 0 split, 1 gelu+single, 2 bias+fp32, 4 fp32, 5 bias+single
template <int EPI, int XA, int BNT>
__device__ __forceinline__
void gemm_body(const __half* __restrict__ Ah, const __half* __restrict__ Al,
               int lda, size_t aBS,
               const __half* __restrict__ Bh, int ldb, size_t bBS,
               int K, int ldc, size_t cBS,
               float* __restrict__ Cf,
               __half* __restrict__ Chi, __half* __restrict__ Clo,
               const float* __restrict__ bias, size_t biasBS)
{
    constexpr uint32_t B_Bt = BNT * BK * 2;
    constexpr uint32_t STG  = XA * A_B + B_Bt;
    constexpr int P = BNT / 64;
    extern __shared__ char smem[];
    const uint32_t sb = smem_u32(smem);
    const int tid = threadIdx.x, wid = tid >> 5, lane = tid & 31;
    const int zz = blockIdx.z;
    const int m0 = blockIdx.y * BM, n0 = blockIdx.x * BNT;

    const __half* pAh = Ah + (size_t)zz * aBS;
    const __half* pAl = (XA == 2) ? Al + (size_t)zz * aBS : nullptr;
    const __half* pBh = Bh + (size_t)zz * bBS;

    const int mwarp = (wid & 1) * 64;
    const int nwarp = (wid >> 1) * (BNT / 4);

    float acc[4][2 * P][4];
#pragma unroll
    for (int i = 0; i < 4; i++)
#pragma unroll
        for (int j = 0; j < 2 * P; j++)
#pragma unroll
            for (int c = 0; c < 4; c++) acc[i][j][c] = 0.f;

    const int nk = K / BK;
    const int fr = tid >> 3, fc = tid & 7;

    auto fill = [&](int kt, int st) {
        const int k0 = kt * BK;
        const uint32_t base = sb + st * STG;
#pragma unroll
        for (int i = 0; i < 4; i++) {
            int r = fr + i * 32;
            cp16(base + swz(r, fc), pAh + (size_t)(m0 + r) * lda + k0 + fc * 8);
            if (XA == 2)
                cp16(base + A_B + swz(r, fc), pAl + (size_t)(m0 + r) * lda + k0 + fc * 8);
        }
#pragma unroll
        for (int i = 0; i < BNT / 32; i++) {
            int r = fr + i * 32;
            cp16(base + XA*A_B + swz(r, fc), pBh + (size_t)(n0 + r) * ldb + k0 + fc * 8);
        }
        CP_COMMIT();
    };

    fill(0, 0);
    if (nk > 1) fill(1, 1);

    const int ra = lane & 15, ca = lane >> 4;
    const int gb = lane >> 3, rb = lane & 7;

    for (int kt = 0; kt < nk; kt++) {
        if (kt + 1 >= nk) { CP_WAIT(0); } else { CP_WAIT(1); }
        __syncthreads();
        if (kt + 2 < nk) fill(kt + 2, (kt + 2) % NST);

        const uint32_t base = sb + (kt % NST) * STG;
        const uint32_t sAh = base, sAl = base + A_B;
        const uint32_t sBh = base + XA * A_B;

#pragma unroll
        for (int kk = 0; kk < 4; kk++) {
            uint32_t ah[4][4], al[4][4];
#pragma unroll
            for (int mt = 0; mt < 4; mt++) {
                uint32_t off = swz(mwarp + mt * 16 + ra, kk * 2 + ca);
                LDSM4(ah[mt], sAh + off);
                if (XA == 2) LDSM4(al[mt], sAl + off);
            }
#pragma unroll
            for (int p = 0; p < P; p++) {
                uint32_t bh[4];
                uint32_t off = swz(nwarp + p * 16 + (gb & 1) * 8 + rb, kk * 2 + (gb >> 1));
                LDSM4(bh, sBh + off);
#pragma unroll
                for (int mt = 0; mt < 4; mt++) {
                    MMA16816(acc[mt][2*p],   ah[mt], bh[0], bh[2]);
                    MMA16816(acc[mt][2*p+1], ah[mt], bh[1], bh[3]);
                    if (XA == 2) {
                        MMA16816(acc[mt][2*p],   al[mt], bh[0], bh[2]);
                        MMA16816(acc[mt][2*p+1], al[mt], bh[1], bh[3]);
                    }
                }
            }
        }
    }

    float* Cfp = Cf ? Cf + (size_t)zz * cBS : nullptr;
    __half* Chp = Chi ? Chi + (size_t)zz * cBS : nullptr;
    __half* Clp = Clo ? Clo + (size_t)zz * cBS : nullptr;
    const float* bp = bias ? bias + (size_t)zz * biasBS : nullptr;
    const int g4 = lane >> 2, q2 = (lane & 3) * 2;

#pragma unroll
    for (int mt = 0; mt < 4; mt++) {
#pragma unroll
        for (int nt = 0; nt < 2 * P; nt++) {
            int r0 = m0 + mwarp + mt * 16 + g4;
            int c  = n0 + nwarp + nt * 8 + q2;
#pragma unroll
            for (int half = 0; half < 2; half++) {
                int rr = r0 + half * 8;
                float v0 = acc[mt][nt][half * 2 + 0];
                float v1 = acc[mt][nt][half * 2 + 1];
                size_t off = (size_t)rr * ldc + c;
                if (EPI == 2) {
                    *reinterpret_cast<float2*>(&Cfp[off]) =
                        make_float2(v0 + bp[c], v1 + bp[c + 1]);
                } else if (EPI == 4) {
                    *reinterpret_cast<float2*>(&Cfp[off]) = make_float2(v0, v1);
                } else if (EPI == 1) {
                    __half2 h2;
                    h2.x = __float2half(gelu_exact(v0));
                    h2.y = __float2half(gelu_exact(v1));
                    *reinterpret_cast<__half2*>(&Chp[off]) = h2;
                } else if (EPI == 5) {
                    __half2 h2;
                    h2.x = __float2half(v0 + bp[c]);
                    h2.y = __float2half(v1 + bp[c + 1]);
                    *reinterpret_cast<__half2*>(&Chp[off]) = h2;
                } else {  // EPI == 0: split
                    __half2 h2, l2;
                    split2(v0, &h2.x, &l2.x);
                    split2(v1, &h2.y, &l2.y);
                    *reinterpret_cast<__half2*>(&Chp[off]) = h2;
                    *reinterpret_cast<__half2*>(&Clp[off]) = l2;
                }
            }
        }
    }
}

template <int EPI, int XA>
__global__ __launch_bounds__(256, 1)
void mma_gemm(const __half* __restrict__ Ah, const __half* __restrict__ Al,
              int lda, size_t aBS,
              const __half* __restrict__ Bh, int ldb, size_t bBS,
              int K, int ldc, size_t cBS,
              float* __restrict__ Cf,
              __half* __restrict__ Chi, __half* __restrict__ Clo,
              const float* __restrict__ bias, size_t biasBS)
{
    gemm_body<EPI, XA, 256>(Ah, Al, lda, aBS, Bh, ldb, bBS, K, ldc, cBS,
                            Cf, Chi, Clo, bias, biasBS);
}

template <int EPI, int XA>
__global__ __launch_bounds__(256, 2)
void mma_gemm2(const __half* __restrict__ Ah, const __half* __restrict__ Al,
               int lda, size_t aBS,
               const __half* __restrict__ Bh, int ldb, size_t bBS,
               int K, int ldc, size_t cBS,
               float* __restrict__ Cf,
               __half* __restrict__ Chi, __half* __restrict__ Clo,
               const float* __restrict__ bias, size_t biasBS)
{
    gemm_body<EPI, XA, 128>(Ah, Al, lda, aBS, Bh, ldb, bBS, K, ldc, cBS,
                            Cf, Chi, Clo, bias, biasBS);
}

// ---------------- attention collapse: scores, softmax, z ----------------
// pointers may be pre-offset by a half-batch (offD); indexing uses full Bsz strides
__global__ __launch_bounds__(256)
void attn_collapse(const __half* __restrict__ qh,
                   const float* __restrict__ t,
                   const __half* __restrict__ yh, const __half* __restrict__ yl,
                   const float* __restrict__ bk,
                   __half* __restrict__ zh)
{
    const int b = blockIdx.x, tid = threadIdx.x;
    const int wid = tid >> 5, lane = tid & 31;
    __shared__ float ys[Ssup][Dm];
    __shared__ float sc[16], qb[Hh], attn[16];

#pragma unroll
    for (int it = 0; it < 8; it++) {
        int idx = tid + it * 256;
        int s = idx >> 9, mm = idx & 511;
        size_t g = ((size_t)s * Bsz + b) * Dm + mm * 2;
        __half2 h2 = *reinterpret_cast<const __half2*>(&yh[g]);
        __half2 l2 = *reinterpret_cast<const __half2*>(&yl[g]);
        ys[s][mm * 2]     = __half2float(h2.x) + __half2float(l2.x);
        ys[s][mm * 2 + 1] = __half2float(h2.y) + __half2float(l2.y);
    }
    if (wid < Hh) {
        float sum = 0.f;
        for (int j = lane; j < HD; j += 32) {
            size_t g = (size_t)b * Dm + wid * HD + j;
            sum = fmaf(__half2float(qh[g]), bk[wid * HD + j], sum);
        }
#pragma unroll
        for (int o = 16; o; o >>= 1) sum += __shfl_xor_sync(0xffffffffu, sum, o);
        if (lane == 0) qb[wid] = sum;
    }
    __syncthreads();

#pragma unroll
    for (int i = 0; i < 2; i++) {
        int p = wid * 2 + i;
        int h = p >> 2, s = p & 3;
        const float* tp = t + ((size_t)h * Bsz + b) * Dm;
        float sum = 0.f;
        for (int m = lane; m < Dm; m += 32) sum = fmaf(ys[s][m], tp[m], sum);
#pragma unroll
        for (int o = 16; o; o >>= 1) sum += __shfl_xor_sync(0xffffffffu, sum, o);
        if (lane == 0) sc[p] = sum;
    }
    __syncthreads();

    if (tid < Hh) {
        int h = tid;
        float s0 = (sc[h*4+0] + qb[h]) * 0.0625f;
        float s1 = (sc[h*4+1] + qb[h]) * 0.0625f;
        float s2 = (sc[h*4+2] + qb[h]) * 0.0625f;
        float s3 = (sc[h*4+3] + qb[h]) * 0.0625f;
        float m = fmaxf(fmaxf(s0, s1), fmaxf(s2, s3));
        float e0 = expf(s0-m), e1 = expf(s1-m), e2 = expf(s2-m), e3 = expf(s3-m);
        float inv = 1.f / (e0 + e1 + e2 + e3);
        attn[h*4+0] = e0*inv; attn[h*4+1] = e1*inv;
        attn[h*4+2] = e2*inv; attn[h*4+3] = e3*inv;
    }
    __syncthreads();

#pragma unroll
    for (int it = 0; it < 8; it++) {
        int idx = tid + it * 256;
        int h = idx >> 9, mm = idx & 511;
        int m = mm * 2;
        float a0 = attn[h*4+0], a1 = attn[h*4+1], a2 = attn[h*4+2], a3 = attn[h*4+3];
        float z0 = a0*ys[0][m]   + a1*ys[1][m]   + a2*ys[2][m]   + a3*ys[3][m];
        float z1 = a0*ys[0][m+1] + a1*ys[1][m+1] + a2*ys[2][m+1] + a3*ys[3][m+1];
        size_t g = ((size_t)h * Bsz + b) * Dm + m;
        __half2 z2;
        z2.x = __float2half(z0);
        z2.y = __float2half(z1);
        *reinterpret_cast<__half2*>(&zh[g]) = z2;
    }
}

// ---------------- launch ----------------
extern "C" void kernel_launch(void* const* d_in, const int* in_sizes, int n_in,
                              void* d_out, int out_size)
{
    const float* x   = (const float*)d_in[0];
    const float* g1a = (const float*)d_in[1];
    const float* g1b = (const float*)d_in[2];
    const float* g2a = (const float*)d_in[3];
    const float* g2b = (const float*)d_in[4];
    const float* wq  = (const float*)d_in[5];
    const float* bq  = (const float*)d_in[6];
    const float* wk  = (const float*)d_in[7];
    const float* bk  = (const float*)d_in[8];
    const float* wv  = (const float*)d_in[9];
    const float* bv  = (const float*)d_in[10];
    const float* wo  = (const float*)d_in[11];
    const float* bo  = (const float*)d_in[12];
    float* out = (float*)d_out;

    __half *xh,*w1,*w2,*wqp,*wk2,*wvp,*wop,*hh,*yh,*yl,*qh,*zh,*oh;
    float *t;
    cudaGetSymbolAddress((void**)&xh, g_xh);
    cudaGetSymbolAddress((void**)&w1, g_w1);   cudaGetSymbolAddress((void**)&w2, g_w2);
    cudaGetSymbolAddress((void**)&wqp, g_wq);  cudaGetSymbolAddress((void**)&wk2, g_wk2);
    cudaGetSymbolAddress((void**)&wvp, g_wv);  cudaGetSymbolAddress((void**)&wop, g_wo);
    cudaGetSymbolAddress((void**)&hh, g_hh);
    cudaGetSymbolAddress((void**)&yh, g_yh);   cudaGetSymbolAddress((void**)&yl, g_yl);
    cudaGetSymbolAddress((void**)&qh, g_qh);
    cudaGetSymbolAddress((void**)&zh, g_zh);
    cudaGetSymbolAddress((void**)&oh, g_oh);
    cudaGetSymbolAddress((void**)&t, g_t);

    const int SM1b = NST * (A_B + 128 * BK * 2);     // 98304  (XA=1, BN=128, occ2)
    const int SM1  = NST * (A_B + 256 * BK * 2);     // 147456 (XA=1, BN=256)
    cudaFuncSetAttribute((const void*)mma_gemm2<1,1>, cudaFuncAttributeMaxDynamicSharedMemorySize, SM1b);
    cudaFuncSetAttribute((const void*)mma_gemm2<0,1>, cudaFuncAttributeMaxDynamicSharedMemorySize, SM1b);
    cudaFuncSetAttribute((const void*)mma_gemm<5,1>,  cudaFuncAttributeMaxDynamicSharedMemorySize, SM1);
    cudaFuncSetAttribute((const void*)mma_gemm<4,1>,  cudaFuncAttributeMaxDynamicSharedMemorySize, SM1);
    cudaFuncSetAttribute((const void*)mma_gemm<2,1>,  cudaFuncAttributeMaxDynamicSharedMemorySize, SM1);
    cudaFuncSetAttribute((const void*)build_w1_tiled, cudaFuncAttributeMaxDynamicSharedMemorySize, W1_SMEM);
    cudaFuncSetAttribute((const void*)build_w2_tiled, cudaFuncAttributeMaxDynamicSharedMemorySize, W2_SMEM);

    const size_t sBD = (size_t)Bsz * Dm, sBF = (size_t)Bsz * Ff;
    const size_t sDD = (size_t)Dm * Dm, sFD = (size_t)Ff * Dm;
    const size_t offH = (size_t)BHALF * Ff;   // half-B offset in h
    const size_t offD = (size_t)BHALF * Dm;   // half-B offset in [B,Dm] arrays

    // streams: s1 = q/t chain, s2 = build_w2, s3 = tail upper-half. Fallback: all on 0.
    cudaStream_t s1 = 0, s2 = 0, s3 = 0;
    cudaEvent_t evX = 0, evJ = 0, evW2 = 0, evY0 = 0, evT0 = 0;
    bool forked = (cudaStreamCreateWithFlags(&s1, cudaStreamNonBlocking) == cudaSuccess);
    if (forked && cudaStreamCreateWithFlags(&s2, cudaStreamNonBlocking) != cudaSuccess) {
        cudaStreamDestroy(s1); s1 = 0; forked = false;
    }
    if (forked && cudaStreamCreateWithFlags(&s3, cudaStreamNonBlocking) != cudaSuccess) {
        cudaStreamDestroy(s1); cudaStreamDestroy(s2); s1 = s2 = 0; forked = false;
    }
    if (forked && (cudaEventCreateWithFlags(&evX, cudaEventDisableTiming) != cudaSuccess ||
                   cudaEventCreateWithFlags(&evJ, cudaEventDisableTiming) != cudaSuccess ||
                   cudaEventCreateWithFlags(&evW2, cudaEventDisableTiming) != cudaSuccess ||
                   cudaEventCreateWithFlags(&evY0, cudaEventDisableTiming) != cudaSuccess ||
                   cudaEventCreateWithFlags(&evT0, cudaEventDisableTiming) != cudaSuccess)) {
        if (evX) cudaEventDestroy(evX);
        if (evJ) cudaEventDestroy(evJ);
        if (evW2) cudaEventDestroy(evW2);
        if (evY0) cudaEventDestroy(evY0);
        if (evT0) cudaEventDestroy(evT0);
        cudaStreamDestroy(s1); cudaStreamDestroy(s2); cudaStreamDestroy(s3);
        s1 = s2 = s3 = 0; evX = evJ = evW2 = evY0 = evT0 = 0; forked = false;
    }

    // main: x -> fp16
    half_arr<<<(Bsz * Dm) / 256, 256>>>(x, xh, sBD);
    if (forked) {
        cudaEventRecord(evX, 0);
        cudaStreamWaitEvent(s1, evX, 0);
        cudaStreamWaitEvent(s2, evX, 0);
        cudaStreamWaitEvent(s3, evX, 0);   // fork s3 now; tail waits added later
    }

    // s2: w2 build
    build_w2_tiled<<<dim3(64, 4, Ssup), 256, W2_SMEM, s2>>>(g2a, g2b, w2);
    if (forked) cudaEventRecord(evW2, s2);

    // s1: attention-path weight preps, then q -> t
    ttile_w<<<dim3(32, 32, 3), 256, 0, s1>>>(wq, wv, wo, wqp, wvp, wop);
    half_arr<<<(Dm * Dm) / 256, 256, 0, s1>>>(wk, wk2, sDD);
    mma_gemm<5,1><<<dim3(Dm/256, Bsz/BM, 1), 256, SM1, s1>>>(
        xh, nullptr, Dm, 0, wqp, Dm, 0, Dm, Dm, 0,
        nullptr, qh, nullptr, bq, 0);
    mma_gemm<4,1><<<dim3(Dm/256, Bsz/BM, Hh), 256, SM1, s1>>>(
        qh, nullptr, Dm, HD, wk2, Dm, HD, HD, Dm, sBD,
        t, nullptr, nullptr, nullptr, 0);
    if (forked) cudaEventRecord(evJ, s1);

    // main: w1 build, FFN1 (full B)
    build_w1_tiled<<<dim3(64, 4, Ssup), 256, W1_SMEM>>>(g1a, g1b, w1);
    mma_gemm2<1,1><<<dim3(Ff/128, Bsz/BM, Ssup), 256, SM1b>>>(
        xh, nullptr, Dm, 0, w1, Dm, sFD, Dm, Ff, sBF,
        nullptr, hh, nullptr, nullptr, 0);

    // main: FFN2 UPPER half first (rows [BHALF, Bsz)) — matches the s3 tail below
    if (forked) cudaStreamWaitEvent(0, evW2, 0);
    mma_gemm2<0,1><<<dim3(Dm/128, BHALF/BM, Ssup), 256, SM1b>>>(
        hh + offH, nullptr, Ff, sBF, w2, Ff, (size_t)Dm*Ff, Ff, Dm, sBD,
        nullptr, yh + offD, yl + offD, nullptr, 0);
    if (forked) cudaEventRecord(evY0, 0);

    // s3: tail for the UPPER half (runs beside FFN2 lower half)
    if (forked) {
        cudaStreamWaitEvent(s3, evY0, 0);
        cudaStreamWaitEvent(s3, evJ, 0);
    }
    attn_collapse<<<BHALF, 256, 0, s3>>>(qh + offD, t + offD, yh + offD, yl + offD, bk, zh + offD);
    mma_gemm<5,1><<<dim3(1, BHALF/BM, Hh), 256, SM1, s3>>>(
        zh + offD, nullptr, Dm, sBD, wvp, Dm, (size_t)HD*Dm, Dm, Dm, (size_t)HD,
        nullptr, oh + offD, nullptr, bv, HD);
    mma_gemm<2,1><<<dim3(Dm/256, BHALF/BM, 1), 256, SM1, s3>>>(
        oh + offD, nullptr, Dm, 0, wop, Dm, 0, Dm, Dm, 0,
        out + offD, nullptr, nullptr, bo, 0);
    if (forked) cudaEventRecord(evT0, s3);

    // main: FFN2 LOWER half (rows [0, BHALF))
    mma_gemm2<0,1><<<dim3(Dm/128, BHALF/BM, Ssup), 256, SM1b>>>(
        hh, nullptr, Ff, sBF, w2, Ff, (size_t)Dm*Ff, Ff, Dm, sBD,
        nullptr, yh, yl, nullptr, 0);

    // main: tail for the LOWER half
    if (forked) cudaStreamWaitEvent(0, evJ, 0);
    attn_collapse<<<BHALF, 256>>>(qh, t, yh, yl, bk, zh);
    mma_gemm<5,1><<<dim3(1, BHALF/BM, Hh), 256, SM1>>>(
        zh, nullptr, Dm, sBD, wvp, Dm, (size_t)HD*Dm, Dm, Dm, (size_t)HD,
        nullptr, oh, nullptr, bv, HD);
    mma_gemm<2,1><<<dim3(Dm/256, BHALF/BM, 1), 256, SM1>>>(
        oh, nullptr, Dm, 0, wop, Dm, 0, Dm, Dm, 0,
        out, nullptr, nullptr, bo, 0);

    // join s3 back into origin before capture ends
    if (forked) cudaStreamWaitEvent(0, evT0, 0);

    if (forked) {
        cudaEventDestroy(evX);
        cudaEventDestroy(evJ);
        cudaEventDestroy(evW2);
        cudaEventDestroy(evY0);
        cudaEventDestroy(evT0);
        cudaStreamDestroy(s1);
        cudaStreamDestroy(s2);
        cudaStreamDestroy(s3);
    }
}